// round 8
// baseline (speedup 1.0000x reference)
#include <cuda_runtime.h>
#include <cuda_fp16.h>
#include <math.h>
#include <stdint.h>

#define B_    2
#define S_    2048
#define D_    2048
#define H_    16
#define NT    4096          // B_*S_
#define QL    1024
#define KVL   512
#define NOPE_ 128
#define ROPE_ 64
#define VH_   128
#define QK_   192
#define KFW   576           // KVL + ROPE
#define KVP   640           // padded kv_full width
#define HQK   3072          // H_*QK_
#define HQF   9216          // H_*KFW
#define SCALE 0.07216878364870322f   // 192^-0.5

// ---------------- scratch (static device globals; no runtime alloc) -------
__device__ __align__(256) __half h_x  [(size_t)NT * D_];
__device__ __align__(256) __half h_qa [(size_t)NT * QL];
__device__ __align__(256) __half h_q  [(size_t)NT * HQK];
__device__ __align__(256) __half h_kvf[(size_t)NT * KVP];
__device__ __align__(256) __half h_qf [(size_t)NT * HQF];
__device__ __align__(256) __half h_kf [(size_t)NT * KFW];
__device__ __align__(256) __half h_kfT[(size_t)B_ * KVL * S_];
__device__ __align__(256) float  g_scores[(size_t)B_ * H_ * S_ * S_];
__device__ __align__(256) __half h_probs [(size_t)B_ * H_ * S_ * S_];
__device__ __align__(256) __half h_om [(size_t)NT * H_ * KVL];
__device__ __align__(256) __half h_oc [(size_t)NT * H_ * VH_];
__device__ __align__(256) __half h_wqa[(size_t)QL * D_];
__device__ __align__(256) __half h_wqb[(size_t)HQK * QL];
__device__ __align__(256) __half h_wkva[(size_t)KVP * D_];
__device__ __align__(256) __half h_wkvb[(size_t)H_ * 256 * KVL];
__device__ __align__(256) __half h_wkvbT[(size_t)H_ * KVL * NOPE_];
__device__ __align__(256) __half h_wo [(size_t)D_ * H_ * VH_];
__device__ float g_biaskva[KVP];

// ---------------- helpers ---------------------------------------------------
__device__ __forceinline__ void mma_f16(float* c, const uint32_t* a, const uint32_t* b) {
    asm volatile(
        "mma.sync.aligned.m16n8k16.row.col.f32.f16.f16.f32 "
        "{%0,%1,%2,%3},{%4,%5,%6,%7},{%8,%9},{%0,%1,%2,%3};"
        : "+f"(c[0]), "+f"(c[1]), "+f"(c[2]), "+f"(c[3])
        : "r"(a[0]), "r"(a[1]), "r"(a[2]), "r"(a[3]), "r"(b[0]), "r"(b[1]));
}

__device__ __forceinline__ void ldsm4(uint32_t* r, uint32_t saddr) {
    asm volatile(
        "ldmatrix.sync.aligned.m8n8.x4.shared.b16 {%0,%1,%2,%3}, [%4];"
        : "=r"(r[0]), "=r"(r[1]), "=r"(r[2]), "=r"(r[3]) : "r"(saddr));
}

__device__ __forceinline__ void cp_async16(void* smem, const void* gmem) {
    uint32_t s = (uint32_t)__cvta_generic_to_shared(smem);
    asm volatile("cp.async.cg.shared.global [%0], [%1], 16;" :: "r"(s), "l"(gmem));
}
__device__ __forceinline__ void cp_commit() {
    asm volatile("cp.async.commit_group;");
}
template<int N>
__device__ __forceinline__ void cp_wait() {
    asm volatile("cp.async.wait_group %0;" :: "n"(N));
}

// =============================================================================
// gemm_h: fp16 in / fp32 acc. CTA tile 128 x TN (TN = 128 or 256),
// warp tile 64x64 (4 or 8 warps), BK=32, 3-stage cp.async, ldmatrix fragments.
// C[z] = alpha * A[z] @ B[z]^T + bias.  A [M,K], B [N,K], both half row-major.
// Rows in smem: 32 halves (64B) + 16B pad = 80B -> LDSM conflict-free (5r mod 8).
// =============================================================================
template<int TN, bool OUTHALF>
__global__ void __launch_bounds__(TN == 256 ? 256 : 128) gemm_h(
    int K,
    const __half* __restrict__ A, int lda, long long sAb, long long sAh,
    const __half* __restrict__ Bp, int ldb, long long sBb, long long sBh,
    void* __restrict__ Cv, int ldc, long long sCb, long long sCh,
    int ZH, float alpha, const float* __restrict__ bias)
{
    constexpr int T = (TN == 256) ? 256 : 128;   // threads
    constexpr int WCOLS = TN / 64;               // warps along N
    constexpr int ASTR = 20;                     // u32 per row (80 B)
    constexpr int STGA = 128 * ASTR;             // u32 per A stage
    constexpr int STGB = TN * ASTR;              // u32 per B stage
    constexpr int AITER = 512 / T;               // A cp.async per thread
    constexpr int BITER = (TN * 4) / T;          // B cp.async per thread

    extern __shared__ uint32_t smu[];
    uint32_t* sA = smu;                          // [3][STGA]
    uint32_t* sB = smu + 3 * STGA;               // [3][STGB]

    int z  = blockIdx.z;
    int zb = z / ZH;
    int zh = z - zb * ZH;
    const __half* Ab = A  + zb * sAb + zh * sAh;
    const __half* Bb = Bp + zb * sBb + zh * sBh;

    int row0 = blockIdx.y << 7;
    int col0 = blockIdx.x * TN;
    int tid  = threadIdx.x;
    int wid  = tid >> 5;
    int lane = tid & 31;
    int wm0 = (wid / WCOLS) << 6;
    int wn0 = (wid % WCOLS) << 6;
    int g = lane >> 2, t4 = lane & 3;
    int j = lane >> 3, r = lane & 7;

    // ldmatrix lane addresses (byte offsets within a stage)
    uint32_t sA_u = (uint32_t)__cvta_generic_to_shared(sA);
    uint32_t sB_u = (uint32_t)__cvta_generic_to_shared(sB);
    uint32_t aoff0 = (uint32_t)(wm0 + (j & 1) * 8 + r) * 80 + (uint32_t)(j >> 1) * 16;
    uint32_t boff0 = (uint32_t)(wn0 + (j >> 1) * 8 + r) * 80 + (uint32_t)(j & 1) * 16;

    float acc[4][8][4] = {};

    auto load_stage = [&](int st, int k0) {
        uint32_t* a_s = sA + st * STGA;
        uint32_t* b_s = sB + st * STGB;
        #pragma unroll
        for (int i = 0; i < AITER; i++) {
            int idx = tid + T * i;
            int rr = idx >> 2, q = idx & 3;
            cp_async16(a_s + rr * ASTR + q * 4,
                       Ab + (size_t)(row0 + rr) * lda + k0 + q * 8);
        }
        #pragma unroll
        for (int i = 0; i < BITER; i++) {
            int idx = tid + T * i;
            int rr = idx >> 2, q = idx & 3;
            cp_async16(b_s + rr * ASTR + q * 4,
                       Bb + (size_t)(col0 + rr) * ldb + k0 + q * 8);
        }
    };

    int nk = K / 32;
    load_stage(0, 0);
    cp_commit();
    load_stage(1, 32);
    cp_commit();

    for (int i = 0; i < nk; i++) {
        cp_wait<1>();
        __syncthreads();
        if (i + 2 < nk) load_stage((i + 2) % 3, (i + 2) * 32);
        cp_commit();

        uint32_t abase = sA_u + (uint32_t)((i % 3) * STGA) * 4 + aoff0;
        uint32_t bbase = sB_u + (uint32_t)((i % 3) * STGB) * 4 + boff0;

        #pragma unroll
        for (int kk = 0; kk < 2; kk++) {
            uint32_t afr[4][4], bfr[4][4];
            #pragma unroll
            for (int mt = 0; mt < 4; mt++)
                ldsm4(afr[mt], abase + mt * 1280 + kk * 32);
            #pragma unroll
            for (int nt2 = 0; nt2 < 4; nt2++)
                ldsm4(bfr[nt2], bbase + nt2 * 1280 + kk * 32);
            #pragma unroll
            for (int mt = 0; mt < 4; mt++)
                #pragma unroll
                for (int nt2 = 0; nt2 < 4; nt2++) {
                    mma_f16(acc[mt][2 * nt2],     afr[mt], &bfr[nt2][0]);
                    mma_f16(acc[mt][2 * nt2 + 1], afr[mt], &bfr[nt2][2]);
                }
        }
    }

    // ---- epilogue ----
    size_t coff = (size_t)zb * sCb + (size_t)zh * sCh;
    #pragma unroll
    for (int mt = 0; mt < 4; mt++) {
        int r0 = row0 + wm0 + mt * 16 + g;
        #pragma unroll
        for (int nt = 0; nt < 8; nt++) {
            int c0c = col0 + wn0 + nt * 8 + 2 * t4;
            float b0 = bias ? bias[c0c] : 0.f;
            float b1 = bias ? bias[c0c + 1] : 0.f;
            float v00 = alpha * acc[mt][nt][0] + b0;
            float v01 = alpha * acc[mt][nt][1] + b1;
            float v10 = alpha * acc[mt][nt][2] + b0;
            float v11 = alpha * acc[mt][nt][3] + b1;
            if (OUTHALF) {
                __half* Ch = (__half*)Cv + coff;
                *(__half2*)&Ch[(size_t)r0 * ldc + c0c]       = __floats2half2_rn(v00, v01);
                *(__half2*)&Ch[(size_t)(r0 + 8) * ldc + c0c] = __floats2half2_rn(v10, v11);
            } else {
                float* Cf = (float*)Cv + coff;
                *(float2*)&Cf[(size_t)r0 * ldc + c0c]       = make_float2(v00, v01);
                *(float2*)&Cf[(size_t)(r0 + 8) * ldc + c0c] = make_float2(v10, v11);
            }
        }
    }
}

// ---------------- prepass kernels --------------------------------------------
__global__ void f2h_k(const float* __restrict__ in, __half* __restrict__ out)
{
    size_t i = ((size_t)blockIdx.x * 256 + threadIdx.x) * 4;
    float4 v = *(const float4*)(in + i);
    __half2* o = (__half2*)(out + i);
    o[0] = __floats2half2_rn(v.x, v.y);
    o[1] = __floats2half2_rn(v.z, v.w);
}

__global__ void wkva_pad_k(const float* __restrict__ in, __half* __restrict__ out)
{
    size_t i = ((size_t)blockIdx.x * 256 + threadIdx.x) * 4;
    if (i < (size_t)KFW * D_) {
        float4 v = *(const float4*)(in + i);
        __half2* o = (__half2*)(out + i);
        o[0] = __floats2half2_rn(v.x, v.y);
        o[1] = __floats2half2_rn(v.z, v.w);
    } else {
        __half2* o = (__half2*)(out + i);
        o[0] = __half2{__half(0.f), __half(0.f)};
        o[1] = __half2{__half(0.f), __half(0.f)};
    }
}

__global__ void biaskva_pad_k(const float* __restrict__ in, float* __restrict__ out)
{
    int i = blockIdx.x * 256 + threadIdx.x;
    if (i < KVP) out[i] = (i < KFW) ? in[i] : 0.f;
}

__global__ void wkvbT_k(const float* __restrict__ in, __half* __restrict__ out)
{
    __shared__ float t[32][33];
    int h = blockIdx.z;
    int r0 = blockIdx.x * 32;
    int c0 = blockIdx.y * 32;
    int x = threadIdx.x, y = threadIdx.y;
    #pragma unroll
    for (int i = 0; i < 32; i += 8)
        t[y + i][x] = in[(size_t)(h * 256 + r0 + y + i) * KVL + c0 + x];
    __syncthreads();
    #pragma unroll
    for (int i = 0; i < 32; i += 8)
        out[(size_t)h * KVL * NOPE_ + (size_t)(c0 + y + i) * NOPE_ + r0 + x] =
            __float2half(t[x][y + i]);
}

__global__ void kfT_k(const __half* __restrict__ kf, __half* __restrict__ kfT)
{
    __shared__ __half t[32][33];
    int b = blockIdx.z;
    int t0 = blockIdx.x * 32;
    int c0 = blockIdx.y * 32;
    int x = threadIdx.x, y = threadIdx.y;
    const __half* src = kf + (size_t)b * S_ * KFW;
    #pragma unroll
    for (int i = 0; i < 32; i += 8)
        t[y + i][x] = src[(size_t)(t0 + y + i) * KFW + c0 + x];
    __syncthreads();
    __half* dst = kfT + (size_t)b * KVL * S_;
    #pragma unroll
    for (int i = 0; i < 32; i += 8)
        dst[(size_t)(c0 + y + i) * S_ + t0 + x] = t[x][y + i];
}

// ---------------- elementwise kernels (half I/O) ------------------------------
__global__ void rmsnorm_h(const __half* __restrict__ in, __half* __restrict__ out,
                          const float* __restrict__ w, int width,
                          int inStride, int outStride)
{
    int row = blockIdx.x;
    const __half* ip = in  + (size_t)row * inStride;
    __half*       op = out + (size_t)row * outStride;
    float ss = 0.f;
    for (int i = threadIdx.x; i < width; i += 256) {
        float v = __half2float(ip[i]);
        ss += v * v;
    }
    __shared__ float sm[256];
    sm[threadIdx.x] = ss;
    __syncthreads();
    for (int s = 128; s > 0; s >>= 1) {
        if (threadIdx.x < s) sm[threadIdx.x] += sm[threadIdx.x + s];
        __syncthreads();
    }
    float r = rsqrtf(sm[0] / (float)width + 1e-3f);
    for (int i = threadIdx.x; i < width; i += 256)
        op[i] = __float2half(w[i] * __half2float(ip[i]) * r);
}

__global__ void rope_q_h(const __half* __restrict__ q, __half* __restrict__ qf,
                         const float* __restrict__ c, const float* __restrict__ s)
{
    int tok = blockIdx.x;
    int h = threadIdx.x >> 5;
    int j = threadIdx.x & 31;
    int pos = tok % S_;
    const __half* src = q  + (size_t)tok * HQK + h * QK_ + NOPE_;
    __half*       dst = qf + (size_t)tok * HQF + h * KFW + KVL;
    float xr = __half2float(src[2 * j]), xi = __half2float(src[2 * j + 1]);
    float cc = c[pos * 32 + j], sn = s[pos * 32 + j];
    dst[2 * j]     = __float2half(xr * cc - xi * sn);
    dst[2 * j + 1] = __float2half(xr * sn + xi * cc);
}

__global__ void rope_k_h(const __half* __restrict__ kvf, __half* __restrict__ kf,
                         const float* __restrict__ c, const float* __restrict__ s)
{
    int tok = blockIdx.x;
    int j = threadIdx.x;
    int pos = tok % S_;
    const __half* src = kvf + (size_t)tok * KVP + KVL;
    __half*       dst = kf  + (size_t)tok * KFW + KVL;
    float xr = __half2float(src[2 * j]), xi = __half2float(src[2 * j + 1]);
    float cc = c[pos * 32 + j], sn = s[pos * 32 + j];
    dst[2 * j]     = __float2half(xr * cc - xi * sn);
    dst[2 * j + 1] = __float2half(xr * sn + xi * cc);
}

__global__ void softmax_h(const float* __restrict__ d, __half* __restrict__ pr)
{
    size_t row = blockIdx.x;
    const float* p = d + row * (size_t)S_;
    __half* ph = pr + row * (size_t)S_;
    int t = threadIdx.x;
    float v[8];
    float m = -INFINITY;
    #pragma unroll
    for (int i = 0; i < 8; i++) {
        v[i] = p[t + i * 256];
        m = fmaxf(m, v[i]);
    }
    __shared__ float sm[256];
    sm[t] = m;
    __syncthreads();
    for (int s = 128; s > 0; s >>= 1) {
        if (t < s) sm[t] = fmaxf(sm[t], sm[t + s]);
        __syncthreads();
    }
    m = sm[0];
    __syncthreads();
    float sum = 0.f;
    #pragma unroll
    for (int i = 0; i < 8; i++) {
        v[i] = __expf(v[i] - m);
        sum += v[i];
    }
    sm[t] = sum;
    __syncthreads();
    for (int s = 128; s > 0; s >>= 1) {
        if (t < s) sm[t] += sm[t + s];
        __syncthreads();
    }
    float inv = 1.f / sm[0];
    #pragma unroll
    for (int i = 0; i < 8; i++)
        ph[t + i * 256] = __float2half(v[i] * inv);
}

// ---------------- host glue --------------------------------------------------
template<int TN, bool OUTHALF>
static void launch_h(int M, int N, int K,
                     const __half* A, int lda, long long sAb, long long sAh,
                     const __half* Bp, int ldb, long long sBb, long long sBh,
                     void* C, int ldc, long long sCb, long long sCh,
                     int nb, int nh, float alpha, const float* bias)
{
    constexpr int SMEM = (3 * 128 * 20 + 3 * TN * 20) * 4;
    cudaFuncSetAttribute(gemm_h<TN, OUTHALF>,
                         cudaFuncAttributeMaxDynamicSharedMemorySize, SMEM);
    dim3 grid(N / TN, M / 128, nb * nh);
    gemm_h<TN, OUTHALF><<<grid, TN == 256 ? 256 : 128, SMEM>>>(
        K, A, lda, sAb, sAh, Bp, ldb, sBb, sBh, C, ldc, sCb, sCh, nh, alpha, bias);
}

static void f2h(const float* in, __half* out, size_t n)
{
    f2h_k<<<(unsigned)(n / 1024), 256>>>(in, out);
}

extern "C" void kernel_launch(void* const* d_in, const int* in_sizes, int n_in,
                              void* d_out, int out_size)
{
    const float* x        = (const float*)d_in[0];
    const float* cosp     = (const float*)d_in[2];
    const float* sinp     = (const float*)d_in[3];
    const float* wq_a_w   = (const float*)d_in[4];
    const float* wq_a_b   = (const float*)d_in[5];
    const float* q_norm_w = (const float*)d_in[6];
    const float* wq_b_w   = (const float*)d_in[7];
    const float* wq_b_b   = (const float*)d_in[8];
    const float* wkv_a_w  = (const float*)d_in[9];
    const float* kv_norm_w= (const float*)d_in[11];
    const float* wkv_b_w  = (const float*)d_in[12];
    const float* wo_w     = (const float*)d_in[13];
    const float* wo_b     = (const float*)d_in[14];
    float* out = (float*)d_out;

    __half *xh, *qa, *q, *kvf, *qf, *kf, *kfT, *probs, *om, *oc;
    __half *wqa, *wqb, *wkva, *wkvb, *wkvbT, *wo;
    float *sc, *bkva;
    cudaGetSymbolAddress((void**)&xh,   h_x);
    cudaGetSymbolAddress((void**)&qa,   h_qa);
    cudaGetSymbolAddress((void**)&q,    h_q);
    cudaGetSymbolAddress((void**)&kvf,  h_kvf);
    cudaGetSymbolAddress((void**)&qf,   h_qf);
    cudaGetSymbolAddress((void**)&kf,   h_kf);
    cudaGetSymbolAddress((void**)&kfT,  h_kfT);
    cudaGetSymbolAddress((void**)&sc,   g_scores);
    cudaGetSymbolAddress((void**)&probs,h_probs);
    cudaGetSymbolAddress((void**)&om,   h_om);
    cudaGetSymbolAddress((void**)&oc,   h_oc);
    cudaGetSymbolAddress((void**)&wqa,  h_wqa);
    cudaGetSymbolAddress((void**)&wqb,  h_wqb);
    cudaGetSymbolAddress((void**)&wkva, h_wkva);
    cudaGetSymbolAddress((void**)&wkvb, h_wkvb);
    cudaGetSymbolAddress((void**)&wkvbT,h_wkvbT);
    cudaGetSymbolAddress((void**)&wo,   h_wo);
    cudaGetSymbolAddress((void**)&bkva, g_biaskva);

    // --- ordered so a main GEMM is the 6th launch (ncu -s 5 -c 1) ---
    // 0,1) convert x and wq_a
    f2h(x,      xh,  (size_t)NT * D_);
    f2h(wq_a_w, wqa, (size_t)QL * D_);
    // 2) q_a = x @ wq_a^T + b          [4096,1024] K=2048
    launch_h<256, true>(NT, QL, D_, xh, D_, 0, 0, wqa, D_, 0, 0,
                        qa, QL, 0, 0, 1, 1, 1.f, wq_a_b);
    // 3) rmsnorm(q_a) in place
    rmsnorm_h<<<NT, 256>>>(qa, qa, q_norm_w, QL, QL, QL);
    // 4) convert wq_b
    f2h(wq_b_w, wqb, (size_t)HQK * QL);
    // 5) q = q_a_n @ wq_b^T + b        [4096,3072] K=1024  <-- profiled
    launch_h<256, true>(NT, HQK, QL, qa, QL, 0, 0, wqb, QL, 0, 0,
                        q, HQK, 0, 0, 1, 1, 1.f, wq_b_b);
    // 6,7) wkva pad + bias pad
    wkva_pad_k<<<(unsigned)((size_t)KVP * D_ / 1024), 256>>>(wkv_a_w, wkva);
    biaskva_pad_k<<<3, 256>>>((const float*)d_in[10], bkva);
    // 8) kv_full = x @ wkva_pad^T + b  [4096,640] K=2048
    launch_h<128, true>(NT, KVP, D_, xh, D_, 0, 0, wkva, D_, 0, 0,
                        kvf, KVP, 0, 0, 1, 1, 1.f, bkva);
    // 9,10) wkvb convert + nope transpose
    f2h(wkv_b_w, wkvb, (size_t)H_ * 256 * KVL);
    {
        dim3 g(NOPE_ / 32, KVL / 32, H_);
        wkvbT_k<<<g, dim3(32, 8)>>>(wkv_b_w, wkvbT);
    }
    // 11) kf[:, :512] = rmsnorm(kv_full[:, :512])
    rmsnorm_h<<<NT, 256>>>(kvf, kf, kv_norm_w, KVL, KVP, KFW);
    // 12) kf[:, 512:576] = rope(k_pe)
    rope_k_h<<<NT, 32>>>(kvf, kf, cosp, sinp);
    // 13) qf[:, h, 512:576] = rope(q_pe)
    rope_q_h<<<NT, 512>>>(q, qf, cosp, sinp);
    // 14) qf[:, h, :512] = q_nope_h @ wkvbT[h]^T  [4096,512] K=128, x16 heads
    launch_h<256, true>(NT, KVL, NOPE_,
                        q, HQK, 0, QK_,
                        wkvbT, NOPE_, 0, (long long)KVL * NOPE_,
                        qf, HQF, 0, KFW,
                        1, H_, 1.f, nullptr);
    // 15) kfT[b] = kv_c[b]^T
    {
        dim3 g(S_ / 32, KVL / 32, B_);
        kfT_k<<<g, dim3(32, 8)>>>(kf, kfT);
    }
    // 16) scores = SCALE * qf @ kf^T   [2048,2048]x32 K=576 -> fp32
    launch_h<256, false>(S_, S_, KFW,
                         qf, HQF, (long long)S_ * HQF, KFW,
                         kf, KFW, (long long)S_ * KFW, 0,
                         sc, S_, (long long)H_ * S_ * S_, (long long)S_ * S_,
                         B_, H_, SCALE, nullptr);
    // 17) softmax rows -> half probs
    softmax_h<<<B_ * H_ * S_, 256>>>(sc, probs);
    // 18) o_mid = probs @ kfT^T        [2048,512]x32 K=2048
    launch_h<256, true>(S_, KVL, S_,
                        probs, S_, (long long)H_ * S_ * S_, (long long)S_ * S_,
                        kfT, S_, (long long)KVL * S_, 0,
                        om, H_ * KVL, (long long)S_ * H_ * KVL, KVL,
                        B_, H_, 1.f, nullptr);
    // 19) convert wo
    f2h(wo_w, wo, (size_t)D_ * H_ * VH_);
    // 20) o_cat = o_mid @ wkvb_v^T     [4096,128] K=512, x16 heads
    launch_h<128, true>(NT, VH_, KVL,
                        om, H_ * KVL, 0, KVL,
                        wkvb + (size_t)NOPE_ * KVL, KVL, 0, (long long)256 * KVL,
                        oc, H_ * VH_, 0, VH_,
                        1, H_, 1.f, nullptr);
    // 21) out = o_cat @ wo^T + b       [4096,2048] K=2048 -> fp32
    launch_h<256, false>(NT, D_, H_ * VH_, oc, H_ * VH_, 0, 0, wo, D_, 0, 0,
                         out, D_, 0, 0, 1, 1, 1.f, wo_b);
}

// round 9
// speedup vs baseline: 1.7139x; 1.7139x over previous
#include <cuda_runtime.h>
#include <cuda_fp16.h>
#include <math.h>
#include <stdint.h>

#define B_    2
#define S_    2048
#define D_    2048
#define H_    16
#define NT    4096          // B_*S_
#define QL    1024
#define KVL   512
#define NOPE_ 128
#define ROPE_ 64
#define VH_   128
#define QK_   192
#define KVP   640           // padded kv_full width
#define HQK   3072          // H_*QK_
#define SCALE 0.07216878364870322f   // 192^-0.5

// ---------------- scratch (static device globals; no runtime alloc) -------
__device__ __align__(256) __half h_x  [(size_t)NT * D_];
__device__ __align__(256) __half h_qa [(size_t)NT * QL];
__device__ __align__(256) __half h_q  [(size_t)NT * HQK];      // [tok][h][192], rope in place
__device__ __align__(256) __half h_kvf[(size_t)NT * KVP];
__device__ __align__(256) __half h_kf [(size_t)NT * KVL];      // kv_c
__device__ __align__(256) __half h_kfull[(size_t)NT * HQK];    // [tok][h][192] = [k_nope|k_pe]
__device__ __align__(256) float  g_scores[(size_t)B_ * H_ * S_ * S_];
__device__ __align__(256) __half h_probs [(size_t)B_ * H_ * S_ * S_];
__device__ __align__(256) __half h_vT [(size_t)B_ * H_ * VH_ * S_];  // [b][h][128][2048]
__device__ __align__(256) __half h_oc [(size_t)NT * H_ * VH_];
__device__ __align__(256) __half h_wqa[(size_t)QL * D_];
__device__ __align__(256) __half h_wqb[(size_t)HQK * QL];
__device__ __align__(256) __half h_wkva[(size_t)KVP * D_];
__device__ __align__(256) __half h_wkvb[(size_t)H_ * 256 * KVL];
__device__ __align__(256) __half h_wo [(size_t)D_ * H_ * VH_];
__device__ float g_biaskva[KVP];

// ---------------- helpers ---------------------------------------------------
__device__ __forceinline__ void mma_f16(float* c, const uint32_t* a, const uint32_t* b) {
    asm volatile(
        "mma.sync.aligned.m16n8k16.row.col.f32.f16.f16.f32 "
        "{%0,%1,%2,%3},{%4,%5,%6,%7},{%8,%9},{%0,%1,%2,%3};"
        : "+f"(c[0]), "+f"(c[1]), "+f"(c[2]), "+f"(c[3])
        : "r"(a[0]), "r"(a[1]), "r"(a[2]), "r"(a[3]), "r"(b[0]), "r"(b[1]));
}

__device__ __forceinline__ void ldsm4(uint32_t* r, uint32_t saddr) {
    asm volatile(
        "ldmatrix.sync.aligned.m8n8.x4.shared.b16 {%0,%1,%2,%3}, [%4];"
        : "=r"(r[0]), "=r"(r[1]), "=r"(r[2]), "=r"(r[3]) : "r"(saddr));
}

__device__ __forceinline__ void cp_async16(void* smem, const void* gmem) {
    uint32_t s = (uint32_t)__cvta_generic_to_shared(smem);
    asm volatile("cp.async.cg.shared.global [%0], [%1], 16;" :: "r"(s), "l"(gmem));
}
__device__ __forceinline__ void cp_commit() {
    asm volatile("cp.async.commit_group;");
}
template<int N>
__device__ __forceinline__ void cp_wait() {
    asm volatile("cp.async.wait_group %0;" :: "n"(N));
}

// =============================================================================
// gemm_h: fp16 in / fp32 acc. CTA tile 128 x TN (TN = 128 or 256),
// warp tile 64x64, BK=32, 3-stage cp.async, ldmatrix fragments.
// C[z] = alpha * A[z] @ B[z]^T + bias.  A [M,K], B [N,K], both half row-major.
// =============================================================================
template<int TN, bool OUTHALF>
__global__ void __launch_bounds__(TN == 256 ? 256 : 128) gemm_h(
    int K,
    const __half* __restrict__ A, int lda, long long sAb, long long sAh,
    const __half* __restrict__ Bp, int ldb, long long sBb, long long sBh,
    void* __restrict__ Cv, int ldc, long long sCb, long long sCh,
    int ZH, float alpha, const float* __restrict__ bias)
{
    constexpr int T = (TN == 256) ? 256 : 128;
    constexpr int WCOLS = TN / 64;
    constexpr int ASTR = 20;                     // u32 per row (80 B)
    constexpr int STGA = 128 * ASTR;
    constexpr int STGB = TN * ASTR;
    constexpr int AITER = 512 / T;
    constexpr int BITER = (TN * 4) / T;

    extern __shared__ uint32_t smu[];
    uint32_t* sA = smu;
    uint32_t* sB = smu + 3 * STGA;

    int z  = blockIdx.z;
    int zb = z / ZH;
    int zh = z - zb * ZH;
    const __half* Ab = A  + zb * sAb + zh * sAh;
    const __half* Bb = Bp + zb * sBb + zh * sBh;

    int row0 = blockIdx.y << 7;
    int col0 = blockIdx.x * TN;
    int tid  = threadIdx.x;
    int wid  = tid >> 5;
    int lane = tid & 31;
    int wm0 = (wid / WCOLS) << 6;
    int wn0 = (wid % WCOLS) << 6;
    int g = lane >> 2, t4 = lane & 3;
    int j = lane >> 3, r = lane & 7;

    uint32_t sA_u = (uint32_t)__cvta_generic_to_shared(sA);
    uint32_t sB_u = (uint32_t)__cvta_generic_to_shared(sB);
    uint32_t aoff0 = (uint32_t)(wm0 + (j & 1) * 8 + r) * 80 + (uint32_t)(j >> 1) * 16;
    uint32_t boff0 = (uint32_t)(wn0 + (j >> 1) * 8 + r) * 80 + (uint32_t)(j & 1) * 16;

    float acc[4][8][4] = {};

    auto load_stage = [&](int st, int k0) {
        uint32_t* a_s = sA + st * STGA;
        uint32_t* b_s = sB + st * STGB;
        #pragma unroll
        for (int i = 0; i < AITER; i++) {
            int idx = tid + T * i;
            int rr = idx >> 2, q = idx & 3;
            cp_async16(a_s + rr * ASTR + q * 4,
                       Ab + (size_t)(row0 + rr) * lda + k0 + q * 8);
        }
        #pragma unroll
        for (int i = 0; i < BITER; i++) {
            int idx = tid + T * i;
            int rr = idx >> 2, q = idx & 3;
            cp_async16(b_s + rr * ASTR + q * 4,
                       Bb + (size_t)(col0 + rr) * ldb + k0 + q * 8);
        }
    };

    int nk = K / 32;
    load_stage(0, 0);
    cp_commit();
    load_stage(1, 32);
    cp_commit();

    for (int i = 0; i < nk; i++) {
        cp_wait<1>();
        __syncthreads();
        if (i + 2 < nk) load_stage((i + 2) % 3, (i + 2) * 32);
        cp_commit();

        uint32_t abase = sA_u + (uint32_t)((i % 3) * STGA) * 4 + aoff0;
        uint32_t bbase = sB_u + (uint32_t)((i % 3) * STGB) * 4 + boff0;

        #pragma unroll
        for (int kk = 0; kk < 2; kk++) {
            uint32_t afr[4][4], bfr[4][4];
            #pragma unroll
            for (int mt = 0; mt < 4; mt++)
                ldsm4(afr[mt], abase + mt * 1280 + kk * 32);
            #pragma unroll
            for (int nt2 = 0; nt2 < 4; nt2++)
                ldsm4(bfr[nt2], bbase + nt2 * 1280 + kk * 32);
            #pragma unroll
            for (int mt = 0; mt < 4; mt++)
                #pragma unroll
                for (int nt2 = 0; nt2 < 4; nt2++) {
                    mma_f16(acc[mt][2 * nt2],     afr[mt], &bfr[nt2][0]);
                    mma_f16(acc[mt][2 * nt2 + 1], afr[mt], &bfr[nt2][2]);
                }
        }
    }

    size_t coff = (size_t)zb * sCb + (size_t)zh * sCh;
    #pragma unroll
    for (int mt = 0; mt < 4; mt++) {
        int r0 = row0 + wm0 + mt * 16 + g;
        #pragma unroll
        for (int nt = 0; nt < 8; nt++) {
            int c0c = col0 + wn0 + nt * 8 + 2 * t4;
            float b0 = bias ? bias[c0c] : 0.f;
            float b1 = bias ? bias[c0c + 1] : 0.f;
            float v00 = alpha * acc[mt][nt][0] + b0;
            float v01 = alpha * acc[mt][nt][1] + b1;
            float v10 = alpha * acc[mt][nt][2] + b0;
            float v11 = alpha * acc[mt][nt][3] + b1;
            if (OUTHALF) {
                __half* Ch = (__half*)Cv + coff;
                *(__half2*)&Ch[(size_t)r0 * ldc + c0c]       = __floats2half2_rn(v00, v01);
                *(__half2*)&Ch[(size_t)(r0 + 8) * ldc + c0c] = __floats2half2_rn(v10, v11);
            } else {
                float* Cf = (float*)Cv + coff;
                *(float2*)&Cf[(size_t)r0 * ldc + c0c]       = make_float2(v00, v01);
                *(float2*)&Cf[(size_t)(r0 + 8) * ldc + c0c] = make_float2(v10, v11);
            }
        }
    }
}

// ---------------- prepass kernels --------------------------------------------
__global__ void f2h_k(const float* __restrict__ in, __half* __restrict__ out)
{
    size_t i = ((size_t)blockIdx.x * 256 + threadIdx.x) * 4;
    float4 v = *(const float4*)(in + i);
    __half2* o = (__half2*)(out + i);
    o[0] = __floats2half2_rn(v.x, v.y);
    o[1] = __floats2half2_rn(v.z, v.w);
}

__global__ void wkva_pad_k(const float* __restrict__ in, __half* __restrict__ out)
{
    size_t i = ((size_t)blockIdx.x * 256 + threadIdx.x) * 4;
    if (i < (size_t)(KVL + ROPE_) * D_) {
        float4 v = *(const float4*)(in + i);
        __half2* o = (__half2*)(out + i);
        o[0] = __floats2half2_rn(v.x, v.y);
        o[1] = __floats2half2_rn(v.z, v.w);
    } else {
        __half2* o = (__half2*)(out + i);
        o[0] = __half2{__half(0.f), __half(0.f)};
        o[1] = __half2{__half(0.f), __half(0.f)};
    }
}

__global__ void biaskva_pad_k(const float* __restrict__ in, float* __restrict__ out)
{
    int i = blockIdx.x * 256 + threadIdx.x;
    if (i < KVP) out[i] = (i < KVL + ROPE_) ? in[i] : 0.f;
}

// ---------------- elementwise kernels -----------------------------------------
__global__ void rmsnorm_h(const __half* __restrict__ in, __half* __restrict__ out,
                          const float* __restrict__ w, int width,
                          int inStride, int outStride)
{
    int row = blockIdx.x;
    const __half* ip = in  + (size_t)row * inStride;
    __half*       op = out + (size_t)row * outStride;
    float ss = 0.f;
    for (int i = threadIdx.x; i < width; i += 256) {
        float v = __half2float(ip[i]);
        ss += v * v;
    }
    __shared__ float sm[256];
    sm[threadIdx.x] = ss;
    __syncthreads();
    for (int s = 128; s > 0; s >>= 1) {
        if (threadIdx.x < s) sm[threadIdx.x] += sm[threadIdx.x + s];
        __syncthreads();
    }
    float r = rsqrtf(sm[0] / (float)width + 1e-3f);
    for (int i = threadIdx.x; i < width; i += 256)
        op[i] = __float2half(w[i] * __half2float(ip[i]) * r);
}

// rope q in place: q[tok][h][128..191]
__global__ void rope_q_h(__half* __restrict__ q,
                         const float* __restrict__ c, const float* __restrict__ s)
{
    int tok = blockIdx.x;
    int h = threadIdx.x >> 5;
    int j = threadIdx.x & 31;
    int pos = tok % S_;
    __half* p = q + (size_t)tok * HQK + h * QK_ + NOPE_;
    float xr = __half2float(p[2 * j]), xi = __half2float(p[2 * j + 1]);
    float cc = c[pos * 32 + j], sn = s[pos * 32 + j];
    p[2 * j]     = __float2half(xr * cc - xi * sn);
    p[2 * j + 1] = __float2half(xr * sn + xi * cc);
}

// rope k_pe and broadcast to all heads of kfull[tok][h][128..191]
__global__ void rope_k_bcast_h(const __half* __restrict__ kvf, __half* __restrict__ kfull,
                               const float* __restrict__ c, const float* __restrict__ s)
{
    int tok = blockIdx.x;
    int j = threadIdx.x;   // 0..31
    int pos = tok % S_;
    const __half* src = kvf + (size_t)tok * KVP + KVL;
    float xr = __half2float(src[2 * j]), xi = __half2float(src[2 * j + 1]);
    float cc = c[pos * 32 + j], sn = s[pos * 32 + j];
    __half2 v;
    v.x = __float2half(xr * cc - xi * sn);
    v.y = __float2half(xr * sn + xi * cc);
    __half* dst = kfull + (size_t)tok * HQK + NOPE_;
    #pragma unroll
    for (int h = 0; h < H_; h++)
        *(__half2*)&dst[h * QK_ + 2 * j] = v;
}

__global__ void softmax_h(const float* __restrict__ d, __half* __restrict__ pr)
{
    size_t row = blockIdx.x;
    const float* p = d + row * (size_t)S_;
    __half* ph = pr + row * (size_t)S_;
    int t = threadIdx.x;
    float v[8];
    float m = -INFINITY;
    #pragma unroll
    for (int i = 0; i < 8; i++) {
        v[i] = p[t + i * 256];
        m = fmaxf(m, v[i]);
    }
    __shared__ float sm[256];
    sm[t] = m;
    __syncthreads();
    for (int s = 128; s > 0; s >>= 1) {
        if (t < s) sm[t] = fmaxf(sm[t], sm[t + s]);
        __syncthreads();
    }
    m = sm[0];
    __syncthreads();
    float sum = 0.f;
    #pragma unroll
    for (int i = 0; i < 8; i++) {
        v[i] = __expf(v[i] - m);
        sum += v[i];
    }
    sm[t] = sum;
    __syncthreads();
    for (int s = 128; s > 0; s >>= 1) {
        if (t < s) sm[t] += sm[t + s];
        __syncthreads();
    }
    float inv = 1.f / sm[0];
    #pragma unroll
    for (int i = 0; i < 8; i++)
        ph[t + i * 256] = __float2half(v[i] * inv);
}

// ---------------- host glue --------------------------------------------------
template<int TN, bool OUTHALF>
static void launch_h(int M, int N, int K,
                     const __half* A, int lda, long long sAb, long long sAh,
                     const __half* Bp, int ldb, long long sBb, long long sBh,
                     void* C, int ldc, long long sCb, long long sCh,
                     int nb, int nh, float alpha, const float* bias)
{
    constexpr int SMEM = (3 * 128 * 20 + 3 * TN * 20) * 4;
    cudaFuncSetAttribute(gemm_h<TN, OUTHALF>,
                         cudaFuncAttributeMaxDynamicSharedMemorySize, SMEM);
    dim3 grid(N / TN, M / 128, nb * nh);
    gemm_h<TN, OUTHALF><<<grid, TN == 256 ? 256 : 128, SMEM>>>(
        K, A, lda, sAb, sAh, Bp, ldb, sBb, sBh, C, ldc, sCb, sCh, nh, alpha, bias);
}

static void f2h(const float* in, __half* out, size_t n)
{
    f2h_k<<<(unsigned)(n / 1024), 256>>>(in, out);
}

extern "C" void kernel_launch(void* const* d_in, const int* in_sizes, int n_in,
                              void* d_out, int out_size)
{
    const float* x        = (const float*)d_in[0];
    const float* cosp     = (const float*)d_in[2];
    const float* sinp     = (const float*)d_in[3];
    const float* wq_a_w   = (const float*)d_in[4];
    const float* wq_a_b   = (const float*)d_in[5];
    const float* q_norm_w = (const float*)d_in[6];
    const float* wq_b_w   = (const float*)d_in[7];
    const float* wq_b_b   = (const float*)d_in[8];
    const float* wkv_a_w  = (const float*)d_in[9];
    const float* kv_norm_w= (const float*)d_in[11];
    const float* wkv_b_w  = (const float*)d_in[12];
    const float* wo_w     = (const float*)d_in[13];
    const float* wo_b     = (const float*)d_in[14];
    float* out = (float*)d_out;

    __half *xh, *qa, *q, *kvf, *kf, *kfull, *probs, *vT, *oc;
    __half *wqa, *wqb, *wkva, *wkvb, *wo;
    float *sc, *bkva;
    cudaGetSymbolAddress((void**)&xh,   h_x);
    cudaGetSymbolAddress((void**)&qa,   h_qa);
    cudaGetSymbolAddress((void**)&q,    h_q);
    cudaGetSymbolAddress((void**)&kvf,  h_kvf);
    cudaGetSymbolAddress((void**)&kf,   h_kf);
    cudaGetSymbolAddress((void**)&kfull,h_kfull);
    cudaGetSymbolAddress((void**)&sc,   g_scores);
    cudaGetSymbolAddress((void**)&probs,h_probs);
    cudaGetSymbolAddress((void**)&vT,   h_vT);
    cudaGetSymbolAddress((void**)&oc,   h_oc);
    cudaGetSymbolAddress((void**)&wqa,  h_wqa);
    cudaGetSymbolAddress((void**)&wqb,  h_wqb);
    cudaGetSymbolAddress((void**)&wkva, h_wkva);
    cudaGetSymbolAddress((void**)&wkvb, h_wkvb);
    cudaGetSymbolAddress((void**)&wo,   h_wo);
    cudaGetSymbolAddress((void**)&bkva, g_biaskva);

    // 0,1) convert x, wq_a
    f2h(x,      xh,  (size_t)NT * D_);
    f2h(wq_a_w, wqa, (size_t)QL * D_);
    // 2) q_a = x @ wq_a^T + b           [4096,1024] K=2048
    launch_h<256, true>(NT, QL, D_, xh, D_, 0, 0, wqa, D_, 0, 0,
                        qa, QL, 0, 0, 1, 1, 1.f, wq_a_b);
    // 3) rmsnorm(q_a) in place
    rmsnorm_h<<<NT, 256>>>(qa, qa, q_norm_w, QL, QL, QL);
    // 4) convert wq_b
    f2h(wq_b_w, wqb, (size_t)HQK * QL);
    // 5) q = q_a_n @ wq_b^T + b         [4096,3072] K=1024   <-- profiled
    launch_h<256, true>(NT, HQK, QL, qa, QL, 0, 0, wqb, QL, 0, 0,
                        q, HQK, 0, 0, 1, 1, 1.f, wq_b_b);
    // 6,7) wkva pad + bias pad
    wkva_pad_k<<<(unsigned)((size_t)KVP * D_ / 1024), 256>>>(wkv_a_w, wkva);
    biaskva_pad_k<<<3, 256>>>((const float*)d_in[10], bkva);
    // 8) kv_full = x @ wkva_pad^T + b   [4096,640] K=2048
    launch_h<128, true>(NT, KVP, D_, xh, D_, 0, 0, wkva, D_, 0, 0,
                        kvf, KVP, 0, 0, 1, 1, 1.f, bkva);
    // 9) convert wkv_b
    f2h(wkv_b_w, wkvb, (size_t)H_ * 256 * KVL);
    // 10) kv_c = rmsnorm(kv_full[:, :512])  -> kf [4096,512]
    rmsnorm_h<<<NT, 256>>>(kvf, kf, kv_norm_w, KVL, KVP, KVL);
    // 11) kfull[:, h, 128:192] = rope(k_pe) broadcast to all heads
    rope_k_bcast_h<<<NT, 32>>>(kvf, kfull, cosp, sinp);
    // 12) q[:, h, 128:192] = rope(q_pe) in place
    rope_q_h<<<NT, 512>>>(q, cosp, sinp);
    // 13) kfull[:, h, :128] = kv_c @ wkvb_nope[h]^T   [4096,128] K=512, x16 heads
    launch_h<128, true>(NT, NOPE_, KVL,
                        kf, KVL, 0, 0,
                        wkvb, KVL, 0, (long long)256 * KVL,
                        kfull, HQK, 0, QK_,
                        1, H_, 1.f, nullptr);
    // 14) scores = SCALE * q @ kfull^T  [2048,2048]x32 K=192 -> fp32
    launch_h<256, false>(S_, S_, QK_,
                         q, HQK, (long long)S_ * HQK, QK_,
                         kfull, HQK, (long long)S_ * HQK, QK_,
                         sc, S_, (long long)H_ * S_ * S_, (long long)S_ * S_,
                         B_, H_, SCALE, nullptr);
    // 15) softmax -> half probs
    softmax_h<<<B_ * H_ * S_, 256>>>(sc, probs);
    // 16) vT[b,h] = wkvb_v[h] @ kv_c[b]^T   [128,2048] K=512, x32
    launch_h<256, true>(VH_, S_, KVL,
                        wkvb + (size_t)NOPE_ * KVL, KVL, 0, (long long)256 * KVL,
                        kf, KVL, (long long)S_ * KVL, 0,
                        vT, S_, (long long)H_ * VH_ * S_, (long long)VH_ * S_,
                        B_, H_, 1.f, nullptr);
    // 17) oc[b,s,h,:] = probs[b,h] @ vT[b,h]^T   [2048,128] K=2048, x32
    launch_h<128, true>(S_, VH_, S_,
                        probs, S_, (long long)H_ * S_ * S_, (long long)S_ * S_,
                        vT, S_, (long long)H_ * VH_ * S_, (long long)VH_ * S_,
                        oc, H_ * VH_, (long long)S_ * H_ * VH_, VH_,
                        B_, H_, 1.f, nullptr);
    // 18) convert wo
    f2h(wo_w, wo, (size_t)D_ * H_ * VH_);
    // 19) out = oc @ wo^T + b           [4096,2048] K=2048 -> fp32
    launch_h<256, false>(NT, D_, H_ * VH_, oc, H_ * VH_, 0, 0, wo, D_, 0, 0,
                         out, D_, 0, 0, 1, 1, 1.f, wo_b);
}

// round 10
// speedup vs baseline: 1.7143x; 1.0002x over previous
#include <cuda_runtime.h>
#include <cuda_fp16.h>
#include <math.h>
#include <stdint.h>

#define B_    2
#define S_    2048
#define D_    2048
#define H_    16
#define NT    4096          // B_*S_
#define QL    1024
#define KVL   512
#define NOPE_ 128
#define ROPE_ 64
#define VH_   128
#define QK_   192
#define KVP   640           // padded kv_full width
#define HQK   3072          // H_*QK_
#define SCALE 0.07216878364870322f   // 192^-0.5

// ---------------- scratch (static device globals; no runtime alloc) -------
__device__ __align__(256) __half h_x  [(size_t)NT * D_];
__device__ __align__(256) __half h_qa [(size_t)NT * QL];
__device__ __align__(256) __half h_q  [(size_t)NT * HQK];      // [tok][h][192], rope in place
__device__ __align__(256) __half h_kvf[(size_t)NT * KVP];
__device__ __align__(256) __half h_kf [(size_t)NT * KVL];      // kv_c
__device__ __align__(256) __half h_kfull[(size_t)NT * HQK];    // [tok][h][192] = [k_nope|k_pe]
__device__ __align__(256) float  g_scores[(size_t)B_ * H_ * S_ * S_];
__device__ __align__(256) __half h_probs [(size_t)B_ * H_ * S_ * S_];
__device__ __align__(256) __half h_vT [(size_t)B_ * H_ * VH_ * S_];  // [b][h][128][2048]
__device__ __align__(256) __half h_oc [(size_t)NT * H_ * VH_];
__device__ __align__(256) __half h_wqa[(size_t)QL * D_];
__device__ __align__(256) __half h_wqb[(size_t)HQK * QL];
__device__ __align__(256) __half h_wkva[(size_t)KVP * D_];
__device__ __align__(256) __half h_wkvb[(size_t)H_ * 256 * KVL];
__device__ __align__(256) __half h_wo [(size_t)D_ * H_ * VH_];
__device__ float g_biaskva[KVP];

// ---------------- helpers ---------------------------------------------------
__device__ __forceinline__ void mma_f16(float* c, const uint32_t* a, const uint32_t* b) {
    asm volatile(
        "mma.sync.aligned.m16n8k16.row.col.f32.f16.f16.f32 "
        "{%0,%1,%2,%3},{%4,%5,%6,%7},{%8,%9},{%0,%1,%2,%3};"
        : "+f"(c[0]), "+f"(c[1]), "+f"(c[2]), "+f"(c[3])
        : "r"(a[0]), "r"(a[1]), "r"(a[2]), "r"(a[3]), "r"(b[0]), "r"(b[1]));
}

__device__ __forceinline__ void ldsm4(uint32_t* r, uint32_t saddr) {
    asm volatile(
        "ldmatrix.sync.aligned.m8n8.x4.shared.b16 {%0,%1,%2,%3}, [%4];"
        : "=r"(r[0]), "=r"(r[1]), "=r"(r[2]), "=r"(r[3]) : "r"(saddr));
}

__device__ __forceinline__ void cp_async16(void* smem, const void* gmem) {
    uint32_t s = (uint32_t)__cvta_generic_to_shared(smem);
    asm volatile("cp.async.cg.shared.global [%0], [%1], 16;" :: "r"(s), "l"(gmem));
}
__device__ __forceinline__ void cp_commit() {
    asm volatile("cp.async.commit_group;");
}
template<int N>
__device__ __forceinline__ void cp_wait() {
    asm volatile("cp.async.wait_group %0;" :: "n"(N));
}

// =============================================================================
// gemm_h: fp16 in / fp32 acc. CTA tile 128 x TN (TN = 128 or 256),
// warp tile 64x64, BK=32, 3-stage cp.async, ldmatrix fragments.
// C[z] = alpha * A[z] @ B[z]^T + bias.  A [M,K], B [N,K], both half row-major.
// =============================================================================
template<int TN, bool OUTHALF>
__global__ void __launch_bounds__(TN == 256 ? 256 : 128) gemm_h(
    int K,
    const __half* __restrict__ A, int lda, long long sAb, long long sAh,
    const __half* __restrict__ Bp, int ldb, long long sBb, long long sBh,
    void* __restrict__ Cv, int ldc, long long sCb, long long sCh,
    int ZH, float alpha, const float* __restrict__ bias)
{
    constexpr int T = (TN == 256) ? 256 : 128;
    constexpr int WCOLS = TN / 64;
    constexpr int ASTR = 20;                     // u32 per row (80 B)
    constexpr int STGA = 128 * ASTR;
    constexpr int STGB = TN * ASTR;
    constexpr int AITER = 512 / T;
    constexpr int BITER = (TN * 4) / T;

    extern __shared__ uint32_t smu[];
    uint32_t* sA = smu;
    uint32_t* sB = smu + 3 * STGA;

    int z  = blockIdx.z;
    int zb = z / ZH;
    int zh = z - zb * ZH;
    const __half* Ab = A  + zb * sAb + zh * sAh;
    const __half* Bb = Bp + zb * sBb + zh * sBh;

    int row0 = blockIdx.y << 7;
    int col0 = blockIdx.x * TN;
    int tid  = threadIdx.x;
    int wid  = tid >> 5;
    int lane = tid & 31;
    int wm0 = (wid / WCOLS) << 6;
    int wn0 = (wid % WCOLS) << 6;
    int g = lane >> 2, t4 = lane & 3;
    int j = lane >> 3, r = lane & 7;

    uint32_t sA_u = (uint32_t)__cvta_generic_to_shared(sA);
    uint32_t sB_u = (uint32_t)__cvta_generic_to_shared(sB);
    uint32_t aoff0 = (uint32_t)(wm0 + (j & 1) * 8 + r) * 80 + (uint32_t)(j >> 1) * 16;
    uint32_t boff0 = (uint32_t)(wn0 + (j >> 1) * 8 + r) * 80 + (uint32_t)(j & 1) * 16;

    float acc[4][8][4] = {};

    auto load_stage = [&](int st, int k0) {
        uint32_t* a_s = sA + st * STGA;
        uint32_t* b_s = sB + st * STGB;
        #pragma unroll
        for (int i = 0; i < AITER; i++) {
            int idx = tid + T * i;
            int rr = idx >> 2, q = idx & 3;
            cp_async16(a_s + rr * ASTR + q * 4,
                       Ab + (size_t)(row0 + rr) * lda + k0 + q * 8);
        }
        #pragma unroll
        for (int i = 0; i < BITER; i++) {
            int idx = tid + T * i;
            int rr = idx >> 2, q = idx & 3;
            cp_async16(b_s + rr * ASTR + q * 4,
                       Bb + (size_t)(col0 + rr) * ldb + k0 + q * 8);
        }
    };

    int nk = K / 32;
    load_stage(0, 0);
    cp_commit();
    load_stage(1, 32);
    cp_commit();

    for (int i = 0; i < nk; i++) {
        cp_wait<1>();
        __syncthreads();
        if (i + 2 < nk) load_stage((i + 2) % 3, (i + 2) * 32);
        cp_commit();

        uint32_t abase = sA_u + (uint32_t)((i % 3) * STGA) * 4 + aoff0;
        uint32_t bbase = sB_u + (uint32_t)((i % 3) * STGB) * 4 + boff0;

        #pragma unroll
        for (int kk = 0; kk < 2; kk++) {
            uint32_t afr[4][4], bfr[4][4];
            #pragma unroll
            for (int mt = 0; mt < 4; mt++)
                ldsm4(afr[mt], abase + mt * 1280 + kk * 32);
            #pragma unroll
            for (int nt2 = 0; nt2 < 4; nt2++)
                ldsm4(bfr[nt2], bbase + nt2 * 1280 + kk * 32);
            #pragma unroll
            for (int mt = 0; mt < 4; mt++)
                #pragma unroll
                for (int nt2 = 0; nt2 < 4; nt2++) {
                    mma_f16(acc[mt][2 * nt2],     afr[mt], &bfr[nt2][0]);
                    mma_f16(acc[mt][2 * nt2 + 1], afr[mt], &bfr[nt2][2]);
                }
        }
    }

    size_t coff = (size_t)zb * sCb + (size_t)zh * sCh;
    #pragma unroll
    for (int mt = 0; mt < 4; mt++) {
        int r0 = row0 + wm0 + mt * 16 + g;
        #pragma unroll
        for (int nt = 0; nt < 8; nt++) {
            int c0c = col0 + wn0 + nt * 8 + 2 * t4;
            float b0 = bias ? bias[c0c] : 0.f;
            float b1 = bias ? bias[c0c + 1] : 0.f;
            float v00 = alpha * acc[mt][nt][0] + b0;
            float v01 = alpha * acc[mt][nt][1] + b1;
            float v10 = alpha * acc[mt][nt][2] + b0;
            float v11 = alpha * acc[mt][nt][3] + b1;
            if (OUTHALF) {
                __half* Ch = (__half*)Cv + coff;
                *(__half2*)&Ch[(size_t)r0 * ldc + c0c]       = __floats2half2_rn(v00, v01);
                *(__half2*)&Ch[(size_t)(r0 + 8) * ldc + c0c] = __floats2half2_rn(v10, v11);
            } else {
                float* Cf = (float*)Cv + coff;
                *(float2*)&Cf[(size_t)r0 * ldc + c0c]       = make_float2(v00, v01);
                *(float2*)&Cf[(size_t)(r0 + 8) * ldc + c0c] = make_float2(v10, v11);
            }
        }
    }
}

// ---------------- prepass kernels --------------------------------------------
__global__ void f2h_k(const float* __restrict__ in, __half* __restrict__ out)
{
    size_t i = ((size_t)blockIdx.x * 256 + threadIdx.x) * 4;
    float4 v = *(const float4*)(in + i);
    __half2* o = (__half2*)(out + i);
    o[0] = __floats2half2_rn(v.x, v.y);
    o[1] = __floats2half2_rn(v.z, v.w);
}

__global__ void wkva_pad_k(const float* __restrict__ in, __half* __restrict__ out)
{
    size_t i = ((size_t)blockIdx.x * 256 + threadIdx.x) * 4;
    if (i < (size_t)(KVL + ROPE_) * D_) {
        float4 v = *(const float4*)(in + i);
        __half2* o = (__half2*)(out + i);
        o[0] = __floats2half2_rn(v.x, v.y);
        o[1] = __floats2half2_rn(v.z, v.w);
    } else {
        __half2* o = (__half2*)(out + i);
        o[0] = __half2{__half(0.f), __half(0.f)};
        o[1] = __half2{__half(0.f), __half(0.f)};
    }
}

__global__ void biaskva_pad_k(const float* __restrict__ in, float* __restrict__ out)
{
    int i = blockIdx.x * 256 + threadIdx.x;
    if (i < KVP) out[i] = (i < KVL + ROPE_) ? in[i] : 0.f;
}

// ---------------- elementwise kernels -----------------------------------------
__global__ void rmsnorm_h(const __half* __restrict__ in, __half* __restrict__ out,
                          const float* __restrict__ w, int width,
                          int inStride, int outStride)
{
    int row = blockIdx.x;
    const __half* ip = in  + (size_t)row * inStride;
    __half*       op = out + (size_t)row * outStride;
    float ss = 0.f;
    for (int i = threadIdx.x; i < width; i += 256) {
        float v = __half2float(ip[i]);
        ss += v * v;
    }
    __shared__ float sm[256];
    sm[threadIdx.x] = ss;
    __syncthreads();
    for (int s = 128; s > 0; s >>= 1) {
        if (threadIdx.x < s) sm[threadIdx.x] += sm[threadIdx.x + s];
        __syncthreads();
    }
    float r = rsqrtf(sm[0] / (float)width + 1e-3f);
    for (int i = threadIdx.x; i < width; i += 256)
        op[i] = __float2half(w[i] * __half2float(ip[i]) * r);
}

// rope q in place: q[tok][h][128..191]
__global__ void rope_q_h(__half* __restrict__ q,
                         const float* __restrict__ c, const float* __restrict__ s)
{
    int tok = blockIdx.x;
    int h = threadIdx.x >> 5;
    int j = threadIdx.x & 31;
    int pos = tok % S_;
    __half* p = q + (size_t)tok * HQK + h * QK_ + NOPE_;
    float xr = __half2float(p[2 * j]), xi = __half2float(p[2 * j + 1]);
    float cc = c[pos * 32 + j], sn = s[pos * 32 + j];
    p[2 * j]     = __float2half(xr * cc - xi * sn);
    p[2 * j + 1] = __float2half(xr * sn + xi * cc);
}

// rope k_pe and broadcast to all heads of kfull[tok][h][128..191]
__global__ void rope_k_bcast_h(const __half* __restrict__ kvf, __half* __restrict__ kfull,
                               const float* __restrict__ c, const float* __restrict__ s)
{
    int tok = blockIdx.x;
    int j = threadIdx.x;   // 0..31
    int pos = tok % S_;
    const __half* src = kvf + (size_t)tok * KVP + KVL;
    float xr = __half2float(src[2 * j]), xi = __half2float(src[2 * j + 1]);
    float cc = c[pos * 32 + j], sn = s[pos * 32 + j];
    __half2 v;
    v.x = __float2half(xr * cc - xi * sn);
    v.y = __float2half(xr * sn + xi * cc);
    __half* dst = kfull + (size_t)tok * HQK + NOPE_;
    #pragma unroll
    for (int h = 0; h < H_; h++)
        *(__half2*)&dst[h * QK_ + 2 * j] = v;
}

__global__ void softmax_h(const float* __restrict__ d, __half* __restrict__ pr)
{
    size_t row = blockIdx.x;
    const float* p = d + row * (size_t)S_;
    __half* ph = pr + row * (size_t)S_;
    int t = threadIdx.x;
    float v[8];
    float m = -INFINITY;
    #pragma unroll
    for (int i = 0; i < 8; i++) {
        v[i] = p[t + i * 256];
        m = fmaxf(m, v[i]);
    }
    __shared__ float sm[256];
    sm[t] = m;
    __syncthreads();
    for (int s = 128; s > 0; s >>= 1) {
        if (t < s) sm[t] = fmaxf(sm[t], sm[t + s]);
        __syncthreads();
    }
    m = sm[0];
    __syncthreads();
    float sum = 0.f;
    #pragma unroll
    for (int i = 0; i < 8; i++) {
        v[i] = __expf(v[i] - m);
        sum += v[i];
    }
    sm[t] = sum;
    __syncthreads();
    for (int s = 128; s > 0; s >>= 1) {
        if (t < s) sm[t] += sm[t + s];
        __syncthreads();
    }
    float inv = 1.f / sm[0];
    #pragma unroll
    for (int i = 0; i < 8; i++)
        ph[t + i * 256] = __float2half(v[i] * inv);
}

// ---------------- host glue --------------------------------------------------
template<int TN, bool OUTHALF>
static void launch_h(int M, int N, int K,
                     const __half* A, int lda, long long sAb, long long sAh,
                     const __half* Bp, int ldb, long long sBb, long long sBh,
                     void* C, int ldc, long long sCb, long long sCh,
                     int nb, int nh, float alpha, const float* bias)
{
    constexpr int SMEM = (3 * 128 * 20 + 3 * TN * 20) * 4;
    cudaFuncSetAttribute(gemm_h<TN, OUTHALF>,
                         cudaFuncAttributeMaxDynamicSharedMemorySize, SMEM);
    dim3 grid(N / TN, M / 128, nb * nh);
    gemm_h<TN, OUTHALF><<<grid, TN == 256 ? 256 : 128, SMEM>>>(
        K, A, lda, sAb, sAh, Bp, ldb, sBb, sBh, C, ldc, sCb, sCh, nh, alpha, bias);
}

static void f2h(const float* in, __half* out, size_t n)
{
    f2h_k<<<(unsigned)(n / 1024), 256>>>(in, out);
}

extern "C" void kernel_launch(void* const* d_in, const int* in_sizes, int n_in,
                              void* d_out, int out_size)
{
    const float* x        = (const float*)d_in[0];
    const float* cosp     = (const float*)d_in[2];
    const float* sinp     = (const float*)d_in[3];
    const float* wq_a_w   = (const float*)d_in[4];
    const float* wq_a_b   = (const float*)d_in[5];
    const float* q_norm_w = (const float*)d_in[6];
    const float* wq_b_w   = (const float*)d_in[7];
    const float* wq_b_b   = (const float*)d_in[8];
    const float* wkv_a_w  = (const float*)d_in[9];
    const float* kv_norm_w= (const float*)d_in[11];
    const float* wkv_b_w  = (const float*)d_in[12];
    const float* wo_w     = (const float*)d_in[13];
    const float* wo_b     = (const float*)d_in[14];
    float* out = (float*)d_out;

    __half *xh, *qa, *q, *kvf, *kf, *kfull, *probs, *vT, *oc;
    __half *wqa, *wqb, *wkva, *wkvb, *wo;
    float *sc, *bkva;
    cudaGetSymbolAddress((void**)&xh,   h_x);
    cudaGetSymbolAddress((void**)&qa,   h_qa);
    cudaGetSymbolAddress((void**)&q,    h_q);
    cudaGetSymbolAddress((void**)&kvf,  h_kvf);
    cudaGetSymbolAddress((void**)&kf,   h_kf);
    cudaGetSymbolAddress((void**)&kfull,h_kfull);
    cudaGetSymbolAddress((void**)&sc,   g_scores);
    cudaGetSymbolAddress((void**)&probs,h_probs);
    cudaGetSymbolAddress((void**)&vT,   h_vT);
    cudaGetSymbolAddress((void**)&oc,   h_oc);
    cudaGetSymbolAddress((void**)&wqa,  h_wqa);
    cudaGetSymbolAddress((void**)&wqb,  h_wqb);
    cudaGetSymbolAddress((void**)&wkva, h_wkva);
    cudaGetSymbolAddress((void**)&wkvb, h_wkvb);
    cudaGetSymbolAddress((void**)&wo,   h_wo);
    cudaGetSymbolAddress((void**)&bkva, g_biaskva);

    // 0,1) convert x, wq_a
    f2h(x,      xh,  (size_t)NT * D_);
    f2h(wq_a_w, wqa, (size_t)QL * D_);
    // 2) q_a = x @ wq_a^T + b           [4096,1024] K=2048
    launch_h<256, true>(NT, QL, D_, xh, D_, 0, 0, wqa, D_, 0, 0,
                        qa, QL, 0, 0, 1, 1, 1.f, wq_a_b);
    // 3) rmsnorm(q_a) in place
    rmsnorm_h<<<NT, 256>>>(qa, qa, q_norm_w, QL, QL, QL);
    // 4) convert wq_b
    f2h(wq_b_w, wqb, (size_t)HQK * QL);
    // 5) q = q_a_n @ wq_b^T + b         [4096,3072] K=1024   <-- profiled
    launch_h<256, true>(NT, HQK, QL, qa, QL, 0, 0, wqb, QL, 0, 0,
                        q, HQK, 0, 0, 1, 1, 1.f, wq_b_b);
    // 6,7) wkva pad + bias pad
    wkva_pad_k<<<(unsigned)((size_t)KVP * D_ / 1024), 256>>>(wkv_a_w, wkva);
    biaskva_pad_k<<<3, 256>>>((const float*)d_in[10], bkva);
    // 8) kv_full = x @ wkva_pad^T + b   [4096,640] K=2048
    launch_h<128, true>(NT, KVP, D_, xh, D_, 0, 0, wkva, D_, 0, 0,
                        kvf, KVP, 0, 0, 1, 1, 1.f, bkva);
    // 9) convert wkv_b
    f2h(wkv_b_w, wkvb, (size_t)H_ * 256 * KVL);
    // 10) kv_c = rmsnorm(kv_full[:, :512])  -> kf [4096,512]
    rmsnorm_h<<<NT, 256>>>(kvf, kf, kv_norm_w, KVL, KVP, KVL);
    // 11) kfull[:, h, 128:192] = rope(k_pe) broadcast to all heads
    rope_k_bcast_h<<<NT, 32>>>(kvf, kfull, cosp, sinp);
    // 12) q[:, h, 128:192] = rope(q_pe) in place
    rope_q_h<<<NT, 512>>>(q, cosp, sinp);
    // 13) kfull[:, h, :128] = kv_c @ wkvb_nope[h]^T   [4096,128] K=512, x16 heads
    launch_h<128, true>(NT, NOPE_, KVL,
                        kf, KVL, 0, 0,
                        wkvb, KVL, 0, (long long)256 * KVL,
                        kfull, HQK, 0, QK_,
                        1, H_, 1.f, nullptr);
    // 14) scores = SCALE * q @ kfull^T  [2048,2048]x32 K=192 -> fp32
    launch_h<256, false>(S_, S_, QK_,
                         q, HQK, (long long)S_ * HQK, QK_,
                         kfull, HQK, (long long)S_ * HQK, QK_,
                         sc, S_, (long long)H_ * S_ * S_, (long long)S_ * S_,
                         B_, H_, SCALE, nullptr);
    // 15) softmax -> half probs
    softmax_h<<<B_ * H_ * S_, 256>>>(sc, probs);
    // 16) vT[b,h] = wkvb_v[h] @ kv_c[b]^T   [128,2048] K=512, x32
    launch_h<256, true>(VH_, S_, KVL,
                        wkvb + (size_t)NOPE_ * KVL, KVL, 0, (long long)256 * KVL,
                        kf, KVL, (long long)S_ * KVL, 0,
                        vT, S_, (long long)H_ * VH_ * S_, (long long)VH_ * S_,
                        B_, H_, 1.f, nullptr);
    // 17) oc[b,s,h,:] = probs[b,h] @ vT[b,h]^T   [2048,128] K=2048, x32
    launch_h<128, true>(S_, VH_, S_,
                        probs, S_, (long long)H_ * S_ * S_, (long long)S_ * S_,
                        vT, S_, (long long)H_ * VH_ * S_, (long long)VH_ * S_,
                        oc, H_ * VH_, (long long)S_ * H_ * VH_, VH_,
                        B_, H_, 1.f, nullptr);
    // 18) convert wo
    f2h(wo_w, wo, (size_t)D_ * H_ * VH_);
    // 19) out = oc @ wo^T + b           [4096,2048] K=2048 -> fp32
    launch_h<256, false>(NT, D_, H_ * VH_, oc, H_ * VH_, 0, 0, wo, D_, 0, 0,
                         out, D_, 0, 0, 1, 1, 1.f, wo_b);
}

// round 11
// speedup vs baseline: 2.1426x; 1.2498x over previous
#include <cuda_runtime.h>
#include <cuda_fp16.h>
#include <math.h>
#include <stdint.h>

#define B_    2
#define S_    2048
#define D_    2048
#define H_    16
#define NT    4096          // B_*S_
#define QL    1024
#define KVL   512
#define NOPE_ 128
#define ROPE_ 64
#define VH_   128
#define QK_   192
#define KVP   640           // padded kv_full width
#define HQK   3072          // H_*QK_
#define SCALE 0.07216878364870322f   // 192^-0.5

// ---------------- scratch (static device globals; no runtime alloc) -------
__device__ __align__(256) __half h_x  [(size_t)NT * D_];
__device__ __align__(256) __half h_qa [(size_t)NT * QL];
__device__ __align__(256) __half h_q  [(size_t)NT * HQK];      // [tok][h][192], rope in place
__device__ __align__(256) __half h_kvf[(size_t)NT * KVP];
__device__ __align__(256) __half h_kf [(size_t)NT * KVL];      // kv_c
__device__ __align__(256) __half h_kfull[(size_t)NT * HQK];    // [tok][h][192] = [k_nope|k_pe]
__device__ __align__(256) __half h_vT [(size_t)B_ * H_ * VH_ * S_];  // [b][h][128][2048]
__device__ __align__(256) __half h_oc [(size_t)NT * H_ * VH_];
__device__ __align__(256) __half h_wqa[(size_t)QL * D_];
__device__ __align__(256) __half h_wqb[(size_t)HQK * QL];
__device__ __align__(256) __half h_wkva[(size_t)KVP * D_];
__device__ __align__(256) __half h_wkvb[(size_t)H_ * 256 * KVL];
__device__ __align__(256) __half h_wo [(size_t)D_ * H_ * VH_];
__device__ float g_biaskva[KVP];

// ---------------- helpers ---------------------------------------------------
__device__ __forceinline__ void mma_f16(float* c, const uint32_t* a, const uint32_t* b) {
    asm volatile(
        "mma.sync.aligned.m16n8k16.row.col.f32.f16.f16.f32 "
        "{%0,%1,%2,%3},{%4,%5,%6,%7},{%8,%9},{%0,%1,%2,%3};"
        : "+f"(c[0]), "+f"(c[1]), "+f"(c[2]), "+f"(c[3])
        : "r"(a[0]), "r"(a[1]), "r"(a[2]), "r"(a[3]), "r"(b[0]), "r"(b[1]));
}

__device__ __forceinline__ void ldsm4(uint32_t* r, uint32_t saddr) {
    asm volatile(
        "ldmatrix.sync.aligned.m8n8.x4.shared.b16 {%0,%1,%2,%3}, [%4];"
        : "=r"(r[0]), "=r"(r[1]), "=r"(r[2]), "=r"(r[3]) : "r"(saddr));
}

__device__ __forceinline__ void cp_async16(void* smem, const void* gmem) {
    uint32_t s = (uint32_t)__cvta_generic_to_shared(smem);
    asm volatile("cp.async.cg.shared.global [%0], [%1], 16;" :: "r"(s), "l"(gmem));
}
__device__ __forceinline__ void cp_commit() {
    asm volatile("cp.async.commit_group;");
}
template<int N>
__device__ __forceinline__ void cp_wait() {
    asm volatile("cp.async.wait_group %0;" :: "n"(N));
}

// =============================================================================
// gemm_h: fp16 in / fp32 acc. CTA tile 128 x TN (TN = 128 or 256),
// warp tile 64x64, BK=32, 3-stage cp.async, ldmatrix fragments.
// C[z] = alpha * A[z] @ B[z]^T + bias.  A [M,K], B [N,K], both half row-major.
// =============================================================================
template<int TN, bool OUTHALF>
__global__ void __launch_bounds__(TN == 256 ? 256 : 128) gemm_h(
    int K,
    const __half* __restrict__ A, int lda, long long sAb, long long sAh,
    const __half* __restrict__ Bp, int ldb, long long sBb, long long sBh,
    void* __restrict__ Cv, int ldc, long long sCb, long long sCh,
    int ZH, float alpha, const float* __restrict__ bias)
{
    constexpr int T = (TN == 256) ? 256 : 128;
    constexpr int WCOLS = TN / 64;
    constexpr int ASTR = 20;                     // u32 per row (80 B)
    constexpr int STGA = 128 * ASTR;
    constexpr int STGB = TN * ASTR;
    constexpr int AITER = 512 / T;
    constexpr int BITER = (TN * 4) / T;

    extern __shared__ uint32_t smu[];
    uint32_t* sA = smu;
    uint32_t* sB = smu + 3 * STGA;

    int z  = blockIdx.z;
    int zb = z / ZH;
    int zh = z - zb * ZH;
    const __half* Ab = A  + zb * sAb + zh * sAh;
    const __half* Bb = Bp + zb * sBb + zh * sBh;

    int row0 = blockIdx.y << 7;
    int col0 = blockIdx.x * TN;
    int tid  = threadIdx.x;
    int wid  = tid >> 5;
    int lane = tid & 31;
    int wm0 = (wid / WCOLS) << 6;
    int wn0 = (wid % WCOLS) << 6;
    int g = lane >> 2, t4 = lane & 3;
    int j = lane >> 3, r = lane & 7;

    uint32_t sA_u = (uint32_t)__cvta_generic_to_shared(sA);
    uint32_t sB_u = (uint32_t)__cvta_generic_to_shared(sB);
    uint32_t aoff0 = (uint32_t)(wm0 + (j & 1) * 8 + r) * 80 + (uint32_t)(j >> 1) * 16;
    uint32_t boff0 = (uint32_t)(wn0 + (j >> 1) * 8 + r) * 80 + (uint32_t)(j & 1) * 16;

    float acc[4][8][4] = {};

    auto load_stage = [&](int st, int k0) {
        uint32_t* a_s = sA + st * STGA;
        uint32_t* b_s = sB + st * STGB;
        #pragma unroll
        for (int i = 0; i < AITER; i++) {
            int idx = tid + T * i;
            int rr = idx >> 2, q = idx & 3;
            cp_async16(a_s + rr * ASTR + q * 4,
                       Ab + (size_t)(row0 + rr) * lda + k0 + q * 8);
        }
        #pragma unroll
        for (int i = 0; i < BITER; i++) {
            int idx = tid + T * i;
            int rr = idx >> 2, q = idx & 3;
            cp_async16(b_s + rr * ASTR + q * 4,
                       Bb + (size_t)(col0 + rr) * ldb + k0 + q * 8);
        }
    };

    int nk = K / 32;
    load_stage(0, 0);
    cp_commit();
    load_stage(1, 32);
    cp_commit();

    for (int i = 0; i < nk; i++) {
        cp_wait<1>();
        __syncthreads();
        if (i + 2 < nk) load_stage((i + 2) % 3, (i + 2) * 32);
        cp_commit();

        uint32_t abase = sA_u + (uint32_t)((i % 3) * STGA) * 4 + aoff0;
        uint32_t bbase = sB_u + (uint32_t)((i % 3) * STGB) * 4 + boff0;

        #pragma unroll
        for (int kk = 0; kk < 2; kk++) {
            uint32_t afr[4][4], bfr[4][4];
            #pragma unroll
            for (int mt = 0; mt < 4; mt++)
                ldsm4(afr[mt], abase + mt * 1280 + kk * 32);
            #pragma unroll
            for (int nt2 = 0; nt2 < 4; nt2++)
                ldsm4(bfr[nt2], bbase + nt2 * 1280 + kk * 32);
            #pragma unroll
            for (int mt = 0; mt < 4; mt++)
                #pragma unroll
                for (int nt2 = 0; nt2 < 4; nt2++) {
                    mma_f16(acc[mt][2 * nt2],     afr[mt], &bfr[nt2][0]);
                    mma_f16(acc[mt][2 * nt2 + 1], afr[mt], &bfr[nt2][2]);
                }
        }
    }

    size_t coff = (size_t)zb * sCb + (size_t)zh * sCh;
    #pragma unroll
    for (int mt = 0; mt < 4; mt++) {
        int r0 = row0 + wm0 + mt * 16 + g;
        #pragma unroll
        for (int nt = 0; nt < 8; nt++) {
            int c0c = col0 + wn0 + nt * 8 + 2 * t4;
            float b0 = bias ? bias[c0c] : 0.f;
            float b1 = bias ? bias[c0c + 1] : 0.f;
            float v00 = alpha * acc[mt][nt][0] + b0;
            float v01 = alpha * acc[mt][nt][1] + b1;
            float v10 = alpha * acc[mt][nt][2] + b0;
            float v11 = alpha * acc[mt][nt][3] + b1;
            if (OUTHALF) {
                __half* Ch = (__half*)Cv + coff;
                *(__half2*)&Ch[(size_t)r0 * ldc + c0c]       = __floats2half2_rn(v00, v01);
                *(__half2*)&Ch[(size_t)(r0 + 8) * ldc + c0c] = __floats2half2_rn(v10, v11);
            } else {
                float* Cf = (float*)Cv + coff;
                *(float2*)&Cf[(size_t)r0 * ldc + c0c]       = make_float2(v00, v01);
                *(float2*)&Cf[(size_t)(r0 + 8) * ldc + c0c] = make_float2(v10, v11);
            }
        }
    }
}

// =============================================================================
// flash_h: fused scores + online softmax + P@V.
// Grid (S/128, B*H). 256 threads = 8 warps, each warp owns 16 query rows.
// Loops over 32 key tiles of 64. Q/K rows 400B-padded, V rows 144B-padded
// (both ≡4 mod 32 words -> ldmatrix conflict-free).
// =============================================================================
#define QROW 400
#define VROW 144
#define SQ_BYTES (128 * QROW)       // 51200
#define SK_STG   (64 * QROW)        // 25600
#define SV_STG   (128 * VROW)       // 18432
#define FLASH_SMEM (SQ_BYTES + 3 * SK_STG + 3 * SV_STG)   // 183296

__global__ void __launch_bounds__(256) flash_h(
    const __half* __restrict__ q,      // [tok][H][192] (rope applied)
    const __half* __restrict__ kfull,  // [tok][H][192]
    const __half* __restrict__ vT,     // [(b*H+h)][128][2048]
    __half* __restrict__ oc)           // [tok][H*128]
{
    extern __shared__ char sm[];
    char* sQ = sm;
    char* sK = sm + SQ_BYTES;
    char* sV = sK + 3 * SK_STG;

    int qt = blockIdx.x;
    int bh = blockIdx.y;
    int b  = bh >> 4, h = bh & 15;
    int q0 = qt << 7;

    int tid = threadIdx.x, wid = tid >> 5, lane = tid & 31;
    int g = lane >> 2, t4 = lane & 3;
    int j = lane >> 3, r = lane & 7;

    const __half* qg = q     + (size_t)b * S_ * HQK + h * QK_;
    const __half* kg = kfull + (size_t)b * S_ * HQK + h * QK_;
    const __half* vg = vT    + (size_t)bh * VH_ * S_;

    // Q tile: 128 rows x 384B
    #pragma unroll
    for (int i = 0; i < 12; i++) {
        int idx = tid + 256 * i;
        int row = idx / 24, c = idx % 24;
        cp_async16(sQ + row * QROW + c * 16,
                   (const char*)(qg + (size_t)(q0 + row) * HQK) + c * 16);
    }
    auto load_kv = [&](int st, int kc0) {
        char* k_s = sK + st * SK_STG;
        char* v_s = sV + st * SV_STG;
        #pragma unroll
        for (int i = 0; i < 6; i++) {
            int idx = tid + 256 * i;
            int row = idx / 24, c = idx % 24;
            cp_async16(k_s + row * QROW + c * 16,
                       (const char*)(kg + (size_t)(kc0 + row) * HQK) + c * 16);
        }
        #pragma unroll
        for (int i = 0; i < 4; i++) {
            int idx = tid + 256 * i;
            int row = idx >> 3, c = idx & 7;
            cp_async16(v_s + row * VROW + c * 16,
                       (const char*)(vg + (size_t)row * S_ + kc0) + c * 16);
        }
    };

    load_kv(0, 0);
    cp_commit();          // group0: Q + KV stage0
    load_kv(1, 64);
    cp_commit();

    uint32_t sQ_u = (uint32_t)__cvta_generic_to_shared(sQ);
    uint32_t sK_u = (uint32_t)__cvta_generic_to_shared(sK);
    uint32_t sV_u = (uint32_t)__cvta_generic_to_shared(sV);
    uint32_t qoff = sQ_u + (uint32_t)(wid * 16 + (j & 1) * 8 + r) * QROW + (j >> 1) * 16;
    uint32_t koff = (uint32_t)((j >> 1) * 8 + r) * QROW + (j & 1) * 16;
    uint32_t voff = (uint32_t)((j >> 1) * 8 + r) * VROW + (j & 1) * 16;

    float oacc[16][4] = {};
    float m0 = -1e30f, m1 = -1e30f, l0 = 0.f, l1 = 0.f;
    const float K2 = SCALE * 1.4426950408889634f;   // fold softmax scale into exp2

    for (int it = 0; it < 32; it++) {
        cp_wait<1>();
        __syncthreads();
        if (it + 2 < 32) load_kv((it + 2) % 3, (it + 2) * 64);
        cp_commit();

        uint32_t kb = sK_u + (uint32_t)((it % 3) * SK_STG) + koff;
        uint32_t vb = sV_u + (uint32_t)((it % 3) * SV_STG) + voff;

        // ---- S = Q @ K^T  (16 x 64 per warp, K=192) ----
        float sacc[8][4] = {};
        #pragma unroll
        for (int kk = 0; kk < 12; kk++) {
            uint32_t aq[4];
            ldsm4(aq, qoff + kk * 32);
            #pragma unroll
            for (int n2 = 0; n2 < 4; n2++) {
                uint32_t bk[4];
                ldsm4(bk, kb + n2 * (16 * QROW) + kk * 32);
                mma_f16(sacc[2 * n2],     aq, &bk[0]);
                mma_f16(sacc[2 * n2 + 1], aq, &bk[2]);
            }
        }

        // ---- online softmax (rows g and g+8) ----
        float mx0 = -1e30f, mx1 = -1e30f;
        #pragma unroll
        for (int nt = 0; nt < 8; nt++) {
            mx0 = fmaxf(mx0, fmaxf(sacc[nt][0], sacc[nt][1]));
            mx1 = fmaxf(mx1, fmaxf(sacc[nt][2], sacc[nt][3]));
        }
        mx0 = fmaxf(mx0, __shfl_xor_sync(0xffffffffu, mx0, 1));
        mx0 = fmaxf(mx0, __shfl_xor_sync(0xffffffffu, mx0, 2));
        mx1 = fmaxf(mx1, __shfl_xor_sync(0xffffffffu, mx1, 1));
        mx1 = fmaxf(mx1, __shfl_xor_sync(0xffffffffu, mx1, 2));
        float mn0 = fmaxf(m0, mx0), mn1 = fmaxf(m1, mx1);
        float rs0 = exp2f((m0 - mn0) * K2), rs1 = exp2f((m1 - mn1) * K2);
        m0 = mn0; m1 = mn1;

        uint32_t p01[8], p23[8];
        float sum0 = 0.f, sum1 = 0.f;
        #pragma unroll
        for (int nt = 0; nt < 8; nt++) {
            float p0 = exp2f((sacc[nt][0] - mn0) * K2);
            float p1 = exp2f((sacc[nt][1] - mn0) * K2);
            float p2 = exp2f((sacc[nt][2] - mn1) * K2);
            float p3 = exp2f((sacc[nt][3] - mn1) * K2);
            sum0 += p0 + p1;
            sum1 += p2 + p3;
            __half2 hA = __floats2half2_rn(p0, p1);
            __half2 hB = __floats2half2_rn(p2, p3);
            p01[nt] = *(uint32_t*)&hA;
            p23[nt] = *(uint32_t*)&hB;
        }
        sum0 += __shfl_xor_sync(0xffffffffu, sum0, 1);
        sum0 += __shfl_xor_sync(0xffffffffu, sum0, 2);
        sum1 += __shfl_xor_sync(0xffffffffu, sum1, 1);
        sum1 += __shfl_xor_sync(0xffffffffu, sum1, 2);
        l0 = l0 * rs0 + sum0;
        l1 = l1 * rs1 + sum1;

        #pragma unroll
        for (int nt = 0; nt < 16; nt++) {
            oacc[nt][0] *= rs0; oacc[nt][1] *= rs0;
            oacc[nt][2] *= rs1; oacc[nt][3] *= rs1;
        }

        // ---- O += P @ V  (K=64, N=128) ----
        #pragma unroll
        for (int kk = 0; kk < 4; kk++) {
            uint32_t pa[4] = {p01[2 * kk], p23[2 * kk], p01[2 * kk + 1], p23[2 * kk + 1]};
            #pragma unroll
            for (int n2 = 0; n2 < 8; n2++) {
                uint32_t bv[4];
                ldsm4(bv, vb + n2 * (16 * VROW) + kk * 32);
                mma_f16(oacc[2 * n2],     pa, &bv[0]);
                mma_f16(oacc[2 * n2 + 1], pa, &bv[2]);
            }
        }
    }

    // ---- normalize and store ----
    float il0 = 1.f / l0, il1 = 1.f / l1;
    int row = q0 + wid * 16 + g;
    size_t tok0 = (size_t)b * S_ + row;
    __half* o0 = oc + tok0 * (H_ * VH_) + h * VH_;
    __half* o1 = o0 + (size_t)8 * (H_ * VH_);
    #pragma unroll
    for (int nt = 0; nt < 16; nt++) {
        int c = nt * 8 + 2 * t4;
        *(__half2*)&o0[c] = __floats2half2_rn(oacc[nt][0] * il0, oacc[nt][1] * il0);
        *(__half2*)&o1[c] = __floats2half2_rn(oacc[nt][2] * il1, oacc[nt][3] * il1);
    }
}

// ---------------- prepass kernels --------------------------------------------
__global__ void f2h_k(const float* __restrict__ in, __half* __restrict__ out)
{
    size_t i = ((size_t)blockIdx.x * 256 + threadIdx.x) * 4;
    float4 v = *(const float4*)(in + i);
    __half2* o = (__half2*)(out + i);
    o[0] = __floats2half2_rn(v.x, v.y);
    o[1] = __floats2half2_rn(v.z, v.w);
}

__global__ void wkva_pad_k(const float* __restrict__ in, __half* __restrict__ out)
{
    size_t i = ((size_t)blockIdx.x * 256 + threadIdx.x) * 4;
    if (i < (size_t)(KVL + ROPE_) * D_) {
        float4 v = *(const float4*)(in + i);
        __half2* o = (__half2*)(out + i);
        o[0] = __floats2half2_rn(v.x, v.y);
        o[1] = __floats2half2_rn(v.z, v.w);
    } else {
        __half2* o = (__half2*)(out + i);
        o[0] = __half2{__half(0.f), __half(0.f)};
        o[1] = __half2{__half(0.f), __half(0.f)};
    }
}

__global__ void biaskva_pad_k(const float* __restrict__ in, float* __restrict__ out)
{
    int i = blockIdx.x * 256 + threadIdx.x;
    if (i < KVP) out[i] = (i < KVL + ROPE_) ? in[i] : 0.f;
}

// ---------------- elementwise kernels -----------------------------------------
__global__ void rmsnorm_h(const __half* __restrict__ in, __half* __restrict__ out,
                          const float* __restrict__ w, int width,
                          int inStride, int outStride)
{
    int row = blockIdx.x;
    const __half* ip = in  + (size_t)row * inStride;
    __half*       op = out + (size_t)row * outStride;
    float ss = 0.f;
    for (int i = threadIdx.x; i < width; i += 256) {
        float v = __half2float(ip[i]);
        ss += v * v;
    }
    __shared__ float sm[256];
    sm[threadIdx.x] = ss;
    __syncthreads();
    for (int s = 128; s > 0; s >>= 1) {
        if (threadIdx.x < s) sm[threadIdx.x] += sm[threadIdx.x + s];
        __syncthreads();
    }
    float r = rsqrtf(sm[0] / (float)width + 1e-3f);
    for (int i = threadIdx.x; i < width; i += 256)
        op[i] = __float2half(w[i] * __half2float(ip[i]) * r);
}

__global__ void rope_q_h(__half* __restrict__ q,
                         const float* __restrict__ c, const float* __restrict__ s)
{
    int tok = blockIdx.x;
    int h = threadIdx.x >> 5;
    int j = threadIdx.x & 31;
    int pos = tok % S_;
    __half* p = q + (size_t)tok * HQK + h * QK_ + NOPE_;
    float xr = __half2float(p[2 * j]), xi = __half2float(p[2 * j + 1]);
    float cc = c[pos * 32 + j], sn = s[pos * 32 + j];
    p[2 * j]     = __float2half(xr * cc - xi * sn);
    p[2 * j + 1] = __float2half(xr * sn + xi * cc);
}

__global__ void rope_k_bcast_h(const __half* __restrict__ kvf, __half* __restrict__ kfull,
                               const float* __restrict__ c, const float* __restrict__ s)
{
    int tok = blockIdx.x;
    int j = threadIdx.x;   // 0..31
    int pos = tok % S_;
    const __half* src = kvf + (size_t)tok * KVP + KVL;
    float xr = __half2float(src[2 * j]), xi = __half2float(src[2 * j + 1]);
    float cc = c[pos * 32 + j], sn = s[pos * 32 + j];
    __half2 v;
    v.x = __float2half(xr * cc - xi * sn);
    v.y = __float2half(xr * sn + xi * cc);
    __half* dst = kfull + (size_t)tok * HQK + NOPE_;
    #pragma unroll
    for (int h = 0; h < H_; h++)
        *(__half2*)&dst[h * QK_ + 2 * j] = v;
}

// ---------------- host glue --------------------------------------------------
template<int TN, bool OUTHALF>
static void launch_h(int M, int N, int K,
                     const __half* A, int lda, long long sAb, long long sAh,
                     const __half* Bp, int ldb, long long sBb, long long sBh,
                     void* C, int ldc, long long sCb, long long sCh,
                     int nb, int nh, float alpha, const float* bias)
{
    constexpr int SMEM = (3 * 128 * 20 + 3 * TN * 20) * 4;
    cudaFuncSetAttribute(gemm_h<TN, OUTHALF>,
                         cudaFuncAttributeMaxDynamicSharedMemorySize, SMEM);
    dim3 grid(N / TN, M / 128, nb * nh);
    gemm_h<TN, OUTHALF><<<grid, TN == 256 ? 256 : 128, SMEM>>>(
        K, A, lda, sAb, sAh, Bp, ldb, sBb, sBh, C, ldc, sCb, sCh, nh, alpha, bias);
}

static void f2h(const float* in, __half* out, size_t n)
{
    f2h_k<<<(unsigned)(n / 1024), 256>>>(in, out);
}

extern "C" void kernel_launch(void* const* d_in, const int* in_sizes, int n_in,
                              void* d_out, int out_size)
{
    const float* x        = (const float*)d_in[0];
    const float* cosp     = (const float*)d_in[2];
    const float* sinp     = (const float*)d_in[3];
    const float* wq_a_w   = (const float*)d_in[4];
    const float* wq_a_b   = (const float*)d_in[5];
    const float* q_norm_w = (const float*)d_in[6];
    const float* wq_b_w   = (const float*)d_in[7];
    const float* wq_b_b   = (const float*)d_in[8];
    const float* wkv_a_w  = (const float*)d_in[9];
    const float* kv_norm_w= (const float*)d_in[11];
    const float* wkv_b_w  = (const float*)d_in[12];
    const float* wo_w     = (const float*)d_in[13];
    const float* wo_b     = (const float*)d_in[14];
    float* out = (float*)d_out;

    __half *xh, *qa, *q, *kvf, *kf, *kfull, *vT, *oc;
    __half *wqa, *wqb, *wkva, *wkvb, *wo;
    float *bkva;
    cudaGetSymbolAddress((void**)&xh,   h_x);
    cudaGetSymbolAddress((void**)&qa,   h_qa);
    cudaGetSymbolAddress((void**)&q,    h_q);
    cudaGetSymbolAddress((void**)&kvf,  h_kvf);
    cudaGetSymbolAddress((void**)&kf,   h_kf);
    cudaGetSymbolAddress((void**)&kfull,h_kfull);
    cudaGetSymbolAddress((void**)&vT,   h_vT);
    cudaGetSymbolAddress((void**)&oc,   h_oc);
    cudaGetSymbolAddress((void**)&wqa,  h_wqa);
    cudaGetSymbolAddress((void**)&wqb,  h_wqb);
    cudaGetSymbolAddress((void**)&wkva, h_wkva);
    cudaGetSymbolAddress((void**)&wkvb, h_wkvb);
    cudaGetSymbolAddress((void**)&wo,   h_wo);
    cudaGetSymbolAddress((void**)&bkva, g_biaskva);

    // 0,1) convert x, wq_a
    f2h(x,      xh,  (size_t)NT * D_);
    f2h(wq_a_w, wqa, (size_t)QL * D_);
    // 2) q_a = x @ wq_a^T + b           [4096,1024] K=2048
    launch_h<256, true>(NT, QL, D_, xh, D_, 0, 0, wqa, D_, 0, 0,
                        qa, QL, 0, 0, 1, 1, 1.f, wq_a_b);
    // 3) rmsnorm(q_a) in place
    rmsnorm_h<<<NT, 256>>>(qa, qa, q_norm_w, QL, QL, QL);
    // 4) convert wq_b
    f2h(wq_b_w, wqb, (size_t)HQK * QL);
    // 5) q = q_a_n @ wq_b^T + b         [4096,3072] K=1024
    launch_h<256, true>(NT, HQK, QL, qa, QL, 0, 0, wqb, QL, 0, 0,
                        q, HQK, 0, 0, 1, 1, 1.f, wq_b_b);
    // 6,7) wkva pad + bias pad
    wkva_pad_k<<<(unsigned)((size_t)KVP * D_ / 1024), 256>>>(wkv_a_w, wkva);
    biaskva_pad_k<<<3, 256>>>((const float*)d_in[10], bkva);
    // 8) kv_full = x @ wkva_pad^T + b   [4096,640] K=2048
    launch_h<128, true>(NT, KVP, D_, xh, D_, 0, 0, wkva, D_, 0, 0,
                        kvf, KVP, 0, 0, 1, 1, 1.f, bkva);
    // 9) convert wkv_b
    f2h(wkv_b_w, wkvb, (size_t)H_ * 256 * KVL);
    // 10) kv_c = rmsnorm(kv_full[:, :512]) -> kf
    rmsnorm_h<<<NT, 256>>>(kvf, kf, kv_norm_w, KVL, KVP, KVL);
    // 11) kfull[:, h, 128:192] = rope(k_pe) broadcast
    rope_k_bcast_h<<<NT, 32>>>(kvf, kfull, cosp, sinp);
    // 12) q[:, h, 128:192] = rope(q_pe) in place
    rope_q_h<<<NT, 512>>>(q, cosp, sinp);
    // 13) kfull[:, h, :128] = kv_c @ wkvb_nope[h]^T   [4096,128] K=512 x16
    launch_h<128, true>(NT, NOPE_, KVL,
                        kf, KVL, 0, 0,
                        wkvb, KVL, 0, (long long)256 * KVL,
                        kfull, HQK, 0, QK_,
                        1, H_, 1.f, nullptr);
    // 14) vT[b,h] = wkvb_v[h] @ kv_c[b]^T   [128,2048] K=512 x32
    launch_h<256, true>(VH_, S_, KVL,
                        wkvb + (size_t)NOPE_ * KVL, KVL, 0, (long long)256 * KVL,
                        kf, KVL, (long long)S_ * KVL, 0,
                        vT, S_, (long long)H_ * VH_ * S_, (long long)VH_ * S_,
                        B_, H_, 1.f, nullptr);
    // 15) fused attention: oc = softmax(SCALE * q @ kfull^T) @ V
    {
        cudaFuncSetAttribute(flash_h, cudaFuncAttributeMaxDynamicSharedMemorySize,
                             FLASH_SMEM);
        dim3 grid(S_ / 128, B_ * H_);
        flash_h<<<grid, 256, FLASH_SMEM>>>(q, kfull, vT, oc);
    }
    // 16) convert wo
    f2h(wo_w, wo, (size_t)D_ * H_ * VH_);
    // 17) out = oc @ wo^T + b           [4096,2048] K=2048 -> fp32
    launch_h<256, false>(NT, D_, H_ * VH_, oc, H_ * VH_, 0, 0, wo, D_, 0, 0,
                         out, D_, 0, 0, 1, 1, 1.f, wo_b);
}

// round 12
// speedup vs baseline: 2.3074x; 1.0769x over previous
#include <cuda_runtime.h>
#include <cuda_fp16.h>
#include <math.h>
#include <stdint.h>

#define B_    2
#define S_    2048
#define D_    2048
#define H_    16
#define NT    4096          // B_*S_
#define QL    1024
#define KVL   512
#define NOPE_ 128
#define ROPE_ 64
#define VH_   128
#define QK_   192
#define KVP   640           // padded kv_full width
#define NCAT  1664          // QL + KVP
#define HQK   3072          // H_*QK_
#define SCALE 0.07216878364870322f   // 192^-0.5

// ---------------- scratch (static device globals; no runtime alloc) -------
__device__ __align__(256) __half h_x   [(size_t)NT * D_];
__device__ __align__(256) __half h_qakv[(size_t)NT * NCAT];    // [q_a(1024) | kv_full(640)]
__device__ __align__(256) __half h_qa  [(size_t)NT * QL];
__device__ __align__(256) __half h_q   [(size_t)NT * HQK];     // [tok][h][192], rope in place
__device__ __align__(256) __half h_kf  [(size_t)NT * KVL];     // kv_c
__device__ __align__(256) __half h_kfull[(size_t)NT * HQK];    // [tok][h][192] = [k_nope|k_pe]
__device__ __align__(256) __half h_vT  [(size_t)B_ * H_ * VH_ * S_]; // [b][h][128][2048]
__device__ __align__(256) __half h_oc  [(size_t)NT * H_ * VH_];
__device__ __align__(256) __half h_wcat[(size_t)NCAT * D_];    // [wq_a | wkv_a_pad]
__device__ __align__(256) __half h_wqb [(size_t)HQK * QL];
__device__ __align__(256) __half h_wkvb[(size_t)H_ * 256 * KVL];
__device__ __align__(256) __half h_wo  [(size_t)D_ * H_ * VH_];
__device__ float g_biascat[NCAT];

// ---------------- helpers ---------------------------------------------------
__device__ __forceinline__ void mma_f16(float* c, const uint32_t* a, const uint32_t* b) {
    asm volatile(
        "mma.sync.aligned.m16n8k16.row.col.f32.f16.f16.f32 "
        "{%0,%1,%2,%3},{%4,%5,%6,%7},{%8,%9},{%0,%1,%2,%3};"
        : "+f"(c[0]), "+f"(c[1]), "+f"(c[2]), "+f"(c[3])
        : "r"(a[0]), "r"(a[1]), "r"(a[2]), "r"(a[3]), "r"(b[0]), "r"(b[1]));
}

__device__ __forceinline__ void ldsm4(uint32_t* r, uint32_t saddr) {
    asm volatile(
        "ldmatrix.sync.aligned.m8n8.x4.shared.b16 {%0,%1,%2,%3}, [%4];"
        : "=r"(r[0]), "=r"(r[1]), "=r"(r[2]), "=r"(r[3]) : "r"(saddr));
}

__device__ __forceinline__ void cp_async16(void* smem, const void* gmem) {
    uint32_t s = (uint32_t)__cvta_generic_to_shared(smem);
    asm volatile("cp.async.cg.shared.global [%0], [%1], 16;" :: "r"(s), "l"(gmem));
}
__device__ __forceinline__ void cp_commit() {
    asm volatile("cp.async.commit_group;");
}
template<int N>
__device__ __forceinline__ void cp_wait() {
    asm volatile("cp.async.wait_group %0;" :: "n"(N));
}

// =============================================================================
// gemm_h: fp16 in / fp32 acc. CTA tile 128 x TN (TN = 128 or 256),
// warp tile 64x64, BK=32, 3-stage cp.async, ldmatrix fragments.
// C[z] = alpha * A[z] @ B[z]^T + bias.  A [M,K], B [N,K], both half row-major.
// =============================================================================
template<int TN, bool OUTHALF>
__global__ void __launch_bounds__(TN == 256 ? 256 : 128) gemm_h(
    int K,
    const __half* __restrict__ A, int lda, long long sAb, long long sAh,
    const __half* __restrict__ Bp, int ldb, long long sBb, long long sBh,
    void* __restrict__ Cv, int ldc, long long sCb, long long sCh,
    int ZH, float alpha, const float* __restrict__ bias)
{
    constexpr int T = (TN == 256) ? 256 : 128;
    constexpr int WCOLS = TN / 64;
    constexpr int ASTR = 20;                     // u32 per row (80 B)
    constexpr int STGA = 128 * ASTR;
    constexpr int STGB = TN * ASTR;
    constexpr int AITER = 512 / T;
    constexpr int BITER = (TN * 4) / T;

    extern __shared__ uint32_t smu[];
    uint32_t* sA = smu;
    uint32_t* sB = smu + 3 * STGA;

    int z  = blockIdx.z;
    int zb = z / ZH;
    int zh = z - zb * ZH;
    const __half* Ab = A  + zb * sAb + zh * sAh;
    const __half* Bb = Bp + zb * sBb + zh * sBh;

    int row0 = blockIdx.y << 7;
    int col0 = blockIdx.x * TN;
    int tid  = threadIdx.x;
    int wid  = tid >> 5;
    int lane = tid & 31;
    int wm0 = (wid / WCOLS) << 6;
    int wn0 = (wid % WCOLS) << 6;
    int g = lane >> 2, t4 = lane & 3;
    int j = lane >> 3, r = lane & 7;

    uint32_t sA_u = (uint32_t)__cvta_generic_to_shared(sA);
    uint32_t sB_u = (uint32_t)__cvta_generic_to_shared(sB);
    uint32_t aoff0 = (uint32_t)(wm0 + (j & 1) * 8 + r) * 80 + (uint32_t)(j >> 1) * 16;
    uint32_t boff0 = (uint32_t)(wn0 + (j >> 1) * 8 + r) * 80 + (uint32_t)(j & 1) * 16;

    float acc[4][8][4] = {};

    auto load_stage = [&](int st, int k0) {
        uint32_t* a_s = sA + st * STGA;
        uint32_t* b_s = sB + st * STGB;
        #pragma unroll
        for (int i = 0; i < AITER; i++) {
            int idx = tid + T * i;
            int rr = idx >> 2, q = idx & 3;
            cp_async16(a_s + rr * ASTR + q * 4,
                       Ab + (size_t)(row0 + rr) * lda + k0 + q * 8);
        }
        #pragma unroll
        for (int i = 0; i < BITER; i++) {
            int idx = tid + T * i;
            int rr = idx >> 2, q = idx & 3;
            cp_async16(b_s + rr * ASTR + q * 4,
                       Bb + (size_t)(col0 + rr) * ldb + k0 + q * 8);
        }
    };

    int nk = K / 32;
    load_stage(0, 0);
    cp_commit();
    load_stage(1, 32);
    cp_commit();

    for (int i = 0; i < nk; i++) {
        cp_wait<1>();
        __syncthreads();
        if (i + 2 < nk) load_stage((i + 2) % 3, (i + 2) * 32);
        cp_commit();

        uint32_t abase = sA_u + (uint32_t)((i % 3) * STGA) * 4 + aoff0;
        uint32_t bbase = sB_u + (uint32_t)((i % 3) * STGB) * 4 + boff0;

        #pragma unroll
        for (int kk = 0; kk < 2; kk++) {
            uint32_t afr[4][4], bfr[4][4];
            #pragma unroll
            for (int mt = 0; mt < 4; mt++)
                ldsm4(afr[mt], abase + mt * 1280 + kk * 32);
            #pragma unroll
            for (int nt2 = 0; nt2 < 4; nt2++)
                ldsm4(bfr[nt2], bbase + nt2 * 1280 + kk * 32);
            #pragma unroll
            for (int mt = 0; mt < 4; mt++)
                #pragma unroll
                for (int nt2 = 0; nt2 < 4; nt2++) {
                    mma_f16(acc[mt][2 * nt2],     afr[mt], &bfr[nt2][0]);
                    mma_f16(acc[mt][2 * nt2 + 1], afr[mt], &bfr[nt2][2]);
                }
        }
    }

    size_t coff = (size_t)zb * sCb + (size_t)zh * sCh;
    #pragma unroll
    for (int mt = 0; mt < 4; mt++) {
        int r0 = row0 + wm0 + mt * 16 + g;
        #pragma unroll
        for (int nt = 0; nt < 8; nt++) {
            int c0c = col0 + wn0 + nt * 8 + 2 * t4;
            float b0 = bias ? bias[c0c] : 0.f;
            float b1 = bias ? bias[c0c + 1] : 0.f;
            float v00 = alpha * acc[mt][nt][0] + b0;
            float v01 = alpha * acc[mt][nt][1] + b1;
            float v10 = alpha * acc[mt][nt][2] + b0;
            float v11 = alpha * acc[mt][nt][3] + b1;
            if (OUTHALF) {
                __half* Ch = (__half*)Cv + coff;
                *(__half2*)&Ch[(size_t)r0 * ldc + c0c]       = __floats2half2_rn(v00, v01);
                *(__half2*)&Ch[(size_t)(r0 + 8) * ldc + c0c] = __floats2half2_rn(v10, v11);
            } else {
                float* Cf = (float*)Cv + coff;
                *(float2*)&Cf[(size_t)r0 * ldc + c0c]       = make_float2(v00, v01);
                *(float2*)&Cf[(size_t)(r0 + 8) * ldc + c0c] = make_float2(v10, v11);
            }
        }
    }
}

// =============================================================================
// flash_h: fused scores + online softmax + P@V. Q fragments register-resident.
// Grid (S/128, B*H). 256 threads = 8 warps, each warp owns 16 query rows.
// =============================================================================
#define QROW 400
#define VROW 144
#define SQ_BYTES (128 * QROW)       // 51200
#define SK_STG   (64 * QROW)        // 25600
#define SV_STG   (128 * VROW)       // 18432
#define FLASH_SMEM (SQ_BYTES + 3 * SK_STG + 3 * SV_STG)   // 183296

__global__ void __launch_bounds__(256) flash_h(
    const __half* __restrict__ q,      // [tok][H][192] (rope applied)
    const __half* __restrict__ kfull,  // [tok][H][192]
    const __half* __restrict__ vT,     // [(b*H+h)][128][2048]
    __half* __restrict__ oc)           // [tok][H*128]
{
    extern __shared__ char sm[];
    char* sQ = sm;
    char* sK = sm + SQ_BYTES;
    char* sV = sK + 3 * SK_STG;

    int qt = blockIdx.x;
    int bh = blockIdx.y;
    int b  = bh >> 4, h = bh & 15;
    int q0 = qt << 7;

    int tid = threadIdx.x, wid = tid >> 5, lane = tid & 31;
    int g = lane >> 2, t4 = lane & 3;
    int j = lane >> 3, r = lane & 7;

    const __half* qg = q     + (size_t)b * S_ * HQK + h * QK_;
    const __half* kg = kfull + (size_t)b * S_ * HQK + h * QK_;
    const __half* vg = vT    + (size_t)bh * VH_ * S_;

    // Q tile: 128 rows x 384B
    #pragma unroll
    for (int i = 0; i < 12; i++) {
        int idx = tid + 256 * i;
        int row = idx / 24, c = idx % 24;
        cp_async16(sQ + row * QROW + c * 16,
                   (const char*)(qg + (size_t)(q0 + row) * HQK) + c * 16);
    }
    auto load_kv = [&](int st, int kc0) {
        char* k_s = sK + st * SK_STG;
        char* v_s = sV + st * SV_STG;
        #pragma unroll
        for (int i = 0; i < 6; i++) {
            int idx = tid + 256 * i;
            int row = idx / 24, c = idx % 24;
            cp_async16(k_s + row * QROW + c * 16,
                       (const char*)(kg + (size_t)(kc0 + row) * HQK) + c * 16);
        }
        #pragma unroll
        for (int i = 0; i < 4; i++) {
            int idx = tid + 256 * i;
            int row = idx >> 3, c = idx & 7;
            cp_async16(v_s + row * VROW + c * 16,
                       (const char*)(vg + (size_t)row * S_ + kc0) + c * 16);
        }
    };

    load_kv(0, 0);
    cp_commit();          // group0: Q + KV stage0
    load_kv(1, 64);
    cp_commit();

    uint32_t sQ_u = (uint32_t)__cvta_generic_to_shared(sQ);
    uint32_t sK_u = (uint32_t)__cvta_generic_to_shared(sK);
    uint32_t sV_u = (uint32_t)__cvta_generic_to_shared(sV);
    uint32_t qoff = sQ_u + (uint32_t)(wid * 16 + (j & 1) * 8 + r) * QROW + (j >> 1) * 16;
    uint32_t koff = (uint32_t)((j >> 1) * 8 + r) * QROW + (j & 1) * 16;
    uint32_t voff = (uint32_t)((j >> 1) * 8 + r) * VROW + (j & 1) * 16;

    // wait for group0 (Q + KV0); hoist Q fragments into registers
    cp_wait<1>();
    __syncthreads();
    uint32_t qfr[12][4];
    #pragma unroll
    for (int kk = 0; kk < 12; kk++)
        ldsm4(qfr[kk], qoff + kk * 32);

    float oacc[16][4] = {};
    float m0 = -1e30f, m1 = -1e30f, l0 = 0.f, l1 = 0.f;
    const float K2 = SCALE * 1.4426950408889634f;

    for (int it = 0; it < 32; it++) {
        if (it > 0) {
            cp_wait<1>();
            __syncthreads();
        }
        if (it + 2 < 32) load_kv((it + 2) % 3, (it + 2) * 64);
        cp_commit();

        uint32_t kb = sK_u + (uint32_t)((it % 3) * SK_STG) + koff;
        uint32_t vb = sV_u + (uint32_t)((it % 3) * SV_STG) + voff;

        // ---- S = Q @ K^T  (16 x 64 per warp, K=192) ----
        float sacc[8][4] = {};
        #pragma unroll
        for (int kk = 0; kk < 12; kk++) {
            #pragma unroll
            for (int n2 = 0; n2 < 4; n2++) {
                uint32_t bk[4];
                ldsm4(bk, kb + n2 * (16 * QROW) + kk * 32);
                mma_f16(sacc[2 * n2],     qfr[kk], &bk[0]);
                mma_f16(sacc[2 * n2 + 1], qfr[kk], &bk[2]);
            }
        }

        // ---- online softmax (rows g and g+8) ----
        float mx0 = -1e30f, mx1 = -1e30f;
        #pragma unroll
        for (int nt = 0; nt < 8; nt++) {
            mx0 = fmaxf(mx0, fmaxf(sacc[nt][0], sacc[nt][1]));
            mx1 = fmaxf(mx1, fmaxf(sacc[nt][2], sacc[nt][3]));
        }
        mx0 = fmaxf(mx0, __shfl_xor_sync(0xffffffffu, mx0, 1));
        mx0 = fmaxf(mx0, __shfl_xor_sync(0xffffffffu, mx0, 2));
        mx1 = fmaxf(mx1, __shfl_xor_sync(0xffffffffu, mx1, 1));
        mx1 = fmaxf(mx1, __shfl_xor_sync(0xffffffffu, mx1, 2));
        float mn0 = fmaxf(m0, mx0), mn1 = fmaxf(m1, mx1);
        float rs0 = exp2f((m0 - mn0) * K2), rs1 = exp2f((m1 - mn1) * K2);
        m0 = mn0; m1 = mn1;

        uint32_t p01[8], p23[8];
        float sum0 = 0.f, sum1 = 0.f;
        #pragma unroll
        for (int nt = 0; nt < 8; nt++) {
            float p0 = exp2f((sacc[nt][0] - mn0) * K2);
            float p1 = exp2f((sacc[nt][1] - mn0) * K2);
            float p2 = exp2f((sacc[nt][2] - mn1) * K2);
            float p3 = exp2f((sacc[nt][3] - mn1) * K2);
            sum0 += p0 + p1;
            sum1 += p2 + p3;
            __half2 hA = __floats2half2_rn(p0, p1);
            __half2 hB = __floats2half2_rn(p2, p3);
            p01[nt] = *(uint32_t*)&hA;
            p23[nt] = *(uint32_t*)&hB;
        }
        sum0 += __shfl_xor_sync(0xffffffffu, sum0, 1);
        sum0 += __shfl_xor_sync(0xffffffffu, sum0, 2);
        sum1 += __shfl_xor_sync(0xffffffffu, sum1, 1);
        sum1 += __shfl_xor_sync(0xffffffffu, sum1, 2);
        l0 = l0 * rs0 + sum0;
        l1 = l1 * rs1 + sum1;

        #pragma unroll
        for (int nt = 0; nt < 16; nt++) {
            oacc[nt][0] *= rs0; oacc[nt][1] *= rs0;
            oacc[nt][2] *= rs1; oacc[nt][3] *= rs1;
        }

        // ---- O += P @ V  (K=64, N=128) ----
        #pragma unroll
        for (int kk = 0; kk < 4; kk++) {
            uint32_t pa[4] = {p01[2 * kk], p23[2 * kk], p01[2 * kk + 1], p23[2 * kk + 1]};
            #pragma unroll
            for (int n2 = 0; n2 < 8; n2++) {
                uint32_t bv[4];
                ldsm4(bv, vb + n2 * (16 * VROW) + kk * 32);
                mma_f16(oacc[2 * n2],     pa, &bv[0]);
                mma_f16(oacc[2 * n2 + 1], pa, &bv[2]);
            }
        }
    }

    // ---- normalize and store ----
    float il0 = 1.f / l0, il1 = 1.f / l1;
    int row = q0 + wid * 16 + g;
    size_t tok0 = (size_t)b * S_ + row;
    __half* o0 = oc + tok0 * (H_ * VH_) + h * VH_;
    __half* o1 = o0 + (size_t)8 * (H_ * VH_);
    #pragma unroll
    for (int nt = 0; nt < 16; nt++) {
        int c = nt * 8 + 2 * t4;
        *(__half2*)&o0[c] = __floats2half2_rn(oacc[nt][0] * il0, oacc[nt][1] * il0);
        *(__half2*)&o1[c] = __floats2half2_rn(oacc[nt][2] * il1, oacc[nt][3] * il1);
    }
}

// ---------------- prepass kernels --------------------------------------------
__global__ void f2h_k(const float* __restrict__ in, __half* __restrict__ out)
{
    size_t i = ((size_t)blockIdx.x * 256 + threadIdx.x) * 4;
    float4 v = *(const float4*)(in + i);
    __half2* o = (__half2*)(out + i);
    o[0] = __floats2half2_rn(v.x, v.y);
    o[1] = __floats2half2_rn(v.z, v.w);
}

// wkv_a padded to [640][2048] appended at out (rows >=576 zero)
__global__ void wkva_pad_k(const float* __restrict__ in, __half* __restrict__ out)
{
    size_t i = ((size_t)blockIdx.x * 256 + threadIdx.x) * 4;
    if (i < (size_t)(KVL + ROPE_) * D_) {
        float4 v = *(const float4*)(in + i);
        __half2* o = (__half2*)(out + i);
        o[0] = __floats2half2_rn(v.x, v.y);
        o[1] = __floats2half2_rn(v.z, v.w);
    } else {
        __half2* o = (__half2*)(out + i);
        o[0] = __half2{__half(0.f), __half(0.f)};
        o[1] = __half2{__half(0.f), __half(0.f)};
    }
}

__global__ void biascat_k(const float* __restrict__ qb, const float* __restrict__ kb,
                          float* __restrict__ out)
{
    int i = blockIdx.x * 256 + threadIdx.x;
    if (i >= NCAT) return;
    if (i < QL) out[i] = qb[i];
    else if (i < QL + KVL + ROPE_) out[i] = kb[i - QL];
    else out[i] = 0.f;
}

// ---------------- elementwise kernels -----------------------------------------
__global__ void rmsnorm_h(const __half* __restrict__ in, __half* __restrict__ out,
                          const float* __restrict__ w, int width,
                          int inStride, int outStride)
{
    int row = blockIdx.x;
    const __half* ip = in  + (size_t)row * inStride;
    __half*       op = out + (size_t)row * outStride;
    float ss = 0.f;
    for (int i = threadIdx.x; i < width; i += 256) {
        float v = __half2float(ip[i]);
        ss += v * v;
    }
    __shared__ float sm[256];
    sm[threadIdx.x] = ss;
    __syncthreads();
    for (int s = 128; s > 0; s >>= 1) {
        if (threadIdx.x < s) sm[threadIdx.x] += sm[threadIdx.x + s];
        __syncthreads();
    }
    float r = rsqrtf(sm[0] / (float)width + 1e-3f);
    for (int i = threadIdx.x; i < width; i += 256)
        op[i] = __float2half(w[i] * __half2float(ip[i]) * r);
}

__global__ void rope_q_h(__half* __restrict__ q,
                         const float* __restrict__ c, const float* __restrict__ s)
{
    int tok = blockIdx.x;
    int h = threadIdx.x >> 5;
    int j = threadIdx.x & 31;
    int pos = tok % S_;
    __half* p = q + (size_t)tok * HQK + h * QK_ + NOPE_;
    float xr = __half2float(p[2 * j]), xi = __half2float(p[2 * j + 1]);
    float cc = c[pos * 32 + j], sn = s[pos * 32 + j];
    p[2 * j]     = __float2half(xr * cc - xi * sn);
    p[2 * j + 1] = __float2half(xr * sn + xi * cc);
}

// rope k_pe (read from qakv at offset 1536, stride NCAT) broadcast to all heads
__global__ void rope_k_bcast_h(const __half* __restrict__ qakv, __half* __restrict__ kfull,
                               const float* __restrict__ c, const float* __restrict__ s)
{
    int tok = blockIdx.x;
    int j = threadIdx.x;   // 0..31
    int pos = tok % S_;
    const __half* src = qakv + (size_t)tok * NCAT + QL + KVL;
    float xr = __half2float(src[2 * j]), xi = __half2float(src[2 * j + 1]);
    float cc = c[pos * 32 + j], sn = s[pos * 32 + j];
    __half2 v;
    v.x = __float2half(xr * cc - xi * sn);
    v.y = __float2half(xr * sn + xi * cc);
    __half* dst = kfull + (size_t)tok * HQK + NOPE_;
    #pragma unroll
    for (int h = 0; h < H_; h++)
        *(__half2*)&dst[h * QK_ + 2 * j] = v;
}

// ---------------- host glue --------------------------------------------------
template<int TN, bool OUTHALF>
static void launch_h(int M, int N, int K,
                     const __half* A, int lda, long long sAb, long long sAh,
                     const __half* Bp, int ldb, long long sBb, long long sBh,
                     void* C, int ldc, long long sCb, long long sCh,
                     int nb, int nh, float alpha, const float* bias)
{
    constexpr int SMEM = (3 * 128 * 20 + 3 * TN * 20) * 4;
    cudaFuncSetAttribute(gemm_h<TN, OUTHALF>,
                         cudaFuncAttributeMaxDynamicSharedMemorySize, SMEM);
    dim3 grid(N / TN, M / 128, nb * nh);
    gemm_h<TN, OUTHALF><<<grid, TN == 256 ? 256 : 128, SMEM>>>(
        K, A, lda, sAb, sAh, Bp, ldb, sBb, sBh, C, ldc, sCb, sCh, nh, alpha, bias);
}

static void f2h(const float* in, __half* out, size_t n)
{
    f2h_k<<<(unsigned)(n / 1024), 256>>>(in, out);
}

extern "C" void kernel_launch(void* const* d_in, const int* in_sizes, int n_in,
                              void* d_out, int out_size)
{
    const float* x        = (const float*)d_in[0];
    const float* cosp     = (const float*)d_in[2];
    const float* sinp     = (const float*)d_in[3];
    const float* wq_a_w   = (const float*)d_in[4];
    const float* wq_a_b   = (const float*)d_in[5];
    const float* q_norm_w = (const float*)d_in[6];
    const float* wq_b_w   = (const float*)d_in[7];
    const float* wq_b_b   = (const float*)d_in[8];
    const float* wkv_a_w  = (const float*)d_in[9];
    const float* wkv_a_b  = (const float*)d_in[10];
    const float* kv_norm_w= (const float*)d_in[11];
    const float* wkv_b_w  = (const float*)d_in[12];
    const float* wo_w     = (const float*)d_in[13];
    const float* wo_b     = (const float*)d_in[14];
    float* out = (float*)d_out;

    __half *xh, *qakv, *qa, *q, *kf, *kfull, *vT, *oc;
    __half *wcat, *wqb, *wkvb, *wo;
    float *bcat;
    cudaGetSymbolAddress((void**)&xh,   h_x);
    cudaGetSymbolAddress((void**)&qakv, h_qakv);
    cudaGetSymbolAddress((void**)&qa,   h_qa);
    cudaGetSymbolAddress((void**)&q,    h_q);
    cudaGetSymbolAddress((void**)&kf,   h_kf);
    cudaGetSymbolAddress((void**)&kfull,h_kfull);
    cudaGetSymbolAddress((void**)&vT,   h_vT);
    cudaGetSymbolAddress((void**)&oc,   h_oc);
    cudaGetSymbolAddress((void**)&wcat, h_wcat);
    cudaGetSymbolAddress((void**)&wqb,  h_wqb);
    cudaGetSymbolAddress((void**)&wkvb, h_wkvb);
    cudaGetSymbolAddress((void**)&wo,   h_wo);
    cudaGetSymbolAddress((void**)&bcat, g_biascat);

    // 0) conversions: x; wq_a -> wcat[:1024]; wkv_a(pad) -> wcat[1024:1664]; bias cat
    f2h(x,      xh,   (size_t)NT * D_);
    f2h(wq_a_w, wcat, (size_t)QL * D_);
    wkva_pad_k<<<(unsigned)((size_t)KVP * D_ / 1024), 256>>>(wkv_a_w,
                                                             wcat + (size_t)QL * D_);
    biascat_k<<<7, 256>>>(wq_a_b, wkv_a_b, bcat);
    // 1) qakv = x @ wcat^T + bcat      [4096,1664] K=2048 (TN=128: 416 CTAs)
    launch_h<128, true>(NT, NCAT, D_, xh, D_, 0, 0, wcat, D_, 0, 0,
                        qakv, NCAT, 0, 0, 1, 1, 1.f, bcat);
    // 2) rmsnorm(q_a): qakv[:, :1024] -> qa
    rmsnorm_h<<<NT, 256>>>(qakv, qa, q_norm_w, QL, NCAT, QL);
    // 3) convert wq_b
    f2h(wq_b_w, wqb, (size_t)HQK * QL);
    // 4) q = qa @ wq_b^T + b           [4096,3072] K=1024
    launch_h<256, true>(NT, HQK, QL, qa, QL, 0, 0, wqb, QL, 0, 0,
                        q, HQK, 0, 0, 1, 1, 1.f, wq_b_b);
    // 5) convert wkv_b
    f2h(wkv_b_w, wkvb, (size_t)H_ * 256 * KVL);
    // 6) kv_c = rmsnorm(qakv[:, 1024:1536]) -> kf
    rmsnorm_h<<<NT, 256>>>(qakv + QL, kf, kv_norm_w, KVL, NCAT, KVL);
    // 7) kfull[:, h, 128:192] = rope(k_pe from qakv[:,1536:1600]) broadcast
    rope_k_bcast_h<<<NT, 32>>>(qakv, kfull, cosp, sinp);
    // 8) q[:, h, 128:192] = rope(q_pe) in place
    rope_q_h<<<NT, 512>>>(q, cosp, sinp);
    // 9) kfull[:, h, :128] = kv_c @ wkvb_nope[h]^T   [4096,128] K=512 x16
    launch_h<128, true>(NT, NOPE_, KVL,
                        kf, KVL, 0, 0,
                        wkvb, KVL, 0, (long long)256 * KVL,
                        kfull, HQK, 0, QK_,
                        1, H_, 1.f, nullptr);
    // 10) vT[b,h] = wkvb_v[h] @ kv_c[b]^T   [128,2048] K=512 x32
    launch_h<256, true>(VH_, S_, KVL,
                        wkvb + (size_t)NOPE_ * KVL, KVL, 0, (long long)256 * KVL,
                        kf, KVL, (long long)S_ * KVL, 0,
                        vT, S_, (long long)H_ * VH_ * S_, (long long)VH_ * S_,
                        B_, H_, 1.f, nullptr);
    // 11) fused attention: oc = softmax(SCALE * q @ kfull^T) @ V
    {
        cudaFuncSetAttribute(flash_h, cudaFuncAttributeMaxDynamicSharedMemorySize,
                             FLASH_SMEM);
        dim3 grid(S_ / 128, B_ * H_);
        flash_h<<<grid, 256, FLASH_SMEM>>>(q, kfull, vT, oc);
    }
    // 12) convert wo
    f2h(wo_w, wo, (size_t)D_ * H_ * VH_);
    // 13) out = oc @ wo^T + b           [4096,2048] K=2048 -> fp32
    launch_h<256, false>(NT, D_, H_ * VH_, oc, H_ * VH_, 0, 0, wo, D_, 0, 0,
                         out, D_, 0, 0, 1, 1, 1.f, wo_b);
}

// round 13
// speedup vs baseline: 2.3510x; 1.0189x over previous
#include <cuda_runtime.h>
#include <cuda_fp16.h>
#include <math.h>
#include <stdint.h>

#define B_    2
#define S_    2048
#define D_    2048
#define H_    16
#define NT    4096          // B_*S_
#define QL    1024
#define KVL   512
#define NOPE_ 128
#define ROPE_ 64
#define VH_   128
#define QK_   192
#define KVP   640           // padded kv_full width
#define NCAT  1664          // QL + KVP
#define HQK   3072          // H_*QK_
#define SCALE 0.07216878364870322f   // 192^-0.5

// ---------------- scratch (static device globals; no runtime alloc) -------
__device__ __align__(256) __half h_x   [(size_t)NT * D_];
__device__ __align__(256) __half h_qakv[(size_t)NT * NCAT];    // [q_a(1024) | kv_full(640)]
__device__ __align__(256) __half h_qa  [(size_t)NT * QL];
__device__ __align__(256) __half h_q   [(size_t)NT * HQK];     // [tok][h][192], rope in place
__device__ __align__(256) __half h_kf  [(size_t)NT * KVL];     // kv_c
__device__ __align__(256) __half h_kfull[(size_t)NT * HQK];    // [tok][h][192] = [k_nope|k_pe]
__device__ __align__(256) __half h_vT  [(size_t)B_ * H_ * VH_ * S_]; // [b][h][128][2048]
__device__ __align__(256) __half h_oc  [(size_t)NT * H_ * VH_];
__device__ __align__(256) __half h_wcat[(size_t)NCAT * D_];    // [wq_a | wkv_a_pad]
__device__ __align__(256) __half h_wqb [(size_t)HQK * QL];
__device__ __align__(256) __half h_wkvb[(size_t)H_ * 256 * KVL];
__device__ __align__(256) __half h_wo  [(size_t)D_ * H_ * VH_];
__device__ float g_biascat[NCAT];

// ---------------- helpers ---------------------------------------------------
__device__ __forceinline__ void mma_f16(float* c, const uint32_t* a, const uint32_t* b) {
    asm volatile(
        "mma.sync.aligned.m16n8k16.row.col.f32.f16.f16.f32 "
        "{%0,%1,%2,%3},{%4,%5,%6,%7},{%8,%9},{%0,%1,%2,%3};"
        : "+f"(c[0]), "+f"(c[1]), "+f"(c[2]), "+f"(c[3])
        : "r"(a[0]), "r"(a[1]), "r"(a[2]), "r"(a[3]), "r"(b[0]), "r"(b[1]));
}

__device__ __forceinline__ void ldsm4(uint32_t* r, uint32_t saddr) {
    asm volatile(
        "ldmatrix.sync.aligned.m8n8.x4.shared.b16 {%0,%1,%2,%3}, [%4];"
        : "=r"(r[0]), "=r"(r[1]), "=r"(r[2]), "=r"(r[3]) : "r"(saddr));
}

__device__ __forceinline__ void cp_async16(void* smem, const void* gmem) {
    uint32_t s = (uint32_t)__cvta_generic_to_shared(smem);
    asm volatile("cp.async.cg.shared.global [%0], [%1], 16;" :: "r"(s), "l"(gmem));
}
__device__ __forceinline__ void cp_commit() {
    asm volatile("cp.async.commit_group;");
}
template<int N>
__device__ __forceinline__ void cp_wait() {
    asm volatile("cp.async.wait_group %0;" :: "n"(N));
}

// =============================================================================
// gemm_h: fp16 in / fp32 acc. CTA tile 128 x TN (TN = 128 or 256),
// warp tile 64x64, BK=32, 3-stage cp.async, ldmatrix fragments.
// C[z] = alpha * A[z] @ B[z]^T + bias.  A [M,K], B [N,K], both half row-major.
// =============================================================================
template<int TN, bool OUTHALF>
__global__ void __launch_bounds__(TN == 256 ? 256 : 128) gemm_h(
    int K,
    const __half* __restrict__ A, int lda, long long sAb, long long sAh,
    const __half* __restrict__ Bp, int ldb, long long sBb, long long sBh,
    void* __restrict__ Cv, int ldc, long long sCb, long long sCh,
    int ZH, float alpha, const float* __restrict__ bias)
{
    constexpr int T = (TN == 256) ? 256 : 128;
    constexpr int WCOLS = TN / 64;
    constexpr int ASTR = 20;                     // u32 per row (80 B)
    constexpr int STGA = 128 * ASTR;
    constexpr int STGB = TN * ASTR;
    constexpr int AITER = 512 / T;
    constexpr int BITER = (TN * 4) / T;

    extern __shared__ uint32_t smu[];
    uint32_t* sA = smu;
    uint32_t* sB = smu + 3 * STGA;

    int z  = blockIdx.z;
    int zb = z / ZH;
    int zh = z - zb * ZH;
    const __half* Ab = A  + zb * sAb + zh * sAh;
    const __half* Bb = Bp + zb * sBb + zh * sBh;

    int row0 = blockIdx.y << 7;
    int col0 = blockIdx.x * TN;
    int tid  = threadIdx.x;
    int wid  = tid >> 5;
    int lane = tid & 31;
    int wm0 = (wid / WCOLS) << 6;
    int wn0 = (wid % WCOLS) << 6;
    int g = lane >> 2, t4 = lane & 3;
    int j = lane >> 3, r = lane & 7;

    uint32_t sA_u = (uint32_t)__cvta_generic_to_shared(sA);
    uint32_t sB_u = (uint32_t)__cvta_generic_to_shared(sB);
    uint32_t aoff0 = (uint32_t)(wm0 + (j & 1) * 8 + r) * 80 + (uint32_t)(j >> 1) * 16;
    uint32_t boff0 = (uint32_t)(wn0 + (j >> 1) * 8 + r) * 80 + (uint32_t)(j & 1) * 16;

    float acc[4][8][4] = {};

    auto load_stage = [&](int st, int k0) {
        uint32_t* a_s = sA + st * STGA;
        uint32_t* b_s = sB + st * STGB;
        #pragma unroll
        for (int i = 0; i < AITER; i++) {
            int idx = tid + T * i;
            int rr = idx >> 2, q = idx & 3;
            cp_async16(a_s + rr * ASTR + q * 4,
                       Ab + (size_t)(row0 + rr) * lda + k0 + q * 8);
        }
        #pragma unroll
        for (int i = 0; i < BITER; i++) {
            int idx = tid + T * i;
            int rr = idx >> 2, q = idx & 3;
            cp_async16(b_s + rr * ASTR + q * 4,
                       Bb + (size_t)(col0 + rr) * ldb + k0 + q * 8);
        }
    };

    int nk = K / 32;
    load_stage(0, 0);
    cp_commit();
    load_stage(1, 32);
    cp_commit();

    for (int i = 0; i < nk; i++) {
        cp_wait<1>();
        __syncthreads();
        if (i + 2 < nk) load_stage((i + 2) % 3, (i + 2) * 32);
        cp_commit();

        uint32_t abase = sA_u + (uint32_t)((i % 3) * STGA) * 4 + aoff0;
        uint32_t bbase = sB_u + (uint32_t)((i % 3) * STGB) * 4 + boff0;

        #pragma unroll
        for (int kk = 0; kk < 2; kk++) {
            uint32_t afr[4][4], bfr[4][4];
            #pragma unroll
            for (int mt = 0; mt < 4; mt++)
                ldsm4(afr[mt], abase + mt * 1280 + kk * 32);
            #pragma unroll
            for (int nt2 = 0; nt2 < 4; nt2++)
                ldsm4(bfr[nt2], bbase + nt2 * 1280 + kk * 32);
            #pragma unroll
            for (int mt = 0; mt < 4; mt++)
                #pragma unroll
                for (int nt2 = 0; nt2 < 4; nt2++) {
                    mma_f16(acc[mt][2 * nt2],     afr[mt], &bfr[nt2][0]);
                    mma_f16(acc[mt][2 * nt2 + 1], afr[mt], &bfr[nt2][2]);
                }
        }
    }

    size_t coff = (size_t)zb * sCb + (size_t)zh * sCh;
    #pragma unroll
    for (int mt = 0; mt < 4; mt++) {
        int r0 = row0 + wm0 + mt * 16 + g;
        #pragma unroll
        for (int nt = 0; nt < 8; nt++) {
            int c0c = col0 + wn0 + nt * 8 + 2 * t4;
            float b0 = bias ? bias[c0c] : 0.f;
            float b1 = bias ? bias[c0c + 1] : 0.f;
            float v00 = alpha * acc[mt][nt][0] + b0;
            float v01 = alpha * acc[mt][nt][1] + b1;
            float v10 = alpha * acc[mt][nt][2] + b0;
            float v11 = alpha * acc[mt][nt][3] + b1;
            if (OUTHALF) {
                __half* Ch = (__half*)Cv + coff;
                *(__half2*)&Ch[(size_t)r0 * ldc + c0c]       = __floats2half2_rn(v00, v01);
                *(__half2*)&Ch[(size_t)(r0 + 8) * ldc + c0c] = __floats2half2_rn(v10, v11);
            } else {
                float* Cf = (float*)Cv + coff;
                *(float2*)&Cf[(size_t)r0 * ldc + c0c]       = make_float2(v00, v01);
                *(float2*)&Cf[(size_t)(r0 + 8) * ldc + c0c] = make_float2(v10, v11);
            }
        }
    }
}

// =============================================================================
// flash_h: fused scores + online softmax (half2 ex2) + P@V. Q register-resident.
// Grid (S/128, B*H). 256 threads = 8 warps, each warp owns 16 query rows.
// =============================================================================
#define QROW 400
#define VROW 144
#define SQ_BYTES (128 * QROW)       // 51200
#define SK_STG   (64 * QROW)        // 25600
#define SV_STG   (128 * VROW)       // 18432
#define FLASH_SMEM (SQ_BYTES + 3 * SK_STG + 3 * SV_STG)   // 183296

__global__ void __launch_bounds__(256) flash_h(
    const __half* __restrict__ q,      // [tok][H][192] (rope applied)
    const __half* __restrict__ kfull,  // [tok][H][192]
    const __half* __restrict__ vT,     // [(b*H+h)][128][2048]
    __half* __restrict__ oc)           // [tok][H*128]
{
    extern __shared__ char sm[];
    char* sQ = sm;
    char* sK = sm + SQ_BYTES;
    char* sV = sK + 3 * SK_STG;

    int qt = blockIdx.x;
    int bh = blockIdx.y;
    int b  = bh >> 4, h = bh & 15;
    int q0 = qt << 7;

    int tid = threadIdx.x, wid = tid >> 5, lane = tid & 31;
    int g = lane >> 2, t4 = lane & 3;
    int j = lane >> 3, r = lane & 7;

    const __half* qg = q     + (size_t)b * S_ * HQK + h * QK_;
    const __half* kg = kfull + (size_t)b * S_ * HQK + h * QK_;
    const __half* vg = vT    + (size_t)bh * VH_ * S_;

    #pragma unroll
    for (int i = 0; i < 12; i++) {
        int idx = tid + 256 * i;
        int row = idx / 24, c = idx % 24;
        cp_async16(sQ + row * QROW + c * 16,
                   (const char*)(qg + (size_t)(q0 + row) * HQK) + c * 16);
    }
    auto load_kv = [&](int st, int kc0) {
        char* k_s = sK + st * SK_STG;
        char* v_s = sV + st * SV_STG;
        #pragma unroll
        for (int i = 0; i < 6; i++) {
            int idx = tid + 256 * i;
            int row = idx / 24, c = idx % 24;
            cp_async16(k_s + row * QROW + c * 16,
                       (const char*)(kg + (size_t)(kc0 + row) * HQK) + c * 16);
        }
        #pragma unroll
        for (int i = 0; i < 4; i++) {
            int idx = tid + 256 * i;
            int row = idx >> 3, c = idx & 7;
            cp_async16(v_s + row * VROW + c * 16,
                       (const char*)(vg + (size_t)row * S_ + kc0) + c * 16);
        }
    };

    load_kv(0, 0);
    cp_commit();
    load_kv(1, 64);
    cp_commit();

    uint32_t sQ_u = (uint32_t)__cvta_generic_to_shared(sQ);
    uint32_t sK_u = (uint32_t)__cvta_generic_to_shared(sK);
    uint32_t sV_u = (uint32_t)__cvta_generic_to_shared(sV);
    uint32_t qoff = sQ_u + (uint32_t)(wid * 16 + (j & 1) * 8 + r) * QROW + (j >> 1) * 16;
    uint32_t koff = (uint32_t)((j >> 1) * 8 + r) * QROW + (j & 1) * 16;
    uint32_t voff = (uint32_t)((j >> 1) * 8 + r) * VROW + (j & 1) * 16;

    cp_wait<1>();
    __syncthreads();
    uint32_t qfr[12][4];
    #pragma unroll
    for (int kk = 0; kk < 12; kk++)
        ldsm4(qfr[kk], qoff + kk * 32);

    float oacc[16][4] = {};
    float m0 = -1e30f, m1 = -1e30f, l0 = 0.f, l1 = 0.f;
    const float K2 = SCALE * 1.4426950408889634f;

    for (int it = 0; it < 32; it++) {
        if (it > 0) {
            cp_wait<1>();
            __syncthreads();
        }
        if (it + 2 < 32) load_kv((it + 2) % 3, (it + 2) * 64);
        cp_commit();

        uint32_t kb = sK_u + (uint32_t)((it % 3) * SK_STG) + koff;
        uint32_t vb = sV_u + (uint32_t)((it % 3) * SV_STG) + voff;

        // ---- S = Q @ K^T  (16 x 64 per warp, K=192) ----
        float sacc[8][4] = {};
        #pragma unroll
        for (int kk = 0; kk < 12; kk++) {
            #pragma unroll
            for (int n2 = 0; n2 < 4; n2++) {
                uint32_t bk[4];
                ldsm4(bk, kb + n2 * (16 * QROW) + kk * 32);
                mma_f16(sacc[2 * n2],     qfr[kk], &bk[0]);
                mma_f16(sacc[2 * n2 + 1], qfr[kk], &bk[2]);
            }
        }

        // ---- online softmax (rows g and g+8), exp in half2 MUFU ----
        float mx0 = -1e30f, mx1 = -1e30f;
        #pragma unroll
        for (int nt = 0; nt < 8; nt++) {
            mx0 = fmaxf(mx0, fmaxf(sacc[nt][0], sacc[nt][1]));
            mx1 = fmaxf(mx1, fmaxf(sacc[nt][2], sacc[nt][3]));
        }
        mx0 = fmaxf(mx0, __shfl_xor_sync(0xffffffffu, mx0, 1));
        mx0 = fmaxf(mx0, __shfl_xor_sync(0xffffffffu, mx0, 2));
        mx1 = fmaxf(mx1, __shfl_xor_sync(0xffffffffu, mx1, 1));
        mx1 = fmaxf(mx1, __shfl_xor_sync(0xffffffffu, mx1, 2));
        float mn0 = fmaxf(m0, mx0), mn1 = fmaxf(m1, mx1);
        float rs0 = exp2f((m0 - mn0) * K2), rs1 = exp2f((m1 - mn1) * K2);
        m0 = mn0; m1 = mn1;

        uint32_t p01[8], p23[8];
        float sum0 = 0.f, sum1 = 0.f;
        #pragma unroll
        for (int nt = 0; nt < 8; nt++) {
            __half2 a01 = __floats2half2_rn((sacc[nt][0] - mn0) * K2,
                                            (sacc[nt][1] - mn0) * K2);
            __half2 a23 = __floats2half2_rn((sacc[nt][2] - mn1) * K2,
                                            (sacc[nt][3] - mn1) * K2);
            __half2 e01 = h2exp2(a01);
            __half2 e23 = h2exp2(a23);
            float2 f01 = __half22float2(e01);
            float2 f23 = __half22float2(e23);
            sum0 += f01.x + f01.y;
            sum1 += f23.x + f23.y;
            p01[nt] = *(uint32_t*)&e01;
            p23[nt] = *(uint32_t*)&e23;
        }
        sum0 += __shfl_xor_sync(0xffffffffu, sum0, 1);
        sum0 += __shfl_xor_sync(0xffffffffu, sum0, 2);
        sum1 += __shfl_xor_sync(0xffffffffu, sum1, 1);
        sum1 += __shfl_xor_sync(0xffffffffu, sum1, 2);
        l0 = l0 * rs0 + sum0;
        l1 = l1 * rs1 + sum1;

        #pragma unroll
        for (int nt = 0; nt < 16; nt++) {
            oacc[nt][0] *= rs0; oacc[nt][1] *= rs0;
            oacc[nt][2] *= rs1; oacc[nt][3] *= rs1;
        }

        // ---- O += P @ V  (K=64, N=128) ----
        #pragma unroll
        for (int kk = 0; kk < 4; kk++) {
            uint32_t pa[4] = {p01[2 * kk], p23[2 * kk], p01[2 * kk + 1], p23[2 * kk + 1]};
            #pragma unroll
            for (int n2 = 0; n2 < 8; n2++) {
                uint32_t bv[4];
                ldsm4(bv, vb + n2 * (16 * VROW) + kk * 32);
                mma_f16(oacc[2 * n2],     pa, &bv[0]);
                mma_f16(oacc[2 * n2 + 1], pa, &bv[2]);
            }
        }
    }

    // ---- normalize and store ----
    float il0 = 1.f / l0, il1 = 1.f / l1;
    int row = q0 + wid * 16 + g;
    size_t tok0 = (size_t)b * S_ + row;
    __half* o0 = oc + tok0 * (H_ * VH_) + h * VH_;
    __half* o1 = o0 + (size_t)8 * (H_ * VH_);
    #pragma unroll
    for (int nt = 0; nt < 16; nt++) {
        int c = nt * 8 + 2 * t4;
        *(__half2*)&o0[c] = __floats2half2_rn(oacc[nt][0] * il0, oacc[nt][1] * il0);
        *(__half2*)&o1[c] = __floats2half2_rn(oacc[nt][2] * il1, oacc[nt][3] * il1);
    }
}

// ---------------- prepass kernels --------------------------------------------
__global__ void f2h_k(const float* __restrict__ in, __half* __restrict__ out)
{
    size_t i = ((size_t)blockIdx.x * 256 + threadIdx.x) * 4;
    float4 v = *(const float4*)(in + i);
    __half2* o = (__half2*)(out + i);
    o[0] = __floats2half2_rn(v.x, v.y);
    o[1] = __floats2half2_rn(v.z, v.w);
}

__global__ void wkva_pad_k(const float* __restrict__ in, __half* __restrict__ out)
{
    size_t i = ((size_t)blockIdx.x * 256 + threadIdx.x) * 4;
    if (i < (size_t)(KVL + ROPE_) * D_) {
        float4 v = *(const float4*)(in + i);
        __half2* o = (__half2*)(out + i);
        o[0] = __floats2half2_rn(v.x, v.y);
        o[1] = __floats2half2_rn(v.z, v.w);
    } else {
        __half2* o = (__half2*)(out + i);
        o[0] = __half2{__half(0.f), __half(0.f)};
        o[1] = __half2{__half(0.f), __half(0.f)};
    }
}

__global__ void biascat_k(const float* __restrict__ qb, const float* __restrict__ kb,
                          float* __restrict__ out)
{
    int i = blockIdx.x * 256 + threadIdx.x;
    if (i >= NCAT) return;
    if (i < QL) out[i] = qb[i];
    else if (i < QL + KVL + ROPE_) out[i] = kb[i - QL];
    else out[i] = 0.f;
}

// ---------------- elementwise kernels -----------------------------------------
// width/strides in halfs (even); vectorized half2 + warp-shuffle reduction.
__global__ void rmsnorm_h(const __half* __restrict__ in, __half* __restrict__ out,
                          const float* __restrict__ w, int width,
                          int inStride, int outStride)
{
    int row = blockIdx.x;
    const __half2* ip = (const __half2*)(in + (size_t)row * inStride);
    __half2*       op = (__half2*)(out + (size_t)row * outStride);
    int w2 = width >> 1;
    float ss = 0.f;
    for (int i = threadIdx.x; i < w2; i += 256) {
        float2 v = __half22float2(ip[i]);
        ss += v.x * v.x + v.y * v.y;
    }
    ss += __shfl_xor_sync(0xffffffffu, ss, 16);
    ss += __shfl_xor_sync(0xffffffffu, ss, 8);
    ss += __shfl_xor_sync(0xffffffffu, ss, 4);
    ss += __shfl_xor_sync(0xffffffffu, ss, 2);
    ss += __shfl_xor_sync(0xffffffffu, ss, 1);
    __shared__ float sm[8];
    if ((threadIdx.x & 31) == 0) sm[threadIdx.x >> 5] = ss;
    __syncthreads();
    float tot = sm[0] + sm[1] + sm[2] + sm[3] + sm[4] + sm[5] + sm[6] + sm[7];
    float rr = rsqrtf(tot / (float)width + 1e-3f);
    for (int i = threadIdx.x; i < w2; i += 256) {
        float2 v = __half22float2(ip[i]);
        op[i] = __floats2half2_rn(w[2 * i] * v.x * rr, w[2 * i + 1] * v.y * rr);
    }
}

__global__ void rope_q_h(__half* __restrict__ q,
                         const float* __restrict__ c, const float* __restrict__ s)
{
    int tok = blockIdx.x;
    int h = threadIdx.x >> 5;
    int j = threadIdx.x & 31;
    int pos = tok % S_;
    __half* p = q + (size_t)tok * HQK + h * QK_ + NOPE_;
    float xr = __half2float(p[2 * j]), xi = __half2float(p[2 * j + 1]);
    float cc = c[pos * 32 + j], sn = s[pos * 32 + j];
    p[2 * j]     = __float2half(xr * cc - xi * sn);
    p[2 * j + 1] = __float2half(xr * sn + xi * cc);
}

// rope k_pe broadcast; 256 threads = 8 tokens x 32 lanes per block
__global__ void rope_k_bcast_h(const __half* __restrict__ qakv, __half* __restrict__ kfull,
                               const float* __restrict__ c, const float* __restrict__ s)
{
    int tok = blockIdx.x * 8 + (threadIdx.x >> 5);
    int j = threadIdx.x & 31;
    int pos = tok % S_;
    const __half* src = qakv + (size_t)tok * NCAT + QL + KVL;
    float xr = __half2float(src[2 * j]), xi = __half2float(src[2 * j + 1]);
    float cc = c[pos * 32 + j], sn = s[pos * 32 + j];
    __half2 v;
    v.x = __float2half(xr * cc - xi * sn);
    v.y = __float2half(xr * sn + xi * cc);
    __half* dst = kfull + (size_t)tok * HQK + NOPE_;
    #pragma unroll
    for (int h = 0; h < H_; h++)
        *(__half2*)&dst[h * QK_ + 2 * j] = v;
}

// ---------------- host glue --------------------------------------------------
template<int TN, bool OUTHALF>
static void launch_h(int M, int N, int K,
                     const __half* A, int lda, long long sAb, long long sAh,
                     const __half* Bp, int ldb, long long sBb, long long sBh,
                     void* C, int ldc, long long sCb, long long sCh,
                     int nb, int nh, float alpha, const float* bias)
{
    constexpr int SMEM = (3 * 128 * 20 + 3 * TN * 20) * 4;
    cudaFuncSetAttribute(gemm_h<TN, OUTHALF>,
                         cudaFuncAttributeMaxDynamicSharedMemorySize, SMEM);
    dim3 grid(N / TN, M / 128, nb * nh);
    gemm_h<TN, OUTHALF><<<grid, TN == 256 ? 256 : 128, SMEM>>>(
        K, A, lda, sAb, sAh, Bp, ldb, sBb, sBh, C, ldc, sCb, sCh, nh, alpha, bias);
}

static void f2h(const float* in, __half* out, size_t n)
{
    f2h_k<<<(unsigned)(n / 1024), 256>>>(in, out);
}

extern "C" void kernel_launch(void* const* d_in, const int* in_sizes, int n_in,
                              void* d_out, int out_size)
{
    const float* x        = (const float*)d_in[0];
    const float* cosp     = (const float*)d_in[2];
    const float* sinp     = (const float*)d_in[3];
    const float* wq_a_w   = (const float*)d_in[4];
    const float* wq_a_b   = (const float*)d_in[5];
    const float* q_norm_w = (const float*)d_in[6];
    const float* wq_b_w   = (const float*)d_in[7];
    const float* wq_b_b   = (const float*)d_in[8];
    const float* wkv_a_w  = (const float*)d_in[9];
    const float* wkv_a_b  = (const float*)d_in[10];
    const float* kv_norm_w= (const float*)d_in[11];
    const float* wkv_b_w  = (const float*)d_in[12];
    const float* wo_w     = (const float*)d_in[13];
    const float* wo_b     = (const float*)d_in[14];
    float* out = (float*)d_out;

    __half *xh, *qakv, *qa, *q, *kf, *kfull, *vT, *oc;
    __half *wcat, *wqb, *wkvb, *wo;
    float *bcat;
    cudaGetSymbolAddress((void**)&xh,   h_x);
    cudaGetSymbolAddress((void**)&qakv, h_qakv);
    cudaGetSymbolAddress((void**)&qa,   h_qa);
    cudaGetSymbolAddress((void**)&q,    h_q);
    cudaGetSymbolAddress((void**)&kf,   h_kf);
    cudaGetSymbolAddress((void**)&kfull,h_kfull);
    cudaGetSymbolAddress((void**)&vT,   h_vT);
    cudaGetSymbolAddress((void**)&oc,   h_oc);
    cudaGetSymbolAddress((void**)&wcat, h_wcat);
    cudaGetSymbolAddress((void**)&wqb,  h_wqb);
    cudaGetSymbolAddress((void**)&wkvb, h_wkvb);
    cudaGetSymbolAddress((void**)&wo,   h_wo);
    cudaGetSymbolAddress((void**)&bcat, g_biascat);

    // 0) conversions
    f2h(x,      xh,   (size_t)NT * D_);
    f2h(wq_a_w, wcat, (size_t)QL * D_);
    wkva_pad_k<<<(unsigned)((size_t)KVP * D_ / 1024), 256>>>(wkv_a_w,
                                                             wcat + (size_t)QL * D_);
    biascat_k<<<7, 256>>>(wq_a_b, wkv_a_b, bcat);
    // 1) qakv = x @ wcat^T + bcat      [4096,1664] K=2048 (TN=128: 416 CTAs)
    launch_h<128, true>(NT, NCAT, D_, xh, D_, 0, 0, wcat, D_, 0, 0,
                        qakv, NCAT, 0, 0, 1, 1, 1.f, bcat);
    // 2) rmsnorm(q_a)
    rmsnorm_h<<<NT, 256>>>(qakv, qa, q_norm_w, QL, NCAT, QL);
    // 3) convert wq_b
    f2h(wq_b_w, wqb, (size_t)HQK * QL);
    // 4) q = qa @ wq_b^T + b           [4096,3072] K=1024 (TN=128: 768 CTAs)
    launch_h<128, true>(NT, HQK, QL, qa, QL, 0, 0, wqb, QL, 0, 0,
                        q, HQK, 0, 0, 1, 1, 1.f, wq_b_b);
    // 5) convert wkv_b
    f2h(wkv_b_w, wkvb, (size_t)H_ * 256 * KVL);
    // 6) kv_c = rmsnorm(qakv[:, 1024:1536])
    rmsnorm_h<<<NT, 256>>>(qakv + QL, kf, kv_norm_w, KVL, NCAT, KVL);
    // 7) kfull[:, h, 128:192] = rope(k_pe) broadcast (8 tokens/block)
    rope_k_bcast_h<<<NT / 8, 256>>>(qakv, kfull, cosp, sinp);
    // 8) q rope in place
    rope_q_h<<<NT, 512>>>(q, cosp, sinp);
    // 9) kfull[:, h, :128] = kv_c @ wkvb_nope[h]^T   [4096,128] K=512 x16
    launch_h<128, true>(NT, NOPE_, KVL,
                        kf, KVL, 0, 0,
                        wkvb, KVL, 0, (long long)256 * KVL,
                        kfull, HQK, 0, QK_,
                        1, H_, 1.f, nullptr);
    // 10) vT[b,h] = wkvb_v[h] @ kv_c[b]^T   [128,2048] K=512 x32
    launch_h<256, true>(VH_, S_, KVL,
                        wkvb + (size_t)NOPE_ * KVL, KVL, 0, (long long)256 * KVL,
                        kf, KVL, (long long)S_ * KVL, 0,
                        vT, S_, (long long)H_ * VH_ * S_, (long long)VH_ * S_,
                        B_, H_, 1.f, nullptr);
    // 11) fused attention
    {
        cudaFuncSetAttribute(flash_h, cudaFuncAttributeMaxDynamicSharedMemorySize,
                             FLASH_SMEM);
        dim3 grid(S_ / 128, B_ * H_);
        flash_h<<<grid, 256, FLASH_SMEM>>>(q, kfull, vT, oc);
    }
    // 12) convert wo
    f2h(wo_w, wo, (size_t)D_ * H_ * VH_);
    // 13) out = oc @ wo^T + b           [4096,2048] K=2048 -> fp32
    launch_h<256, false>(NT, D_, H_ * VH_, oc, H_ * VH_, 0, 0, wo, D_, 0, 0,
                         out, D_, 0, 0, 1, 1, 1.f, wo_b);
}

// round 14
// speedup vs baseline: 2.3942x; 1.0183x over previous
#include <cuda_runtime.h>
#include <cuda_fp16.h>
#include <math.h>
#include <stdint.h>

#define B_    2
#define S_    2048
#define D_    2048
#define H_    16
#define NT    4096          // B_*S_
#define QL    1024
#define KVL   512
#define NOPE_ 128
#define ROPE_ 64
#define VH_   128
#define QK_   192
#define KVP   640           // padded kv_full width
#define NCAT  1664          // QL + KVP
#define HQK   3072          // H_*QK_
#define SCALE 0.07216878364870322f   // 192^-0.5

// ---------------- scratch (static device globals; no runtime alloc) -------
__device__ __align__(256) __half h_x   [(size_t)NT * D_];
__device__ __align__(256) __half h_qakv[(size_t)NT * NCAT];
__device__ __align__(256) __half h_qa  [(size_t)NT * QL];
__device__ __align__(256) __half h_q   [(size_t)NT * HQK];
__device__ __align__(256) __half h_kf  [(size_t)NT * KVL];
__device__ __align__(256) __half h_kfull[(size_t)NT * HQK];
__device__ __align__(256) __half h_vT  [(size_t)B_ * H_ * VH_ * S_];
__device__ __align__(256) __half h_oc  [(size_t)NT * H_ * VH_];
__device__ __align__(256) __half h_wcat[(size_t)NCAT * D_];
__device__ __align__(256) __half h_wqb [(size_t)HQK * QL];
__device__ __align__(256) __half h_wkvb[(size_t)H_ * 256 * KVL];
__device__ __align__(256) __half h_wo  [(size_t)D_ * H_ * VH_];
__device__ float g_biascat[NCAT];

// ---------------- helpers ---------------------------------------------------
__device__ __forceinline__ void mma_f16(float* c, const uint32_t* a, const uint32_t* b) {
    asm volatile(
        "mma.sync.aligned.m16n8k16.row.col.f32.f16.f16.f32 "
        "{%0,%1,%2,%3},{%4,%5,%6,%7},{%8,%9},{%0,%1,%2,%3};"
        : "+f"(c[0]), "+f"(c[1]), "+f"(c[2]), "+f"(c[3])
        : "r"(a[0]), "r"(a[1]), "r"(a[2]), "r"(a[3]), "r"(b[0]), "r"(b[1]));
}

__device__ __forceinline__ void ldsm4(uint32_t* r, uint32_t saddr) {
    asm volatile(
        "ldmatrix.sync.aligned.m8n8.x4.shared.b16 {%0,%1,%2,%3}, [%4];"
        : "=r"(r[0]), "=r"(r[1]), "=r"(r[2]), "=r"(r[3]) : "r"(saddr));
}

__device__ __forceinline__ void cp_async16(void* smem, const void* gmem) {
    uint32_t s = (uint32_t)__cvta_generic_to_shared(smem);
    asm volatile("cp.async.cg.shared.global [%0], [%1], 16;" :: "r"(s), "l"(gmem));
}
__device__ __forceinline__ void cp_commit() {
    asm volatile("cp.async.commit_group;");
}
template<int N>
__device__ __forceinline__ void cp_wait() {
    asm volatile("cp.async.wait_group %0;" :: "n"(N));
}

// =============================================================================
// gemm_body: fp16 in / fp32 acc. CTA tile 128 x TN, warp tile 64x64, BK=32,
// 3-stage cp.async, ldmatrix fragments. C = alpha * A @ B^T + bias.
// ROPE: apply rope to cols with (col % 192) >= 128 in the epilogue (q GEMM).
// =============================================================================
template<int TN, bool OUTHALF, bool ROPE>
__device__ __forceinline__ void gemm_body(
    int bx, int by, int bz, int K,
    const __half* __restrict__ A, int lda, long long sAb, long long sAh,
    const __half* __restrict__ Bp, int ldb, long long sBb, long long sBh,
    void* __restrict__ Cv, int ldc, long long sCb, long long sCh,
    int ZH, float alpha, const float* __restrict__ bias,
    const float* __restrict__ cosp, const float* __restrict__ sinp,
    uint32_t* smu)
{
    constexpr int T = (TN == 256) ? 256 : 128;
    constexpr int WCOLS = TN / 64;
    constexpr int ASTR = 20;                     // u32 per row (80 B)
    constexpr int STGA = 128 * ASTR;
    constexpr int STGB = TN * ASTR;
    constexpr int AITER = 512 / T;
    constexpr int BITER = (TN * 4) / T;

    uint32_t* sA = smu;
    uint32_t* sB = smu + 3 * STGA;

    int zb = bz / ZH;
    int zh = bz - zb * ZH;
    const __half* Ab = A  + zb * sAb + zh * sAh;
    const __half* Bb = Bp + zb * sBb + zh * sBh;

    int row0 = by << 7;
    int col0 = bx * TN;
    int tid  = threadIdx.x;
    int wid  = tid >> 5;
    int lane = tid & 31;
    int wm0 = (wid / WCOLS) << 6;
    int wn0 = (wid % WCOLS) << 6;
    int g = lane >> 2, t4 = lane & 3;
    int j = lane >> 3, r = lane & 7;

    uint32_t sA_u = (uint32_t)__cvta_generic_to_shared(sA);
    uint32_t sB_u = (uint32_t)__cvta_generic_to_shared(sB);
    uint32_t aoff0 = (uint32_t)(wm0 + (j & 1) * 8 + r) * 80 + (uint32_t)(j >> 1) * 16;
    uint32_t boff0 = (uint32_t)(wn0 + (j >> 1) * 8 + r) * 80 + (uint32_t)(j & 1) * 16;

    float acc[4][8][4] = {};

    auto load_stage = [&](int st, int k0) {
        uint32_t* a_s = sA + st * STGA;
        uint32_t* b_s = sB + st * STGB;
        #pragma unroll
        for (int i = 0; i < AITER; i++) {
            int idx = tid + T * i;
            int rr = idx >> 2, q = idx & 3;
            cp_async16(a_s + rr * ASTR + q * 4,
                       Ab + (size_t)(row0 + rr) * lda + k0 + q * 8);
        }
        #pragma unroll
        for (int i = 0; i < BITER; i++) {
            int idx = tid + T * i;
            int rr = idx >> 2, q = idx & 3;
            cp_async16(b_s + rr * ASTR + q * 4,
                       Bb + (size_t)(col0 + rr) * ldb + k0 + q * 8);
        }
    };

    int nk = K / 32;
    load_stage(0, 0);
    cp_commit();
    load_stage(1, 32);
    cp_commit();

    for (int i = 0; i < nk; i++) {
        cp_wait<1>();
        __syncthreads();
        if (i + 2 < nk) load_stage((i + 2) % 3, (i + 2) * 32);
        cp_commit();

        uint32_t abase = sA_u + (uint32_t)((i % 3) * STGA) * 4 + aoff0;
        uint32_t bbase = sB_u + (uint32_t)((i % 3) * STGB) * 4 + boff0;

        #pragma unroll
        for (int kk = 0; kk < 2; kk++) {
            uint32_t afr[4][4], bfr[4][4];
            #pragma unroll
            for (int mt = 0; mt < 4; mt++)
                ldsm4(afr[mt], abase + mt * 1280 + kk * 32);
            #pragma unroll
            for (int nt2 = 0; nt2 < 4; nt2++)
                ldsm4(bfr[nt2], bbase + nt2 * 1280 + kk * 32);
            #pragma unroll
            for (int mt = 0; mt < 4; mt++)
                #pragma unroll
                for (int nt2 = 0; nt2 < 4; nt2++) {
                    mma_f16(acc[mt][2 * nt2],     afr[mt], &bfr[nt2][0]);
                    mma_f16(acc[mt][2 * nt2 + 1], afr[mt], &bfr[nt2][2]);
                }
        }
        __syncthreads();
    }

    size_t coff = (size_t)zb * sCb + (size_t)zh * sCh;
    #pragma unroll
    for (int mt = 0; mt < 4; mt++) {
        int r0 = row0 + wm0 + mt * 16 + g;
        #pragma unroll
        for (int nt = 0; nt < 8; nt++) {
            int c0c = col0 + wn0 + nt * 8 + 2 * t4;
            float b0 = bias ? bias[c0c] : 0.f;
            float b1 = bias ? bias[c0c + 1] : 0.f;
            float v00 = alpha * acc[mt][nt][0] + b0;
            float v01 = alpha * acc[mt][nt][1] + b1;
            float v10 = alpha * acc[mt][nt][2] + b0;
            float v11 = alpha * acc[mt][nt][3] + b1;
            if (ROPE) {
                int hc = c0c % QK_;
                if (hc >= NOPE_) {
                    int jj = (hc - NOPE_) >> 1;
                    int pos0 = r0 & (S_ - 1);
                    int pos1 = (r0 + 8) & (S_ - 1);
                    float c0 = cosp[pos0 * 32 + jj], s0 = sinp[pos0 * 32 + jj];
                    float c1 = cosp[pos1 * 32 + jj], s1 = sinp[pos1 * 32 + jj];
                    float xr = v00, xi = v01;
                    v00 = xr * c0 - xi * s0;
                    v01 = xr * s0 + xi * c0;
                    xr = v10; xi = v11;
                    v10 = xr * c1 - xi * s1;
                    v11 = xr * s1 + xi * c1;
                }
            }
            if (OUTHALF) {
                __half* Ch = (__half*)Cv + coff;
                *(__half2*)&Ch[(size_t)r0 * ldc + c0c]       = __floats2half2_rn(v00, v01);
                *(__half2*)&Ch[(size_t)(r0 + 8) * ldc + c0c] = __floats2half2_rn(v10, v11);
            } else {
                float* Cf = (float*)Cv + coff;
                *(float2*)&Cf[(size_t)r0 * ldc + c0c]       = make_float2(v00, v01);
                *(float2*)&Cf[(size_t)(r0 + 8) * ldc + c0c] = make_float2(v10, v11);
            }
        }
    }
}

template<int TN, bool OUTHALF, bool ROPE>
__global__ void __launch_bounds__(TN == 256 ? 256 : 128) gemm_h(
    int K,
    const __half* __restrict__ A, int lda, long long sAb, long long sAh,
    const __half* __restrict__ Bp, int ldb, long long sBb, long long sBh,
    void* __restrict__ Cv, int ldc, long long sCb, long long sCh,
    int ZH, float alpha, const float* __restrict__ bias,
    const float* __restrict__ cosp, const float* __restrict__ sinp)
{
    extern __shared__ uint32_t smu[];
    gemm_body<TN, OUTHALF, ROPE>(blockIdx.x, blockIdx.y, blockIdx.z, K,
                                 A, lda, sAb, sAh, Bp, ldb, sBb, sBh,
                                 Cv, ldc, sCb, sCh, ZH, alpha, bias,
                                 cosp, sinp, smu);
}

// Dual GEMM: blocks [0,512) = vT (x=bid&15,z=bid>>4); [512,1024) = knope.
__global__ void __launch_bounds__(128) gemm_dual(
    int K1, const __half* A1, int lda1, long long sAb1, long long sAh1,
    const __half* B1, int ldb1, long long sBb1, long long sBh1,
    void* C1, int ldc1, long long sCb1, long long sCh1, int ZH1,
    int K2, const __half* A2, int lda2, long long sAb2, long long sAh2,
    const __half* B2, int ldb2, long long sBb2, long long sBh2,
    void* C2, int ldc2, long long sCb2, long long sCh2, int ZH2)
{
    extern __shared__ uint32_t smu[];
    int bid = blockIdx.x;
    if (bid < 512) {
        gemm_body<128, true, false>(bid & 15, 0, bid >> 4, K1,
                                    A1, lda1, sAb1, sAh1, B1, ldb1, sBb1, sBh1,
                                    C1, ldc1, sCb1, sCh1, ZH1, 1.f, nullptr,
                                    nullptr, nullptr, smu);
    } else {
        int t = bid - 512;
        gemm_body<128, true, false>(0, t & 31, t >> 5, K2,
                                    A2, lda2, sAb2, sAh2, B2, ldb2, sBb2, sBh2,
                                    C2, ldc2, sCb2, sCh2, ZH2, 1.f, nullptr,
                                    nullptr, nullptr, smu);
    }
}

// =============================================================================
// flash_h: fused scores + online softmax (half2 ex2) + P@V. Q register-resident.
// =============================================================================
#define QROW 400
#define VROW 144
#define SQ_BYTES (128 * QROW)
#define SK_STG   (64 * QROW)
#define SV_STG   (128 * VROW)
#define FLASH_SMEM (SQ_BYTES + 3 * SK_STG + 3 * SV_STG)   // 183296

__global__ void __launch_bounds__(256) flash_h(
    const __half* __restrict__ q,
    const __half* __restrict__ kfull,
    const __half* __restrict__ vT,
    __half* __restrict__ oc)
{
    extern __shared__ char sm[];
    char* sQ = sm;
    char* sK = sm + SQ_BYTES;
    char* sV = sK + 3 * SK_STG;

    int qt = blockIdx.x;
    int bh = blockIdx.y;
    int b  = bh >> 4, h = bh & 15;
    int q0 = qt << 7;

    int tid = threadIdx.x, wid = tid >> 5, lane = tid & 31;
    int g = lane >> 2, t4 = lane & 3;
    int j = lane >> 3, r = lane & 7;

    const __half* qg = q     + (size_t)b * S_ * HQK + h * QK_;
    const __half* kg = kfull + (size_t)b * S_ * HQK + h * QK_;
    const __half* vg = vT    + (size_t)bh * VH_ * S_;

    #pragma unroll
    for (int i = 0; i < 12; i++) {
        int idx = tid + 256 * i;
        int row = idx / 24, c = idx % 24;
        cp_async16(sQ + row * QROW + c * 16,
                   (const char*)(qg + (size_t)(q0 + row) * HQK) + c * 16);
    }
    auto load_kv = [&](int st, int kc0) {
        char* k_s = sK + st * SK_STG;
        char* v_s = sV + st * SV_STG;
        #pragma unroll
        for (int i = 0; i < 6; i++) {
            int idx = tid + 256 * i;
            int row = idx / 24, c = idx % 24;
            cp_async16(k_s + row * QROW + c * 16,
                       (const char*)(kg + (size_t)(kc0 + row) * HQK) + c * 16);
        }
        #pragma unroll
        for (int i = 0; i < 4; i++) {
            int idx = tid + 256 * i;
            int row = idx >> 3, c = idx & 7;
            cp_async16(v_s + row * VROW + c * 16,
                       (const char*)(vg + (size_t)row * S_ + kc0) + c * 16);
        }
    };

    load_kv(0, 0);
    cp_commit();
    load_kv(1, 64);
    cp_commit();

    uint32_t sQ_u = (uint32_t)__cvta_generic_to_shared(sQ);
    uint32_t sK_u = (uint32_t)__cvta_generic_to_shared(sK);
    uint32_t sV_u = (uint32_t)__cvta_generic_to_shared(sV);
    uint32_t qoff = sQ_u + (uint32_t)(wid * 16 + (j & 1) * 8 + r) * QROW + (j >> 1) * 16;
    uint32_t koff = (uint32_t)((j >> 1) * 8 + r) * QROW + (j & 1) * 16;
    uint32_t voff = (uint32_t)((j >> 1) * 8 + r) * VROW + (j & 1) * 16;

    cp_wait<1>();
    __syncthreads();
    uint32_t qfr[12][4];
    #pragma unroll
    for (int kk = 0; kk < 12; kk++)
        ldsm4(qfr[kk], qoff + kk * 32);

    float oacc[16][4] = {};
    float m0 = -1e30f, m1 = -1e30f, l0 = 0.f, l1 = 0.f;
    const float K2 = SCALE * 1.4426950408889634f;

    for (int it = 0; it < 32; it++) {
        if (it > 0) {
            cp_wait<1>();
            __syncthreads();
        }
        if (it + 2 < 32) load_kv((it + 2) % 3, (it + 2) * 64);
        cp_commit();

        uint32_t kb = sK_u + (uint32_t)((it % 3) * SK_STG) + koff;
        uint32_t vb = sV_u + (uint32_t)((it % 3) * SV_STG) + voff;

        float sacc[8][4] = {};
        #pragma unroll
        for (int kk = 0; kk < 12; kk++) {
            #pragma unroll
            for (int n2 = 0; n2 < 4; n2++) {
                uint32_t bk[4];
                ldsm4(bk, kb + n2 * (16 * QROW) + kk * 32);
                mma_f16(sacc[2 * n2],     qfr[kk], &bk[0]);
                mma_f16(sacc[2 * n2 + 1], qfr[kk], &bk[2]);
            }
        }

        float mx0 = -1e30f, mx1 = -1e30f;
        #pragma unroll
        for (int nt = 0; nt < 8; nt++) {
            mx0 = fmaxf(mx0, fmaxf(sacc[nt][0], sacc[nt][1]));
            mx1 = fmaxf(mx1, fmaxf(sacc[nt][2], sacc[nt][3]));
        }
        mx0 = fmaxf(mx0, __shfl_xor_sync(0xffffffffu, mx0, 1));
        mx0 = fmaxf(mx0, __shfl_xor_sync(0xffffffffu, mx0, 2));
        mx1 = fmaxf(mx1, __shfl_xor_sync(0xffffffffu, mx1, 1));
        mx1 = fmaxf(mx1, __shfl_xor_sync(0xffffffffu, mx1, 2));
        float mn0 = fmaxf(m0, mx0), mn1 = fmaxf(m1, mx1);
        float rs0 = exp2f((m0 - mn0) * K2), rs1 = exp2f((m1 - mn1) * K2);
        m0 = mn0; m1 = mn1;

        uint32_t p01[8], p23[8];
        float sum0 = 0.f, sum1 = 0.f;
        #pragma unroll
        for (int nt = 0; nt < 8; nt++) {
            __half2 a01 = __floats2half2_rn((sacc[nt][0] - mn0) * K2,
                                            (sacc[nt][1] - mn0) * K2);
            __half2 a23 = __floats2half2_rn((sacc[nt][2] - mn1) * K2,
                                            (sacc[nt][3] - mn1) * K2);
            __half2 e01 = h2exp2(a01);
            __half2 e23 = h2exp2(a23);
            float2 f01 = __half22float2(e01);
            float2 f23 = __half22float2(e23);
            sum0 += f01.x + f01.y;
            sum1 += f23.x + f23.y;
            p01[nt] = *(uint32_t*)&e01;
            p23[nt] = *(uint32_t*)&e23;
        }
        sum0 += __shfl_xor_sync(0xffffffffu, sum0, 1);
        sum0 += __shfl_xor_sync(0xffffffffu, sum0, 2);
        sum1 += __shfl_xor_sync(0xffffffffu, sum1, 1);
        sum1 += __shfl_xor_sync(0xffffffffu, sum1, 2);
        l0 = l0 * rs0 + sum0;
        l1 = l1 * rs1 + sum1;

        #pragma unroll
        for (int nt = 0; nt < 16; nt++) {
            oacc[nt][0] *= rs0; oacc[nt][1] *= rs0;
            oacc[nt][2] *= rs1; oacc[nt][3] *= rs1;
        }

        #pragma unroll
        for (int kk = 0; kk < 4; kk++) {
            uint32_t pa[4] = {p01[2 * kk], p23[2 * kk], p01[2 * kk + 1], p23[2 * kk + 1]};
            #pragma unroll
            for (int n2 = 0; n2 < 8; n2++) {
                uint32_t bv[4];
                ldsm4(bv, vb + n2 * (16 * VROW) + kk * 32);
                mma_f16(oacc[2 * n2],     pa, &bv[0]);
                mma_f16(oacc[2 * n2 + 1], pa, &bv[2]);
            }
        }
    }

    float il0 = 1.f / l0, il1 = 1.f / l1;
    int row = q0 + wid * 16 + g;
    size_t tok0 = (size_t)b * S_ + row;
    __half* o0 = oc + tok0 * (H_ * VH_) + h * VH_;
    __half* o1 = o0 + (size_t)8 * (H_ * VH_);
    #pragma unroll
    for (int nt = 0; nt < 16; nt++) {
        int c = nt * 8 + 2 * t4;
        *(__half2*)&o0[c] = __floats2half2_rn(oacc[nt][0] * il0, oacc[nt][1] * il0);
        *(__half2*)&o1[c] = __floats2half2_rn(oacc[nt][2] * il1, oacc[nt][3] * il1);
    }
}

// =============================================================================
// convall_k: ALL input conversions in one launch, region-dispatched.
// =============================================================================
#define RE0 ((size_t)NT * D_)                  // x -> h_x
#define RE1 (RE0 + (size_t)QL * D_)            // wq_a -> wcat
#define RE2 (RE1 + (size_t)KVP * D_)           // wkv_a (pad) -> wcat+QL*D
#define RE3 (RE2 + (size_t)HQK * QL)           // wq_b -> wqb
#define RE4 (RE3 + (size_t)H_ * 256 * KVL)     // wkv_b -> wkvb
#define RE5 (RE4 + (size_t)D_ * H_ * VH_)      // wo -> wo
#define RE6 (RE5 + NCAT)                       // biases -> biascat
#define KFWD ((size_t)(KVL + ROPE_) * D_)

__device__ __forceinline__ void cvt4(const float* in, __half* out) {
    float4 v = *(const float4*)in;
    __half2* o = (__half2*)out;
    o[0] = __floats2half2_rn(v.x, v.y);
    o[1] = __floats2half2_rn(v.z, v.w);
}

__global__ void convall_k(
    const float* __restrict__ x,     __half* __restrict__ xh,
    const float* __restrict__ wqa,   __half* __restrict__ wcat,
    const float* __restrict__ wkva,
    const float* __restrict__ wqbf,  __half* __restrict__ wqb,
    const float* __restrict__ wkvbf, __half* __restrict__ wkvb,
    const float* __restrict__ wof,   __half* __restrict__ wo,
    const float* __restrict__ qbias, const float* __restrict__ kbias,
    float* __restrict__ bcat)
{
    size_t i = ((size_t)blockIdx.x * 256 + threadIdx.x) * 4;
    if (i >= RE6) return;
    if (i < RE0) {
        cvt4(x + i, xh + i);
    } else if (i < RE1) {
        size_t k = i - RE0;
        cvt4(wqa + k, wcat + k);
    } else if (i < RE2) {
        size_t k = i - RE1;
        __half* dst = wcat + (size_t)QL * D_ + k;
        if (k < KFWD) cvt4(wkva + k, dst);
        else {
            __half2 z = __half2{__half(0.f), __half(0.f)};
            ((__half2*)dst)[0] = z;
            ((__half2*)dst)[1] = z;
        }
    } else if (i < RE3) {
        size_t k = i - RE2;
        cvt4(wqbf + k, wqb + k);
    } else if (i < RE4) {
        size_t k = i - RE3;
        cvt4(wkvbf + k, wkvb + k);
    } else if (i < RE5) {
        size_t k = i - RE4;
        cvt4(wof + k, wo + k);
    } else {
        size_t k = i - RE5;
        #pragma unroll
        for (int m = 0; m < 4; m++) {
            size_t kk = k + m;
            bcat[kk] = (kk < QL) ? qbias[kk]
                     : (kk < QL + KVL + ROPE_) ? kbias[kk - QL] : 0.f;
        }
    }
}

// ---------------- elementwise kernels -----------------------------------------
__global__ void rmsnorm_h(const __half* __restrict__ in, __half* __restrict__ out,
                          const float* __restrict__ w, int width,
                          int inStride, int outStride)
{
    int row = blockIdx.x;
    const __half2* ip = (const __half2*)(in + (size_t)row * inStride);
    __half2*       op = (__half2*)(out + (size_t)row * outStride);
    int w2 = width >> 1;
    float ss = 0.f;
    for (int i = threadIdx.x; i < w2; i += 256) {
        float2 v = __half22float2(ip[i]);
        ss += v.x * v.x + v.y * v.y;
    }
    ss += __shfl_xor_sync(0xffffffffu, ss, 16);
    ss += __shfl_xor_sync(0xffffffffu, ss, 8);
    ss += __shfl_xor_sync(0xffffffffu, ss, 4);
    ss += __shfl_xor_sync(0xffffffffu, ss, 2);
    ss += __shfl_xor_sync(0xffffffffu, ss, 1);
    __shared__ float sm[8];
    if ((threadIdx.x & 31) == 0) sm[threadIdx.x >> 5] = ss;
    __syncthreads();
    float tot = sm[0] + sm[1] + sm[2] + sm[3] + sm[4] + sm[5] + sm[6] + sm[7];
    float rr = rsqrtf(tot / (float)width + 1e-3f);
    for (int i = threadIdx.x; i < w2; i += 256) {
        float2 v = __half22float2(ip[i]);
        op[i] = __floats2half2_rn(w[2 * i] * v.x * rr, w[2 * i + 1] * v.y * rr);
    }
}

__global__ void rope_k_bcast_h(const __half* __restrict__ qakv, __half* __restrict__ kfull,
                               const float* __restrict__ c, const float* __restrict__ s)
{
    int tok = blockIdx.x * 8 + (threadIdx.x >> 5);
    int j = threadIdx.x & 31;
    int pos = tok % S_;
    const __half* src = qakv + (size_t)tok * NCAT + QL + KVL;
    float xr = __half2float(src[2 * j]), xi = __half2float(src[2 * j + 1]);
    float cc = c[pos * 32 + j], sn = s[pos * 32 + j];
    __half2 v;
    v.x = __float2half(xr * cc - xi * sn);
    v.y = __float2half(xr * sn + xi * cc);
    __half* dst = kfull + (size_t)tok * HQK + NOPE_;
    #pragma unroll
    for (int h = 0; h < H_; h++)
        *(__half2*)&dst[h * QK_ + 2 * j] = v;
}

// ---------------- host glue --------------------------------------------------
template<int TN, bool OUTHALF, bool ROPE>
static void launch_h(int M, int N, int K,
                     const __half* A, int lda, long long sAb, long long sAh,
                     const __half* Bp, int ldb, long long sBb, long long sBh,
                     void* C, int ldc, long long sCb, long long sCh,
                     int nb, int nh, float alpha, const float* bias,
                     const float* cosp, const float* sinp)
{
    constexpr int SMEM = (3 * 128 * 20 + 3 * TN * 20) * 4;
    cudaFuncSetAttribute(gemm_h<TN, OUTHALF, ROPE>,
                         cudaFuncAttributeMaxDynamicSharedMemorySize, SMEM);
    dim3 grid(N / TN, M / 128, nb * nh);
    gemm_h<TN, OUTHALF, ROPE><<<grid, TN == 256 ? 256 : 128, SMEM>>>(
        K, A, lda, sAb, sAh, Bp, ldb, sBb, sBh, C, ldc, sCb, sCh, nh, alpha, bias,
        cosp, sinp);
}

extern "C" void kernel_launch(void* const* d_in, const int* in_sizes, int n_in,
                              void* d_out, int out_size)
{
    const float* x        = (const float*)d_in[0];
    const float* cosp     = (const float*)d_in[2];
    const float* sinp     = (const float*)d_in[3];
    const float* wq_a_w   = (const float*)d_in[4];
    const float* wq_a_b   = (const float*)d_in[5];
    const float* q_norm_w = (const float*)d_in[6];
    const float* wq_b_w   = (const float*)d_in[7];
    const float* wq_b_b   = (const float*)d_in[8];
    const float* wkv_a_w  = (const float*)d_in[9];
    const float* wkv_a_b  = (const float*)d_in[10];
    const float* kv_norm_w= (const float*)d_in[11];
    const float* wkv_b_w  = (const float*)d_in[12];
    const float* wo_w     = (const float*)d_in[13];
    const float* wo_b     = (const float*)d_in[14];
    float* out = (float*)d_out;

    __half *xh, *qakv, *qa, *q, *kf, *kfull, *vT, *oc;
    __half *wcat, *wqb, *wkvb, *wo;
    float *bcat;
    cudaGetSymbolAddress((void**)&xh,   h_x);
    cudaGetSymbolAddress((void**)&qakv, h_qakv);
    cudaGetSymbolAddress((void**)&qa,   h_qa);
    cudaGetSymbolAddress((void**)&q,    h_q);
    cudaGetSymbolAddress((void**)&kf,   h_kf);
    cudaGetSymbolAddress((void**)&kfull,h_kfull);
    cudaGetSymbolAddress((void**)&vT,   h_vT);
    cudaGetSymbolAddress((void**)&oc,   h_oc);
    cudaGetSymbolAddress((void**)&wcat, h_wcat);
    cudaGetSymbolAddress((void**)&wqb,  h_wqb);
    cudaGetSymbolAddress((void**)&wkvb, h_wkvb);
    cudaGetSymbolAddress((void**)&wo,   h_wo);
    cudaGetSymbolAddress((void**)&bcat, g_biascat);

    // 0) ALL conversions in one launch
    {
        unsigned grid = (unsigned)((RE6 / 4 + 255) / 256);
        convall_k<<<grid, 256>>>(x, xh, wq_a_w, wcat, wkv_a_w,
                                 wq_b_w, wqb, wkv_b_w, wkvb, wo_w, wo,
                                 wq_a_b, wkv_a_b, bcat);
    }
    // 1) qakv = x @ wcat^T + bcat      [4096,1664] K=2048
    launch_h<128, true, false>(NT, NCAT, D_, xh, D_, 0, 0, wcat, D_, 0, 0,
                               qakv, NCAT, 0, 0, 1, 1, 1.f, bcat, nullptr, nullptr);
    // 2) rmsnorm(q_a)
    rmsnorm_h<<<NT, 256>>>(qakv, qa, q_norm_w, QL, NCAT, QL);
    // 3) q = qa @ wq_b^T + b, rope applied in epilogue   [4096,3072] K=1024
    launch_h<128, true, true>(NT, HQK, QL, qa, QL, 0, 0, wqb, QL, 0, 0,
                              q, HQK, 0, 0, 1, 1, 1.f, wq_b_b, cosp, sinp);
    // 4) kv_c = rmsnorm(qakv[:, 1024:1536])
    rmsnorm_h<<<NT, 256>>>(qakv + QL, kf, kv_norm_w, KVL, NCAT, KVL);
    // 5) kfull[:, h, 128:192] = rope(k_pe) broadcast
    rope_k_bcast_h<<<NT / 8, 256>>>(qakv, kfull, cosp, sinp);
    // 6) dual GEMM: vT (512 blocks) + knope (512 blocks)
    {
        constexpr int SMEM = (3 * 128 * 20 + 3 * 128 * 20) * 4;
        cudaFuncSetAttribute(gemm_dual,
                             cudaFuncAttributeMaxDynamicSharedMemorySize, SMEM);
        gemm_dual<<<1024, 128, SMEM>>>(
            // vT[b,h] = wkvb_v[h] @ kv_c[b]^T   [128,2048] K=512, x=16,z=32
            KVL, wkvb + (size_t)NOPE_ * KVL, KVL, 0, (long long)256 * KVL,
            kf, KVL, (long long)S_ * KVL, 0,
            vT, S_, (long long)H_ * VH_ * S_, (long long)VH_ * S_, H_,
            // kfull[:, h, :128] = kv_c @ wkvb_nope[h]^T  [4096,128] K=512, y=32,z=16
            KVL, kf, KVL, 0, 0,
            wkvb, KVL, 0, (long long)256 * KVL,
            kfull, HQK, 0, QK_, H_);
    }
    // 7) fused attention
    {
        cudaFuncSetAttribute(flash_h, cudaFuncAttributeMaxDynamicSharedMemorySize,
                             FLASH_SMEM);
        dim3 grid(S_ / 128, B_ * H_);
        flash_h<<<grid, 256, FLASH_SMEM>>>(q, kfull, vT, oc);
    }
    // 8) out = oc @ wo^T + b           [4096,2048] K=2048 -> fp32
    launch_h<256, false, false>(NT, D_, H_ * VH_, oc, H_ * VH_, 0, 0, wo, D_, 0, 0,
                                out, D_, 0, 0, 1, 1, 1.f, wo_b, nullptr, nullptr);
}

// round 15
// speedup vs baseline: 2.5063x; 1.0468x over previous
#include <cuda_runtime.h>
#include <cuda_fp16.h>
#include <math.h>
#include <stdint.h>

#define B_    2
#define S_    2048
#define D_    2048
#define H_    16
#define NT    4096
#define QL    1024
#define KVL   512
#define NOPE_ 128
#define ROPE_ 64
#define VH_   128
#define QK_   192
#define KVP   640
#define NCAT  1664
#define HQK   3072
#define SCALE 0.07216878364870322f

// ---------------- scratch ----------------------------------------------------
__device__ __align__(256) __half h_x   [(size_t)NT * D_];
__device__ __align__(256) __half h_qakv[(size_t)NT * NCAT];
__device__ __align__(256) __half h_qa  [(size_t)NT * QL];
__device__ __align__(256) __half h_q   [(size_t)NT * HQK];
__device__ __align__(256) __half h_kf  [(size_t)NT * KVL];
__device__ __align__(256) __half h_kfull[(size_t)NT * HQK];
__device__ __align__(256) __half h_vT  [(size_t)B_ * H_ * VH_ * S_];
__device__ __align__(256) __half h_oc  [(size_t)NT * H_ * VH_];
__device__ __align__(256) __half h_wcat[(size_t)NCAT * D_];
__device__ __align__(256) __half h_wqb [(size_t)HQK * QL];
__device__ __align__(256) __half h_wkvb[(size_t)H_ * 256 * KVL];
__device__ __align__(256) __half h_wo  [(size_t)D_ * H_ * VH_];
__device__ float g_biascat[NCAT];

// ---------------- helpers ---------------------------------------------------
__device__ __forceinline__ void mma_f16(float* c, const uint32_t* a, const uint32_t* b) {
    asm volatile(
        "mma.sync.aligned.m16n8k16.row.col.f32.f16.f16.f32 "
        "{%0,%1,%2,%3},{%4,%5,%6,%7},{%8,%9},{%0,%1,%2,%3};"
        : "+f"(c[0]), "+f"(c[1]), "+f"(c[2]), "+f"(c[3])
        : "r"(a[0]), "r"(a[1]), "r"(a[2]), "r"(a[3]), "r"(b[0]), "r"(b[1]));
}

__device__ __forceinline__ void ldsm4(uint32_t* r, uint32_t saddr) {
    asm volatile(
        "ldmatrix.sync.aligned.m8n8.x4.shared.b16 {%0,%1,%2,%3}, [%4];"
        : "=r"(r[0]), "=r"(r[1]), "=r"(r[2]), "=r"(r[3]) : "r"(saddr));
}

__device__ __forceinline__ void cp_async16(void* smem, const void* gmem) {
    uint32_t s = (uint32_t)__cvta_generic_to_shared(smem);
    asm volatile("cp.async.cg.shared.global [%0], [%1], 16;" :: "r"(s), "l"(gmem));
}
__device__ __forceinline__ void cp_commit() {
    asm volatile("cp.async.commit_group;");
}
template<int N>
__device__ __forceinline__ void cp_wait() {
    asm volatile("cp.async.wait_group %0;" :: "n"(N));
}

// =============================================================================
// gemm_body: fp16 in / fp32 acc. CTA tile 128 x TN, warp 64x64, BK=32,
// 3-stage cp.async, ldmatrix. C = alpha * A @ B^T + bias. ROPE: q epilogue.
// =============================================================================
template<int TN, bool OUTHALF, bool ROPE>
__device__ __forceinline__ void gemm_body(
    int bx, int by, int bz, int K,
    const __half* __restrict__ A, int lda, long long sAb, long long sAh,
    const __half* __restrict__ Bp, int ldb, long long sBb, long long sBh,
    void* __restrict__ Cv, int ldc, long long sCb, long long sCh,
    int ZH, float alpha, const float* __restrict__ bias,
    const float* __restrict__ cosp, const float* __restrict__ sinp,
    uint32_t* smu)
{
    constexpr int T = (TN == 256) ? 256 : 128;
    constexpr int WCOLS = TN / 64;
    constexpr int ASTR = 20;
    constexpr int STGA = 128 * ASTR;
    constexpr int STGB = TN * ASTR;
    constexpr int AITER = 512 / T;
    constexpr int BITER = (TN * 4) / T;

    uint32_t* sA = smu;
    uint32_t* sB = smu + 3 * STGA;

    int zb = bz / ZH;
    int zh = bz - zb * ZH;
    const __half* Ab = A  + zb * sAb + zh * sAh;
    const __half* Bb = Bp + zb * sBb + zh * sBh;

    int row0 = by << 7;
    int col0 = bx * TN;
    int tid  = threadIdx.x;
    int wid  = tid >> 5;
    int lane = tid & 31;
    int wm0 = (wid / WCOLS) << 6;
    int wn0 = (wid % WCOLS) << 6;
    int g = lane >> 2, t4 = lane & 3;
    int j = lane >> 3, r = lane & 7;

    uint32_t sA_u = (uint32_t)__cvta_generic_to_shared(sA);
    uint32_t sB_u = (uint32_t)__cvta_generic_to_shared(sB);
    uint32_t aoff0 = (uint32_t)(wm0 + (j & 1) * 8 + r) * 80 + (uint32_t)(j >> 1) * 16;
    uint32_t boff0 = (uint32_t)(wn0 + (j >> 1) * 8 + r) * 80 + (uint32_t)(j & 1) * 16;

    float acc[4][8][4] = {};

    auto load_stage = [&](int st, int k0) {
        uint32_t* a_s = sA + st * STGA;
        uint32_t* b_s = sB + st * STGB;
        #pragma unroll
        for (int i = 0; i < AITER; i++) {
            int idx = tid + T * i;
            int rr = idx >> 2, q = idx & 3;
            cp_async16(a_s + rr * ASTR + q * 4,
                       Ab + (size_t)(row0 + rr) * lda + k0 + q * 8);
        }
        #pragma unroll
        for (int i = 0; i < BITER; i++) {
            int idx = tid + T * i;
            int rr = idx >> 2, q = idx & 3;
            cp_async16(b_s + rr * ASTR + q * 4,
                       Bb + (size_t)(col0 + rr) * ldb + k0 + q * 8);
        }
    };

    int nk = K / 32;
    load_stage(0, 0);
    cp_commit();
    load_stage(1, 32);
    cp_commit();

    for (int i = 0; i < nk; i++) {
        cp_wait<1>();
        __syncthreads();
        if (i + 2 < nk) load_stage((i + 2) % 3, (i + 2) * 32);
        cp_commit();

        uint32_t abase = sA_u + (uint32_t)((i % 3) * STGA) * 4 + aoff0;
        uint32_t bbase = sB_u + (uint32_t)((i % 3) * STGB) * 4 + boff0;

        #pragma unroll
        for (int kk = 0; kk < 2; kk++) {
            uint32_t afr[4][4], bfr[4][4];
            #pragma unroll
            for (int mt = 0; mt < 4; mt++)
                ldsm4(afr[mt], abase + mt * 1280 + kk * 32);
            #pragma unroll
            for (int nt2 = 0; nt2 < 4; nt2++)
                ldsm4(bfr[nt2], bbase + nt2 * 1280 + kk * 32);
            #pragma unroll
            for (int mt = 0; mt < 4; mt++)
                #pragma unroll
                for (int nt2 = 0; nt2 < 4; nt2++) {
                    mma_f16(acc[mt][2 * nt2],     afr[mt], &bfr[nt2][0]);
                    mma_f16(acc[mt][2 * nt2 + 1], afr[mt], &bfr[nt2][2]);
                }
        }
        __syncthreads();
    }

    size_t coff = (size_t)zb * sCb + (size_t)zh * sCh;
    #pragma unroll
    for (int mt = 0; mt < 4; mt++) {
        int r0 = row0 + wm0 + mt * 16 + g;
        #pragma unroll
        for (int nt = 0; nt < 8; nt++) {
            int c0c = col0 + wn0 + nt * 8 + 2 * t4;
            float b0 = bias ? bias[c0c] : 0.f;
            float b1 = bias ? bias[c0c + 1] : 0.f;
            float v00 = alpha * acc[mt][nt][0] + b0;
            float v01 = alpha * acc[mt][nt][1] + b1;
            float v10 = alpha * acc[mt][nt][2] + b0;
            float v11 = alpha * acc[mt][nt][3] + b1;
            if (ROPE) {
                int hc = c0c % QK_;
                if (hc >= NOPE_) {
                    int jj = (hc - NOPE_) >> 1;
                    int pos0 = r0 & (S_ - 1);
                    int pos1 = (r0 + 8) & (S_ - 1);
                    float c0 = cosp[pos0 * 32 + jj], s0 = sinp[pos0 * 32 + jj];
                    float c1 = cosp[pos1 * 32 + jj], s1 = sinp[pos1 * 32 + jj];
                    float xr = v00, xi = v01;
                    v00 = xr * c0 - xi * s0;
                    v01 = xr * s0 + xi * c0;
                    xr = v10; xi = v11;
                    v10 = xr * c1 - xi * s1;
                    v11 = xr * s1 + xi * c1;
                }
            }
            if (OUTHALF) {
                __half* Ch = (__half*)Cv + coff;
                *(__half2*)&Ch[(size_t)r0 * ldc + c0c]       = __floats2half2_rn(v00, v01);
                *(__half2*)&Ch[(size_t)(r0 + 8) * ldc + c0c] = __floats2half2_rn(v10, v11);
            } else {
                float* Cf = (float*)Cv + coff;
                *(float2*)&Cf[(size_t)r0 * ldc + c0c]       = make_float2(v00, v01);
                *(float2*)&Cf[(size_t)(r0 + 8) * ldc + c0c] = make_float2(v10, v11);
            }
        }
    }
}

template<int TN, bool OUTHALF, bool ROPE>
__global__ void __launch_bounds__(TN == 256 ? 256 : 128) gemm_h(
    int K,
    const __half* __restrict__ A, int lda, long long sAb, long long sAh,
    const __half* __restrict__ Bp, int ldb, long long sBb, long long sBh,
    void* __restrict__ Cv, int ldc, long long sCb, long long sCh,
    int ZH, float alpha, const float* __restrict__ bias,
    const float* __restrict__ cosp, const float* __restrict__ sinp)
{
    extern __shared__ uint32_t smu[];
    gemm_body<TN, OUTHALF, ROPE>(blockIdx.x, blockIdx.y, blockIdx.z, K,
                                 A, lda, sAb, sAh, Bp, ldb, sBb, sBh,
                                 Cv, ldc, sCb, sCh, ZH, alpha, bias,
                                 cosp, sinp, smu);
}

// Mega GEMM: [0,768)=q-proj(+rope); [768,1280)=vT; [1280,1792)=knope.
__global__ void __launch_bounds__(128) gemm_mega(
    const __half* __restrict__ qa,   const __half* __restrict__ wqb,
    __half* __restrict__ q,          const float* __restrict__ biasq,
    const float* __restrict__ cosp,  const float* __restrict__ sinp,
    const __half* __restrict__ wkvb, const __half* __restrict__ kf,
    __half* __restrict__ vT,         __half* __restrict__ kfull)
{
    extern __shared__ uint32_t smu[];
    int bid = blockIdx.x;
    if (bid < 768) {
        gemm_body<128, true, true>(bid % 24, bid / 24, 0, QL,
                                   qa, QL, 0, 0, wqb, QL, 0, 0,
                                   q, HQK, 0, 0, 1, 1.f, biasq, cosp, sinp, smu);
    } else if (bid < 1280) {
        int t = bid - 768;
        gemm_body<128, true, false>(t & 15, 0, t >> 4, KVL,
                                    wkvb + (size_t)NOPE_ * KVL, KVL, 0,
                                    (long long)256 * KVL,
                                    kf, KVL, (long long)S_ * KVL, 0,
                                    vT, S_, (long long)H_ * VH_ * S_,
                                    (long long)VH_ * S_, H_, 1.f, nullptr,
                                    nullptr, nullptr, smu);
    } else {
        int t = bid - 1280;
        gemm_body<128, true, false>(0, t & 31, t >> 5, KVL,
                                    kf, KVL, 0, 0,
                                    wkvb, KVL, 0, (long long)256 * KVL,
                                    kfull, HQK, 0, QK_, H_, 1.f, nullptr,
                                    nullptr, nullptr, smu);
    }
}

// =============================================================================
// flash_h: 64-query CTAs, 128 threads (4 warps x 16 rows), 2-stage K/V,
// 113.7 KB smem -> 2 CTAs/SM. Q register-resident.
// =============================================================================
#define QROW 400
#define VROW 144
#define SQ_BYTES (64 * QROW)        // 25600
#define SK_STG   (64 * QROW)        // 25600
#define SV_STG   (128 * VROW)       // 18432
#define FLASH_SMEM (SQ_BYTES + 2 * SK_STG + 2 * SV_STG)   // 113664

__global__ void __launch_bounds__(128) flash_h(
    const __half* __restrict__ q,
    const __half* __restrict__ kfull,
    const __half* __restrict__ vT,
    __half* __restrict__ oc)
{
    extern __shared__ char sm[];
    char* sQ = sm;
    char* sK = sm + SQ_BYTES;
    char* sV = sK + 2 * SK_STG;

    int qt = blockIdx.x;
    int bh = blockIdx.y;
    int b  = bh >> 4, h = bh & 15;
    int q0 = qt << 6;

    int tid = threadIdx.x, wid = tid >> 5, lane = tid & 31;
    int g = lane >> 2, t4 = lane & 3;
    int j = lane >> 3, r = lane & 7;

    const __half* qg = q     + (size_t)b * S_ * HQK + h * QK_;
    const __half* kg = kfull + (size_t)b * S_ * HQK + h * QK_;
    const __half* vg = vT    + (size_t)bh * VH_ * S_;

    // Q tile: 64 rows x 24 16B-chunks = 1536 / 128 thr = 12 iters
    #pragma unroll
    for (int i = 0; i < 12; i++) {
        int idx = tid + 128 * i;
        int row = idx / 24, c = idx % 24;
        cp_async16(sQ + row * QROW + c * 16,
                   (const char*)(qg + (size_t)(q0 + row) * HQK) + c * 16);
    }
    auto load_kv = [&](int st, int kc0) {
        char* k_s = sK + st * SK_STG;
        char* v_s = sV + st * SV_STG;
        #pragma unroll
        for (int i = 0; i < 12; i++) {
            int idx = tid + 128 * i;
            int row = idx / 24, c = idx % 24;
            cp_async16(k_s + row * QROW + c * 16,
                       (const char*)(kg + (size_t)(kc0 + row) * HQK) + c * 16);
        }
        #pragma unroll
        for (int i = 0; i < 8; i++) {
            int idx = tid + 128 * i;
            int row = idx >> 3, c = idx & 7;
            cp_async16(v_s + row * VROW + c * 16,
                       (const char*)(vg + (size_t)row * S_ + kc0) + c * 16);
        }
    };

    load_kv(0, 0);
    cp_commit();          // g0: Q + KV0
    load_kv(1, 64);
    cp_commit();          // g1: KV1

    uint32_t sQ_u = (uint32_t)__cvta_generic_to_shared(sQ);
    uint32_t sK_u = (uint32_t)__cvta_generic_to_shared(sK);
    uint32_t sV_u = (uint32_t)__cvta_generic_to_shared(sV);
    uint32_t qoff = sQ_u + (uint32_t)(wid * 16 + (j & 1) * 8 + r) * QROW + (j >> 1) * 16;
    uint32_t koff = (uint32_t)((j >> 1) * 8 + r) * QROW + (j & 1) * 16;
    uint32_t voff = (uint32_t)((j >> 1) * 8 + r) * VROW + (j & 1) * 16;

    cp_wait<1>();
    __syncthreads();
    uint32_t qfr[12][4];
    #pragma unroll
    for (int kk = 0; kk < 12; kk++)
        ldsm4(qfr[kk], qoff + kk * 32);

    float oacc[16][4] = {};
    float m0 = -1e30f, m1 = -1e30f, l0 = 0.f, l1 = 0.f;
    const float K2 = SCALE * 1.4426950408889634f;

    for (int it = 0; it < 32; it++) {
        if (it > 0) {
            cp_wait<1>();
            __syncthreads();
        }
        int st = it & 1;
        uint32_t kb = sK_u + (uint32_t)(st * SK_STG) + koff;
        uint32_t vb = sV_u + (uint32_t)(st * SV_STG) + voff;

        // ---- S = Q @ K^T ----
        float sacc[8][4] = {};
        #pragma unroll
        for (int kk = 0; kk < 12; kk++) {
            #pragma unroll
            for (int n2 = 0; n2 < 4; n2++) {
                uint32_t bk[4];
                ldsm4(bk, kb + n2 * (16 * QROW) + kk * 32);
                mma_f16(sacc[2 * n2],     qfr[kk], &bk[0]);
                mma_f16(sacc[2 * n2 + 1], qfr[kk], &bk[2]);
            }
        }

        // ---- online softmax ----
        float mx0 = -1e30f, mx1 = -1e30f;
        #pragma unroll
        for (int nt = 0; nt < 8; nt++) {
            mx0 = fmaxf(mx0, fmaxf(sacc[nt][0], sacc[nt][1]));
            mx1 = fmaxf(mx1, fmaxf(sacc[nt][2], sacc[nt][3]));
        }
        mx0 = fmaxf(mx0, __shfl_xor_sync(0xffffffffu, mx0, 1));
        mx0 = fmaxf(mx0, __shfl_xor_sync(0xffffffffu, mx0, 2));
        mx1 = fmaxf(mx1, __shfl_xor_sync(0xffffffffu, mx1, 1));
        mx1 = fmaxf(mx1, __shfl_xor_sync(0xffffffffu, mx1, 2));
        float mn0 = fmaxf(m0, mx0), mn1 = fmaxf(m1, mx1);
        float rs0 = exp2f((m0 - mn0) * K2), rs1 = exp2f((m1 - mn1) * K2);
        m0 = mn0; m1 = mn1;

        uint32_t p01[8], p23[8];
        float sum0 = 0.f, sum1 = 0.f;
        #pragma unroll
        for (int nt = 0; nt < 8; nt++) {
            __half2 a01 = __floats2half2_rn((sacc[nt][0] - mn0) * K2,
                                            (sacc[nt][1] - mn0) * K2);
            __half2 a23 = __floats2half2_rn((sacc[nt][2] - mn1) * K2,
                                            (sacc[nt][3] - mn1) * K2);
            __half2 e01 = h2exp2(a01);
            __half2 e23 = h2exp2(a23);
            float2 f01 = __half22float2(e01);
            float2 f23 = __half22float2(e23);
            sum0 += f01.x + f01.y;
            sum1 += f23.x + f23.y;
            p01[nt] = *(uint32_t*)&e01;
            p23[nt] = *(uint32_t*)&e23;
        }
        sum0 += __shfl_xor_sync(0xffffffffu, sum0, 1);
        sum0 += __shfl_xor_sync(0xffffffffu, sum0, 2);
        sum1 += __shfl_xor_sync(0xffffffffu, sum1, 1);
        sum1 += __shfl_xor_sync(0xffffffffu, sum1, 2);
        l0 = l0 * rs0 + sum0;
        l1 = l1 * rs1 + sum1;

        #pragma unroll
        for (int nt = 0; nt < 16; nt++) {
            oacc[nt][0] *= rs0; oacc[nt][1] *= rs0;
            oacc[nt][2] *= rs1; oacc[nt][3] *= rs1;
        }

        // ---- O += P @ V ----
        #pragma unroll
        for (int kk = 0; kk < 4; kk++) {
            uint32_t pa[4] = {p01[2 * kk], p23[2 * kk], p01[2 * kk + 1], p23[2 * kk + 1]};
            #pragma unroll
            for (int n2 = 0; n2 < 8; n2++) {
                uint32_t bv[4];
                ldsm4(bv, vb + n2 * (16 * VROW) + kk * 32);
                mma_f16(oacc[2 * n2],     pa, &bv[0]);
                mma_f16(oacc[2 * n2 + 1], pa, &bv[2]);
            }
        }

        // free stage st, refill with it+2
        __syncthreads();
        if (it + 2 < 32) load_kv(st, (it + 2) * 64);
        cp_commit();
    }

    float il0 = 1.f / l0, il1 = 1.f / l1;
    int row = q0 + wid * 16 + g;
    size_t tok0 = (size_t)b * S_ + row;
    __half* o0 = oc + tok0 * (H_ * VH_) + h * VH_;
    __half* o1 = o0 + (size_t)8 * (H_ * VH_);
    #pragma unroll
    for (int nt = 0; nt < 16; nt++) {
        int c = nt * 8 + 2 * t4;
        *(__half2*)&o0[c] = __floats2half2_rn(oacc[nt][0] * il0, oacc[nt][1] * il0);
        *(__half2*)&o1[c] = __floats2half2_rn(oacc[nt][2] * il1, oacc[nt][3] * il1);
    }
}

// =============================================================================
// convall_k: ALL input conversions in one launch.
// =============================================================================
#define RE0 ((size_t)NT * D_)
#define RE1 (RE0 + (size_t)QL * D_)
#define RE2 (RE1 + (size_t)KVP * D_)
#define RE3 (RE2 + (size_t)HQK * QL)
#define RE4 (RE3 + (size_t)H_ * 256 * KVL)
#define RE5 (RE4 + (size_t)D_ * H_ * VH_)
#define RE6 (RE5 + NCAT)
#define KFWD ((size_t)(KVL + ROPE_) * D_)

__device__ __forceinline__ void cvt4(const float* in, __half* out) {
    float4 v = *(const float4*)in;
    __half2* o = (__half2*)out;
    o[0] = __floats2half2_rn(v.x, v.y);
    o[1] = __floats2half2_rn(v.z, v.w);
}

__global__ void convall_k(
    const float* __restrict__ x,     __half* __restrict__ xh,
    const float* __restrict__ wqa,   __half* __restrict__ wcat,
    const float* __restrict__ wkva,
    const float* __restrict__ wqbf,  __half* __restrict__ wqb,
    const float* __restrict__ wkvbf, __half* __restrict__ wkvb,
    const float* __restrict__ wof,   __half* __restrict__ wo,
    const float* __restrict__ qbias, const float* __restrict__ kbias,
    float* __restrict__ bcat)
{
    size_t i = ((size_t)blockIdx.x * 256 + threadIdx.x) * 4;
    if (i >= RE6) return;
    if (i < RE0) {
        cvt4(x + i, xh + i);
    } else if (i < RE1) {
        size_t k = i - RE0;
        cvt4(wqa + k, wcat + k);
    } else if (i < RE2) {
        size_t k = i - RE1;
        __half* dst = wcat + (size_t)QL * D_ + k;
        if (k < KFWD) cvt4(wkva + k, dst);
        else {
            __half2 z = __half2{__half(0.f), __half(0.f)};
            ((__half2*)dst)[0] = z;
            ((__half2*)dst)[1] = z;
        }
    } else if (i < RE3) {
        size_t k = i - RE2;
        cvt4(wqbf + k, wqb + k);
    } else if (i < RE4) {
        size_t k = i - RE3;
        cvt4(wkvbf + k, wkvb + k);
    } else if (i < RE5) {
        size_t k = i - RE4;
        cvt4(wof + k, wo + k);
    } else {
        size_t k = i - RE5;
        #pragma unroll
        for (int m = 0; m < 4; m++) {
            size_t kk = k + m;
            bcat[kk] = (kk < QL) ? qbias[kk]
                     : (kk < QL + KVL + ROPE_) ? kbias[kk - QL] : 0.f;
        }
    }
}

// =============================================================================
// elem_k: rmsnorm_q (blocks [0,4096)) + rmsnorm_kv ([4096,8192)) +
//         rope_k_bcast ([8192,8704), 8 tokens/block).
// =============================================================================
__device__ __forceinline__ void rms_body(const __half* ip_, __half* op_,
                                         const float* w, int width)
{
    const __half2* ip = (const __half2*)ip_;
    __half2* op = (__half2*)op_;
    int w2 = width >> 1;
    float ss = 0.f;
    for (int i = threadIdx.x; i < w2; i += 256) {
        float2 v = __half22float2(ip[i]);
        ss += v.x * v.x + v.y * v.y;
    }
    ss += __shfl_xor_sync(0xffffffffu, ss, 16);
    ss += __shfl_xor_sync(0xffffffffu, ss, 8);
    ss += __shfl_xor_sync(0xffffffffu, ss, 4);
    ss += __shfl_xor_sync(0xffffffffu, ss, 2);
    ss += __shfl_xor_sync(0xffffffffu, ss, 1);
    __shared__ float sm[8];
    if ((threadIdx.x & 31) == 0) sm[threadIdx.x >> 5] = ss;
    __syncthreads();
    float tot = sm[0] + sm[1] + sm[2] + sm[3] + sm[4] + sm[5] + sm[6] + sm[7];
    float rr = rsqrtf(tot / (float)width + 1e-3f);
    for (int i = threadIdx.x; i < w2; i += 256) {
        float2 v = __half22float2(ip[i]);
        op[i] = __floats2half2_rn(w[2 * i] * v.x * rr, w[2 * i + 1] * v.y * rr);
    }
}

__global__ void elem_k(const __half* __restrict__ qakv,
                       __half* __restrict__ qa, __half* __restrict__ kf,
                       __half* __restrict__ kfull,
                       const float* __restrict__ qw, const float* __restrict__ kvw,
                       const float* __restrict__ c, const float* __restrict__ s)
{
    int bid = blockIdx.x;
    if (bid < NT) {
        rms_body(qakv + (size_t)bid * NCAT, qa + (size_t)bid * QL, qw, QL);
    } else if (bid < 2 * NT) {
        int row = bid - NT;
        rms_body(qakv + (size_t)row * NCAT + QL, kf + (size_t)row * KVL, kvw, KVL);
    } else {
        int tok = (bid - 2 * NT) * 8 + (threadIdx.x >> 5);
        int j = threadIdx.x & 31;
        int pos = tok % S_;
        const __half* src = qakv + (size_t)tok * NCAT + QL + KVL;
        float xr = __half2float(src[2 * j]), xi = __half2float(src[2 * j + 1]);
        float cc = c[pos * 32 + j], sn = s[pos * 32 + j];
        __half2 v;
        v.x = __float2half(xr * cc - xi * sn);
        v.y = __float2half(xr * sn + xi * cc);
        __half* dst = kfull + (size_t)tok * HQK + NOPE_;
        #pragma unroll
        for (int h = 0; h < H_; h++)
            *(__half2*)&dst[h * QK_ + 2 * j] = v;
    }
}

// ---------------- host glue --------------------------------------------------
template<int TN, bool OUTHALF, bool ROPE>
static void launch_h(int M, int N, int K,
                     const __half* A, int lda, long long sAb, long long sAh,
                     const __half* Bp, int ldb, long long sBb, long long sBh,
                     void* C, int ldc, long long sCb, long long sCh,
                     int nb, int nh, float alpha, const float* bias,
                     const float* cosp, const float* sinp)
{
    constexpr int SMEM = (3 * 128 * 20 + 3 * TN * 20) * 4;
    cudaFuncSetAttribute(gemm_h<TN, OUTHALF, ROPE>,
                         cudaFuncAttributeMaxDynamicSharedMemorySize, SMEM);
    dim3 grid(N / TN, M / 128, nb * nh);
    gemm_h<TN, OUTHALF, ROPE><<<grid, TN == 256 ? 256 : 128, SMEM>>>(
        K, A, lda, sAb, sAh, Bp, ldb, sBb, sBh, C, ldc, sCb, sCh, nh, alpha, bias,
        cosp, sinp);
}

extern "C" void kernel_launch(void* const* d_in, const int* in_sizes, int n_in,
                              void* d_out, int out_size)
{
    const float* x        = (const float*)d_in[0];
    const float* cosp     = (const float*)d_in[2];
    const float* sinp     = (const float*)d_in[3];
    const float* wq_a_w   = (const float*)d_in[4];
    const float* wq_a_b   = (const float*)d_in[5];
    const float* q_norm_w = (const float*)d_in[6];
    const float* wq_b_w   = (const float*)d_in[7];
    const float* wq_b_b   = (const float*)d_in[8];
    const float* wkv_a_w  = (const float*)d_in[9];
    const float* wkv_a_b  = (const float*)d_in[10];
    const float* kv_norm_w= (const float*)d_in[11];
    const float* wkv_b_w  = (const float*)d_in[12];
    const float* wo_w     = (const float*)d_in[13];
    const float* wo_b     = (const float*)d_in[14];
    float* out = (float*)d_out;

    __half *xh, *qakv, *qa, *q, *kf, *kfull, *vT, *oc;
    __half *wcat, *wqb, *wkvb, *wo;
    float *bcat;
    cudaGetSymbolAddress((void**)&xh,   h_x);
    cudaGetSymbolAddress((void**)&qakv, h_qakv);
    cudaGetSymbolAddress((void**)&qa,   h_qa);
    cudaGetSymbolAddress((void**)&q,    h_q);
    cudaGetSymbolAddress((void**)&kf,   h_kf);
    cudaGetSymbolAddress((void**)&kfull,h_kfull);
    cudaGetSymbolAddress((void**)&vT,   h_vT);
    cudaGetSymbolAddress((void**)&oc,   h_oc);
    cudaGetSymbolAddress((void**)&wcat, h_wcat);
    cudaGetSymbolAddress((void**)&wqb,  h_wqb);
    cudaGetSymbolAddress((void**)&wkvb, h_wkvb);
    cudaGetSymbolAddress((void**)&wo,   h_wo);
    cudaGetSymbolAddress((void**)&bcat, g_biascat);

    // 0) ALL conversions
    {
        unsigned grid = (unsigned)((RE6 / 4 + 255) / 256);
        convall_k<<<grid, 256>>>(x, xh, wq_a_w, wcat, wkv_a_w,
                                 wq_b_w, wqb, wkv_b_w, wkvb, wo_w, wo,
                                 wq_a_b, wkv_a_b, bcat);
    }
    // 1) qakv = x @ wcat^T + bcat      [4096,1664] K=2048
    launch_h<128, true, false>(NT, NCAT, D_, xh, D_, 0, 0, wcat, D_, 0, 0,
                               qakv, NCAT, 0, 0, 1, 1, 1.f, bcat, nullptr, nullptr);
    // 2) merged elementwise: rmsnorm_q + rmsnorm_kv + rope_k_bcast
    elem_k<<<2 * NT + NT / 8, 256>>>(qakv, qa, kf, kfull, q_norm_w, kv_norm_w,
                                     cosp, sinp);
    // 3) mega GEMM: q-proj(+rope) + vT + knope  (1792 CTAs)
    {
        constexpr int SMEM = (3 * 128 * 20 + 3 * 128 * 20) * 4;
        cudaFuncSetAttribute(gemm_mega,
                             cudaFuncAttributeMaxDynamicSharedMemorySize, SMEM);
        gemm_mega<<<1792, 128, SMEM>>>(qa, wqb, q, wq_b_b, cosp, sinp,
                                       wkvb, kf, vT, kfull);
    }
    // 4) fused attention (2 CTAs/SM)
    {
        cudaFuncSetAttribute(flash_h, cudaFuncAttributeMaxDynamicSharedMemorySize,
                             FLASH_SMEM);
        dim3 grid(S_ / 64, B_ * H_);
        flash_h<<<grid, 128, FLASH_SMEM>>>(q, kfull, vT, oc);
    }
    // 5) out = oc @ wo^T + b           [4096,2048] K=2048 -> fp32
    launch_h<256, false, false>(NT, D_, H_ * VH_, oc, H_ * VH_, 0, 0, wo, D_, 0, 0,
                                out, D_, 0, 0, 1, 1, 1.f, wo_b, nullptr, nullptr);
}

// round 16
// speedup vs baseline: 2.5159x; 1.0038x over previous
#include <cuda_runtime.h>
#include <cuda_fp16.h>
#include <math.h>
#include <stdint.h>

#define B_    2
#define S_    2048
#define D_    2048
#define H_    16
#define NT    4096
#define QL    1024
#define KVL   512
#define NOPE_ 128
#define ROPE_ 64
#define VH_   128
#define QK_   192
#define KVP   640
#define NCAT  1664
#define HQK   3072
#define SCALE 0.07216878364870322f

// ---------------- scratch ----------------------------------------------------
__device__ __align__(256) __half h_x   [(size_t)NT * D_];
__device__ __align__(256) __half h_qakv[(size_t)NT * NCAT];
__device__ __align__(256) __half h_qa  [(size_t)NT * QL];
__device__ __align__(256) __half h_q   [(size_t)NT * HQK];
__device__ __align__(256) __half h_kf  [(size_t)NT * KVL];
__device__ __align__(256) __half h_kfull[(size_t)NT * HQK];
__device__ __align__(256) __half h_vT  [(size_t)B_ * H_ * VH_ * S_];
__device__ __align__(256) __half h_oc  [(size_t)NT * H_ * VH_];
__device__ __align__(256) __half h_wcat[(size_t)NCAT * D_];
__device__ __align__(256) __half h_wqb [(size_t)HQK * QL];
__device__ __align__(256) __half h_wkvb[(size_t)H_ * 256 * KVL];
__device__ __align__(256) __half h_wo  [(size_t)D_ * H_ * VH_];
__device__ float g_biascat[NCAT];

// ---------------- helpers ---------------------------------------------------
__device__ __forceinline__ void mma_f16(float* c, const uint32_t* a, const uint32_t* b) {
    asm volatile(
        "mma.sync.aligned.m16n8k16.row.col.f32.f16.f16.f32 "
        "{%0,%1,%2,%3},{%4,%5,%6,%7},{%8,%9},{%0,%1,%2,%3};"
        : "+f"(c[0]), "+f"(c[1]), "+f"(c[2]), "+f"(c[3])
        : "r"(a[0]), "r"(a[1]), "r"(a[2]), "r"(a[3]), "r"(b[0]), "r"(b[1]));
}

__device__ __forceinline__ void ldsm4(uint32_t* r, uint32_t saddr) {
    asm volatile(
        "ldmatrix.sync.aligned.m8n8.x4.shared.b16 {%0,%1,%2,%3}, [%4];"
        : "=r"(r[0]), "=r"(r[1]), "=r"(r[2]), "=r"(r[3]) : "r"(saddr));
}

__device__ __forceinline__ void cp_async16(void* smem, const void* gmem) {
    uint32_t s = (uint32_t)__cvta_generic_to_shared(smem);
    asm volatile("cp.async.cg.shared.global [%0], [%1], 16;" :: "r"(s), "l"(gmem));
}
__device__ __forceinline__ void cp_commit() {
    asm volatile("cp.async.commit_group;");
}
template<int N>
__device__ __forceinline__ void cp_wait() {
    asm volatile("cp.async.wait_group %0;" :: "n"(N));
}

// =============================================================================
// gemm_body: fp16 in / fp32 acc. CTA tile 128 x TN, warp 64x64, BK=32,
// 3-stage cp.async. All 16 LDSM issued before the 32 MMAs per K-tile;
// single barrier per K-tile (top-of-loop barrier protects the 3-stage ring).
// =============================================================================
template<int TN, bool OUTHALF, bool ROPE>
__device__ __forceinline__ void gemm_body(
    int bx, int by, int bz, int K,
    const __half* __restrict__ A, int lda, long long sAb, long long sAh,
    const __half* __restrict__ Bp, int ldb, long long sBb, long long sBh,
    void* __restrict__ Cv, int ldc, long long sCb, long long sCh,
    int ZH, float alpha, const float* __restrict__ bias,
    const float* __restrict__ cosp, const float* __restrict__ sinp,
    uint32_t* smu)
{
    constexpr int T = (TN == 256) ? 256 : 128;
    constexpr int WCOLS = TN / 64;
    constexpr int ASTR = 20;
    constexpr int STGA = 128 * ASTR;
    constexpr int STGB = TN * ASTR;
    constexpr int AITER = 512 / T;
    constexpr int BITER = (TN * 4) / T;

    uint32_t* sA = smu;
    uint32_t* sB = smu + 3 * STGA;

    int zb = bz / ZH;
    int zh = bz - zb * ZH;
    const __half* Ab = A  + zb * sAb + zh * sAh;
    const __half* Bb = Bp + zb * sBb + zh * sBh;

    int row0 = by << 7;
    int col0 = bx * TN;
    int tid  = threadIdx.x;
    int wid  = tid >> 5;
    int lane = tid & 31;
    int wm0 = (wid / WCOLS) << 6;
    int wn0 = (wid % WCOLS) << 6;
    int g = lane >> 2, t4 = lane & 3;
    int j = lane >> 3, r = lane & 7;

    uint32_t sA_u = (uint32_t)__cvta_generic_to_shared(sA);
    uint32_t sB_u = (uint32_t)__cvta_generic_to_shared(sB);
    uint32_t aoff0 = (uint32_t)(wm0 + (j & 1) * 8 + r) * 80 + (uint32_t)(j >> 1) * 16;
    uint32_t boff0 = (uint32_t)(wn0 + (j >> 1) * 8 + r) * 80 + (uint32_t)(j & 1) * 16;

    float acc[4][8][4] = {};

    auto load_stage = [&](int st, int k0) {
        uint32_t* a_s = sA + st * STGA;
        uint32_t* b_s = sB + st * STGB;
        #pragma unroll
        for (int i = 0; i < AITER; i++) {
            int idx = tid + T * i;
            int rr = idx >> 2, q = idx & 3;
            cp_async16(a_s + rr * ASTR + q * 4,
                       Ab + (size_t)(row0 + rr) * lda + k0 + q * 8);
        }
        #pragma unroll
        for (int i = 0; i < BITER; i++) {
            int idx = tid + T * i;
            int rr = idx >> 2, q = idx & 3;
            cp_async16(b_s + rr * ASTR + q * 4,
                       Bb + (size_t)(col0 + rr) * ldb + k0 + q * 8);
        }
    };

    int nk = K / 32;
    load_stage(0, 0);
    cp_commit();
    load_stage(1, 32);
    cp_commit();

    for (int i = 0; i < nk; i++) {
        cp_wait<1>();
        __syncthreads();
        // stage (i+2)%3 == (i-1)%3 was consumed in iteration i-1; the barrier
        // above guarantees all warps finished it -> safe to overwrite now.
        if (i + 2 < nk) load_stage((i + 2) % 3, (i + 2) * 32);
        cp_commit();

        uint32_t abase = sA_u + (uint32_t)((i % 3) * STGA) * 4 + aoff0;
        uint32_t bbase = sB_u + (uint32_t)((i % 3) * STGB) * 4 + boff0;

        // batch ALL fragment loads (both kk steps) so LDSM latencies overlap,
        // then run all 32 MMAs back-to-back.
        uint32_t afr[2][4][4], bfr[2][4][4];
        #pragma unroll
        for (int kk = 0; kk < 2; kk++) {
            #pragma unroll
            for (int mt = 0; mt < 4; mt++)
                ldsm4(afr[kk][mt], abase + mt * 1280 + kk * 32);
            #pragma unroll
            for (int nt2 = 0; nt2 < 4; nt2++)
                ldsm4(bfr[kk][nt2], bbase + nt2 * 1280 + kk * 32);
        }
        #pragma unroll
        for (int kk = 0; kk < 2; kk++)
            #pragma unroll
            for (int mt = 0; mt < 4; mt++)
                #pragma unroll
                for (int nt2 = 0; nt2 < 4; nt2++) {
                    mma_f16(acc[mt][2 * nt2],     afr[kk][mt], &bfr[kk][nt2][0]);
                    mma_f16(acc[mt][2 * nt2 + 1], afr[kk][mt], &bfr[kk][nt2][2]);
                }
    }

    size_t coff = (size_t)zb * sCb + (size_t)zh * sCh;
    #pragma unroll
    for (int mt = 0; mt < 4; mt++) {
        int r0 = row0 + wm0 + mt * 16 + g;
        #pragma unroll
        for (int nt = 0; nt < 8; nt++) {
            int c0c = col0 + wn0 + nt * 8 + 2 * t4;
            float b0 = bias ? bias[c0c] : 0.f;
            float b1 = bias ? bias[c0c + 1] : 0.f;
            float v00 = alpha * acc[mt][nt][0] + b0;
            float v01 = alpha * acc[mt][nt][1] + b1;
            float v10 = alpha * acc[mt][nt][2] + b0;
            float v11 = alpha * acc[mt][nt][3] + b1;
            if (ROPE) {
                int hc = c0c % QK_;
                if (hc >= NOPE_) {
                    int jj = (hc - NOPE_) >> 1;
                    int pos0 = r0 & (S_ - 1);
                    int pos1 = (r0 + 8) & (S_ - 1);
                    float c0 = cosp[pos0 * 32 + jj], s0 = sinp[pos0 * 32 + jj];
                    float c1 = cosp[pos1 * 32 + jj], s1 = sinp[pos1 * 32 + jj];
                    float xr = v00, xi = v01;
                    v00 = xr * c0 - xi * s0;
                    v01 = xr * s0 + xi * c0;
                    xr = v10; xi = v11;
                    v10 = xr * c1 - xi * s1;
                    v11 = xr * s1 + xi * c1;
                }
            }
            if (OUTHALF) {
                __half* Ch = (__half*)Cv + coff;
                *(__half2*)&Ch[(size_t)r0 * ldc + c0c]       = __floats2half2_rn(v00, v01);
                *(__half2*)&Ch[(size_t)(r0 + 8) * ldc + c0c] = __floats2half2_rn(v10, v11);
            } else {
                float* Cf = (float*)Cv + coff;
                *(float2*)&Cf[(size_t)r0 * ldc + c0c]       = make_float2(v00, v01);
                *(float2*)&Cf[(size_t)(r0 + 8) * ldc + c0c] = make_float2(v10, v11);
            }
        }
    }
}

template<int TN, bool OUTHALF, bool ROPE>
__global__ void __launch_bounds__(TN == 256 ? 256 : 128) gemm_h(
    int K,
    const __half* __restrict__ A, int lda, long long sAb, long long sAh,
    const __half* __restrict__ Bp, int ldb, long long sBb, long long sBh,
    void* __restrict__ Cv, int ldc, long long sCb, long long sCh,
    int ZH, float alpha, const float* __restrict__ bias,
    const float* __restrict__ cosp, const float* __restrict__ sinp)
{
    extern __shared__ uint32_t smu[];
    gemm_body<TN, OUTHALF, ROPE>(blockIdx.x, blockIdx.y, blockIdx.z, K,
                                 A, lda, sAb, sAh, Bp, ldb, sBb, sBh,
                                 Cv, ldc, sCb, sCh, ZH, alpha, bias,
                                 cosp, sinp, smu);
}

// Mega GEMM: [0,768)=q-proj(+rope); [768,1280)=vT; [1280,1792)=knope.
__global__ void __launch_bounds__(128) gemm_mega(
    const __half* __restrict__ qa,   const __half* __restrict__ wqb,
    __half* __restrict__ q,          const float* __restrict__ biasq,
    const float* __restrict__ cosp,  const float* __restrict__ sinp,
    const __half* __restrict__ wkvb, const __half* __restrict__ kf,
    __half* __restrict__ vT,         __half* __restrict__ kfull)
{
    extern __shared__ uint32_t smu[];
    int bid = blockIdx.x;
    if (bid < 768) {
        gemm_body<128, true, true>(bid % 24, bid / 24, 0, QL,
                                   qa, QL, 0, 0, wqb, QL, 0, 0,
                                   q, HQK, 0, 0, 1, 1.f, biasq, cosp, sinp, smu);
    } else if (bid < 1280) {
        int t = bid - 768;
        gemm_body<128, true, false>(t & 15, 0, t >> 4, KVL,
                                    wkvb + (size_t)NOPE_ * KVL, KVL, 0,
                                    (long long)256 * KVL,
                                    kf, KVL, (long long)S_ * KVL, 0,
                                    vT, S_, (long long)H_ * VH_ * S_,
                                    (long long)VH_ * S_, H_, 1.f, nullptr,
                                    nullptr, nullptr, smu);
    } else {
        int t = bid - 1280;
        gemm_body<128, true, false>(0, t & 31, t >> 5, KVL,
                                    kf, KVL, 0, 0,
                                    wkvb, KVL, 0, (long long)256 * KVL,
                                    kfull, HQK, 0, QK_, H_, 1.f, nullptr,
                                    nullptr, nullptr, smu);
    }
}

// =============================================================================
// flash_h: 64-query CTAs, 128 threads (4 warps x 16 rows), 2-stage K/V,
// 113.7 KB smem -> 2 CTAs/SM. Q register-resident.
// =============================================================================
#define QROW 400
#define VROW 144
#define SQ_BYTES (64 * QROW)
#define SK_STG   (64 * QROW)
#define SV_STG   (128 * VROW)
#define FLASH_SMEM (SQ_BYTES + 2 * SK_STG + 2 * SV_STG)   // 113664

__global__ void __launch_bounds__(128) flash_h(
    const __half* __restrict__ q,
    const __half* __restrict__ kfull,
    const __half* __restrict__ vT,
    __half* __restrict__ oc)
{
    extern __shared__ char sm[];
    char* sQ = sm;
    char* sK = sm + SQ_BYTES;
    char* sV = sK + 2 * SK_STG;

    int qt = blockIdx.x;
    int bh = blockIdx.y;
    int b  = bh >> 4, h = bh & 15;
    int q0 = qt << 6;

    int tid = threadIdx.x, wid = tid >> 5, lane = tid & 31;
    int g = lane >> 2, t4 = lane & 3;
    int j = lane >> 3, r = lane & 7;

    const __half* qg = q     + (size_t)b * S_ * HQK + h * QK_;
    const __half* kg = kfull + (size_t)b * S_ * HQK + h * QK_;
    const __half* vg = vT    + (size_t)bh * VH_ * S_;

    #pragma unroll
    for (int i = 0; i < 12; i++) {
        int idx = tid + 128 * i;
        int row = idx / 24, c = idx % 24;
        cp_async16(sQ + row * QROW + c * 16,
                   (const char*)(qg + (size_t)(q0 + row) * HQK) + c * 16);
    }
    auto load_kv = [&](int st, int kc0) {
        char* k_s = sK + st * SK_STG;
        char* v_s = sV + st * SV_STG;
        #pragma unroll
        for (int i = 0; i < 12; i++) {
            int idx = tid + 128 * i;
            int row = idx / 24, c = idx % 24;
            cp_async16(k_s + row * QROW + c * 16,
                       (const char*)(kg + (size_t)(kc0 + row) * HQK) + c * 16);
        }
        #pragma unroll
        for (int i = 0; i < 8; i++) {
            int idx = tid + 128 * i;
            int row = idx >> 3, c = idx & 7;
            cp_async16(v_s + row * VROW + c * 16,
                       (const char*)(vg + (size_t)row * S_ + kc0) + c * 16);
        }
    };

    load_kv(0, 0);
    cp_commit();
    load_kv(1, 64);
    cp_commit();

    uint32_t sQ_u = (uint32_t)__cvta_generic_to_shared(sQ);
    uint32_t sK_u = (uint32_t)__cvta_generic_to_shared(sK);
    uint32_t sV_u = (uint32_t)__cvta_generic_to_shared(sV);
    uint32_t qoff = sQ_u + (uint32_t)(wid * 16 + (j & 1) * 8 + r) * QROW + (j >> 1) * 16;
    uint32_t koff = (uint32_t)((j >> 1) * 8 + r) * QROW + (j & 1) * 16;
    uint32_t voff = (uint32_t)((j >> 1) * 8 + r) * VROW + (j & 1) * 16;

    cp_wait<1>();
    __syncthreads();
    uint32_t qfr[12][4];
    #pragma unroll
    for (int kk = 0; kk < 12; kk++)
        ldsm4(qfr[kk], qoff + kk * 32);

    float oacc[16][4] = {};
    float m0 = -1e30f, m1 = -1e30f, l0 = 0.f, l1 = 0.f;
    const float K2 = SCALE * 1.4426950408889634f;

    for (int it = 0; it < 32; it++) {
        if (it > 0) {
            cp_wait<1>();
            __syncthreads();
        }
        int st = it & 1;
        uint32_t kb = sK_u + (uint32_t)(st * SK_STG) + koff;
        uint32_t vb = sV_u + (uint32_t)(st * SV_STG) + voff;

        float sacc[8][4] = {};
        #pragma unroll
        for (int kk = 0; kk < 12; kk++) {
            #pragma unroll
            for (int n2 = 0; n2 < 4; n2++) {
                uint32_t bk[4];
                ldsm4(bk, kb + n2 * (16 * QROW) + kk * 32);
                mma_f16(sacc[2 * n2],     qfr[kk], &bk[0]);
                mma_f16(sacc[2 * n2 + 1], qfr[kk], &bk[2]);
            }
        }

        float mx0 = -1e30f, mx1 = -1e30f;
        #pragma unroll
        for (int nt = 0; nt < 8; nt++) {
            mx0 = fmaxf(mx0, fmaxf(sacc[nt][0], sacc[nt][1]));
            mx1 = fmaxf(mx1, fmaxf(sacc[nt][2], sacc[nt][3]));
        }
        mx0 = fmaxf(mx0, __shfl_xor_sync(0xffffffffu, mx0, 1));
        mx0 = fmaxf(mx0, __shfl_xor_sync(0xffffffffu, mx0, 2));
        mx1 = fmaxf(mx1, __shfl_xor_sync(0xffffffffu, mx1, 1));
        mx1 = fmaxf(mx1, __shfl_xor_sync(0xffffffffu, mx1, 2));
        float mn0 = fmaxf(m0, mx0), mn1 = fmaxf(m1, mx1);
        float rs0 = exp2f((m0 - mn0) * K2), rs1 = exp2f((m1 - mn1) * K2);
        m0 = mn0; m1 = mn1;

        uint32_t p01[8], p23[8];
        float sum0 = 0.f, sum1 = 0.f;
        #pragma unroll
        for (int nt = 0; nt < 8; nt++) {
            __half2 a01 = __floats2half2_rn((sacc[nt][0] - mn0) * K2,
                                            (sacc[nt][1] - mn0) * K2);
            __half2 a23 = __floats2half2_rn((sacc[nt][2] - mn1) * K2,
                                            (sacc[nt][3] - mn1) * K2);
            __half2 e01 = h2exp2(a01);
            __half2 e23 = h2exp2(a23);
            float2 f01 = __half22float2(e01);
            float2 f23 = __half22float2(e23);
            sum0 += f01.x + f01.y;
            sum1 += f23.x + f23.y;
            p01[nt] = *(uint32_t*)&e01;
            p23[nt] = *(uint32_t*)&e23;
        }
        sum0 += __shfl_xor_sync(0xffffffffu, sum0, 1);
        sum0 += __shfl_xor_sync(0xffffffffu, sum0, 2);
        sum1 += __shfl_xor_sync(0xffffffffu, sum1, 1);
        sum1 += __shfl_xor_sync(0xffffffffu, sum1, 2);
        l0 = l0 * rs0 + sum0;
        l1 = l1 * rs1 + sum1;

        #pragma unroll
        for (int nt = 0; nt < 16; nt++) {
            oacc[nt][0] *= rs0; oacc[nt][1] *= rs0;
            oacc[nt][2] *= rs1; oacc[nt][3] *= rs1;
        }

        #pragma unroll
        for (int kk = 0; kk < 4; kk++) {
            uint32_t pa[4] = {p01[2 * kk], p23[2 * kk], p01[2 * kk + 1], p23[2 * kk + 1]};
            #pragma unroll
            for (int n2 = 0; n2 < 8; n2++) {
                uint32_t bv[4];
                ldsm4(bv, vb + n2 * (16 * VROW) + kk * 32);
                mma_f16(oacc[2 * n2],     pa, &bv[0]);
                mma_f16(oacc[2 * n2 + 1], pa, &bv[2]);
            }
        }

        __syncthreads();             // 2-stage: all warps done with stage st
        if (it + 2 < 32) load_kv(st, (it + 2) * 64);
        cp_commit();
    }

    float il0 = 1.f / l0, il1 = 1.f / l1;
    int row = q0 + wid * 16 + g;
    size_t tok0 = (size_t)b * S_ + row;
    __half* o0 = oc + tok0 * (H_ * VH_) + h * VH_;
    __half* o1 = o0 + (size_t)8 * (H_ * VH_);
    #pragma unroll
    for (int nt = 0; nt < 16; nt++) {
        int c = nt * 8 + 2 * t4;
        *(__half2*)&o0[c] = __floats2half2_rn(oacc[nt][0] * il0, oacc[nt][1] * il0);
        *(__half2*)&o1[c] = __floats2half2_rn(oacc[nt][2] * il1, oacc[nt][3] * il1);
    }
}

// =============================================================================
// convall_k: ALL input conversions in one launch.
// =============================================================================
#define RE0 ((size_t)NT * D_)
#define RE1 (RE0 + (size_t)QL * D_)
#define RE2 (RE1 + (size_t)KVP * D_)
#define RE3 (RE2 + (size_t)HQK * QL)
#define RE4 (RE3 + (size_t)H_ * 256 * KVL)
#define RE5 (RE4 + (size_t)D_ * H_ * VH_)
#define RE6 (RE5 + NCAT)
#define KFWD ((size_t)(KVL + ROPE_) * D_)

__device__ __forceinline__ void cvt4(const float* in, __half* out) {
    float4 v = *(const float4*)in;
    __half2* o = (__half2*)out;
    o[0] = __floats2half2_rn(v.x, v.y);
    o[1] = __floats2half2_rn(v.z, v.w);
}

__global__ void convall_k(
    const float* __restrict__ x,     __half* __restrict__ xh,
    const float* __restrict__ wqa,   __half* __restrict__ wcat,
    const float* __restrict__ wkva,
    const float* __restrict__ wqbf,  __half* __restrict__ wqb,
    const float* __restrict__ wkvbf, __half* __restrict__ wkvb,
    const float* __restrict__ wof,   __half* __restrict__ wo,
    const float* __restrict__ qbias, const float* __restrict__ kbias,
    float* __restrict__ bcat)
{
    size_t i = ((size_t)blockIdx.x * 256 + threadIdx.x) * 4;
    if (i >= RE6) return;
    if (i < RE0) {
        cvt4(x + i, xh + i);
    } else if (i < RE1) {
        size_t k = i - RE0;
        cvt4(wqa + k, wcat + k);
    } else if (i < RE2) {
        size_t k = i - RE1;
        __half* dst = wcat + (size_t)QL * D_ + k;
        if (k < KFWD) cvt4(wkva + k, dst);
        else {
            __half2 z = __half2{__half(0.f), __half(0.f)};
            ((__half2*)dst)[0] = z;
            ((__half2*)dst)[1] = z;
        }
    } else if (i < RE3) {
        size_t k = i - RE2;
        cvt4(wqbf + k, wqb + k);
    } else if (i < RE4) {
        size_t k = i - RE3;
        cvt4(wkvbf + k, wkvb + k);
    } else if (i < RE5) {
        size_t k = i - RE4;
        cvt4(wof + k, wo + k);
    } else {
        size_t k = i - RE5;
        #pragma unroll
        for (int m = 0; m < 4; m++) {
            size_t kk = k + m;
            bcat[kk] = (kk < QL) ? qbias[kk]
                     : (kk < QL + KVL + ROPE_) ? kbias[kk - QL] : 0.f;
        }
    }
}

// =============================================================================
// elem_k: rmsnorm_q + rmsnorm_kv + rope_k_bcast, one launch.
// =============================================================================
__device__ __forceinline__ void rms_body(const __half* ip_, __half* op_,
                                         const float* w, int width)
{
    const __half2* ip = (const __half2*)ip_;
    __half2* op = (__half2*)op_;
    int w2 = width >> 1;
    float ss = 0.f;
    for (int i = threadIdx.x; i < w2; i += 256) {
        float2 v = __half22float2(ip[i]);
        ss += v.x * v.x + v.y * v.y;
    }
    ss += __shfl_xor_sync(0xffffffffu, ss, 16);
    ss += __shfl_xor_sync(0xffffffffu, ss, 8);
    ss += __shfl_xor_sync(0xffffffffu, ss, 4);
    ss += __shfl_xor_sync(0xffffffffu, ss, 2);
    ss += __shfl_xor_sync(0xffffffffu, ss, 1);
    __shared__ float sm[8];
    if ((threadIdx.x & 31) == 0) sm[threadIdx.x >> 5] = ss;
    __syncthreads();
    float tot = sm[0] + sm[1] + sm[2] + sm[3] + sm[4] + sm[5] + sm[6] + sm[7];
    float rr = rsqrtf(tot / (float)width + 1e-3f);
    for (int i = threadIdx.x; i < w2; i += 256) {
        float2 v = __half22float2(ip[i]);
        op[i] = __floats2half2_rn(w[2 * i] * v.x * rr, w[2 * i + 1] * v.y * rr);
    }
}

__global__ void elem_k(const __half* __restrict__ qakv,
                       __half* __restrict__ qa, __half* __restrict__ kf,
                       __half* __restrict__ kfull,
                       const float* __restrict__ qw, const float* __restrict__ kvw,
                       const float* __restrict__ c, const float* __restrict__ s)
{
    int bid = blockIdx.x;
    if (bid < NT) {
        rms_body(qakv + (size_t)bid * NCAT, qa + (size_t)bid * QL, qw, QL);
    } else if (bid < 2 * NT) {
        int row = bid - NT;
        rms_body(qakv + (size_t)row * NCAT + QL, kf + (size_t)row * KVL, kvw, KVL);
    } else {
        int tok = (bid - 2 * NT) * 8 + (threadIdx.x >> 5);
        int j = threadIdx.x & 31;
        int pos = tok % S_;
        const __half* src = qakv + (size_t)tok * NCAT + QL + KVL;
        float xr = __half2float(src[2 * j]), xi = __half2float(src[2 * j + 1]);
        float cc = c[pos * 32 + j], sn = s[pos * 32 + j];
        __half2 v;
        v.x = __float2half(xr * cc - xi * sn);
        v.y = __float2half(xr * sn + xi * cc);
        __half* dst = kfull + (size_t)tok * HQK + NOPE_;
        #pragma unroll
        for (int h = 0; h < H_; h++)
            *(__half2*)&dst[h * QK_ + 2 * j] = v;
    }
}

// ---------------- host glue --------------------------------------------------
template<int TN, bool OUTHALF, bool ROPE>
static void launch_h(int M, int N, int K,
                     const __half* A, int lda, long long sAb, long long sAh,
                     const __half* Bp, int ldb, long long sBb, long long sBh,
                     void* C, int ldc, long long sCb, long long sCh,
                     int nb, int nh, float alpha, const float* bias,
                     const float* cosp, const float* sinp)
{
    constexpr int SMEM = (3 * 128 * 20 + 3 * TN * 20) * 4;
    cudaFuncSetAttribute(gemm_h<TN, OUTHALF, ROPE>,
                         cudaFuncAttributeMaxDynamicSharedMemorySize, SMEM);
    dim3 grid(N / TN, M / 128, nb * nh);
    gemm_h<TN, OUTHALF, ROPE><<<grid, TN == 256 ? 256 : 128, SMEM>>>(
        K, A, lda, sAb, sAh, Bp, ldb, sBb, sBh, C, ldc, sCb, sCh, nh, alpha, bias,
        cosp, sinp);
}

extern "C" void kernel_launch(void* const* d_in, const int* in_sizes, int n_in,
                              void* d_out, int out_size)
{
    const float* x        = (const float*)d_in[0];
    const float* cosp     = (const float*)d_in[2];
    const float* sinp     = (const float*)d_in[3];
    const float* wq_a_w   = (const float*)d_in[4];
    const float* wq_a_b   = (const float*)d_in[5];
    const float* q_norm_w = (const float*)d_in[6];
    const float* wq_b_w   = (const float*)d_in[7];
    const float* wq_b_b   = (const float*)d_in[8];
    const float* wkv_a_w  = (const float*)d_in[9];
    const float* wkv_a_b  = (const float*)d_in[10];
    const float* kv_norm_w= (const float*)d_in[11];
    const float* wkv_b_w  = (const float*)d_in[12];
    const float* wo_w     = (const float*)d_in[13];
    const float* wo_b     = (const float*)d_in[14];
    float* out = (float*)d_out;

    __half *xh, *qakv, *qa, *q, *kf, *kfull, *vT, *oc;
    __half *wcat, *wqb, *wkvb, *wo;
    float *bcat;
    cudaGetSymbolAddress((void**)&xh,   h_x);
    cudaGetSymbolAddress((void**)&qakv, h_qakv);
    cudaGetSymbolAddress((void**)&qa,   h_qa);
    cudaGetSymbolAddress((void**)&q,    h_q);
    cudaGetSymbolAddress((void**)&kf,   h_kf);
    cudaGetSymbolAddress((void**)&kfull,h_kfull);
    cudaGetSymbolAddress((void**)&vT,   h_vT);
    cudaGetSymbolAddress((void**)&oc,   h_oc);
    cudaGetSymbolAddress((void**)&wcat, h_wcat);
    cudaGetSymbolAddress((void**)&wqb,  h_wqb);
    cudaGetSymbolAddress((void**)&wkvb, h_wkvb);
    cudaGetSymbolAddress((void**)&wo,   h_wo);
    cudaGetSymbolAddress((void**)&bcat, g_biascat);

    // 0) ALL conversions
    {
        unsigned grid = (unsigned)((RE6 / 4 + 255) / 256);
        convall_k<<<grid, 256>>>(x, xh, wq_a_w, wcat, wkv_a_w,
                                 wq_b_w, wqb, wkv_b_w, wkvb, wo_w, wo,
                                 wq_a_b, wkv_a_b, bcat);
    }
    // 1) qakv = x @ wcat^T + bcat      [4096,1664] K=2048
    launch_h<128, true, false>(NT, NCAT, D_, xh, D_, 0, 0, wcat, D_, 0, 0,
                               qakv, NCAT, 0, 0, 1, 1, 1.f, bcat, nullptr, nullptr);
    // 2) merged elementwise
    elem_k<<<2 * NT + NT / 8, 256>>>(qakv, qa, kf, kfull, q_norm_w, kv_norm_w,
                                     cosp, sinp);
    // 3) mega GEMM: q-proj(+rope) + vT + knope (1792 CTAs)
    {
        constexpr int SMEM = (3 * 128 * 20 + 3 * 128 * 20) * 4;
        cudaFuncSetAttribute(gemm_mega,
                             cudaFuncAttributeMaxDynamicSharedMemorySize, SMEM);
        gemm_mega<<<1792, 128, SMEM>>>(qa, wqb, q, wq_b_b, cosp, sinp,
                                       wkvb, kf, vT, kfull);
    }
    // 4) fused attention (2 CTAs/SM)
    {
        cudaFuncSetAttribute(flash_h, cudaFuncAttributeMaxDynamicSharedMemorySize,
                             FLASH_SMEM);
        dim3 grid(S_ / 64, B_ * H_);
        flash_h<<<grid, 128, FLASH_SMEM>>>(q, kfull, vT, oc);
    }
    // 5) out = oc @ wo^T + b           [4096,2048] K=2048 -> fp32
    launch_h<256, false, false>(NT, D_, H_ * VH_, oc, H_ * VH_, 0, 0, wo, D_, 0, 0,
                                out, D_, 0, 0, 1, 1, 1.f, wo_b, nullptr, nullptr);
}

// round 17
// speedup vs baseline: 2.5793x; 1.0252x over previous
#include <cuda_runtime.h>
#include <cuda_fp16.h>
#include <math.h>
#include <stdint.h>

#define B_    2
#define S_    2048
#define D_    2048
#define H_    16
#define NT    4096
#define QL    1024
#define KVL   512
#define NOPE_ 128
#define ROPE_ 64
#define VH_   128
#define QK_   192
#define KVP   640
#define NCAT  1664
#define HQK   3072
#define SCALE 0.07216878364870322f

// ---------------- scratch ----------------------------------------------------
__device__ __align__(256) __half h_x   [(size_t)NT * D_];
__device__ __align__(256) __half h_qakv[(size_t)NT * NCAT];
__device__ __align__(256) __half h_qa  [(size_t)NT * QL];
__device__ __align__(256) __half h_q   [(size_t)NT * HQK];
__device__ __align__(256) __half h_kf  [(size_t)NT * KVL];
__device__ __align__(256) __half h_kfull[(size_t)NT * HQK];
__device__ __align__(256) __half h_vT  [(size_t)B_ * H_ * VH_ * S_];
__device__ __align__(256) __half h_oc  [(size_t)NT * H_ * VH_];
__device__ __align__(256) __half h_wcat[(size_t)NCAT * D_];
__device__ __align__(256) __half h_wqb [(size_t)HQK * QL];
__device__ __align__(256) __half h_wkvb[(size_t)H_ * 256 * KVL];
__device__ __align__(256) __half h_wo  [(size_t)D_ * H_ * VH_];
__device__ float g_biascat[NCAT];

// ---------------- helpers ---------------------------------------------------
__device__ __forceinline__ void mma_f16(float* c, const uint32_t* a, const uint32_t* b) {
    asm volatile(
        "mma.sync.aligned.m16n8k16.row.col.f32.f16.f16.f32 "
        "{%0,%1,%2,%3},{%4,%5,%6,%7},{%8,%9},{%0,%1,%2,%3};"
        : "+f"(c[0]), "+f"(c[1]), "+f"(c[2]), "+f"(c[3])
        : "r"(a[0]), "r"(a[1]), "r"(a[2]), "r"(a[3]), "r"(b[0]), "r"(b[1]));
}

__device__ __forceinline__ void ldsm4(uint32_t* r, uint32_t saddr) {
    asm volatile(
        "ldmatrix.sync.aligned.m8n8.x4.shared.b16 {%0,%1,%2,%3}, [%4];"
        : "=r"(r[0]), "=r"(r[1]), "=r"(r[2]), "=r"(r[3]) : "r"(saddr));
}

__device__ __forceinline__ void cp_async16(void* smem, const void* gmem) {
    uint32_t s = (uint32_t)__cvta_generic_to_shared(smem);
    asm volatile("cp.async.cg.shared.global [%0], [%1], 16;" :: "r"(s), "l"(gmem));
}
__device__ __forceinline__ void cp_commit() {
    asm volatile("cp.async.commit_group;");
}
template<int N>
__device__ __forceinline__ void cp_wait() {
    asm volatile("cp.async.wait_group %0;" :: "n"(N));
}

// =============================================================================
// gemm_body: fp16 in / fp32 acc. CTA tile 128x128, 256 threads = 8 warps
// (2 rows x 4 cols), warp tile 64x32 (acc=64 regs -> 16 warps/SM at 2 CTAs).
// BK=32, 3-stage cp.async, ldmatrix fragments.
// =============================================================================
template<bool OUTHALF, bool ROPE>
__device__ __forceinline__ void gemm_body(
    int bx, int by, int bz, int K,
    const __half* __restrict__ A, int lda, long long sAb, long long sAh,
    const __half* __restrict__ Bp, int ldb, long long sBb, long long sBh,
    void* __restrict__ Cv, int ldc, long long sCb, long long sCh,
    int ZH, float alpha, const float* __restrict__ bias,
    const float* __restrict__ cosp, const float* __restrict__ sinp,
    uint32_t* smu)
{
    constexpr int ASTR = 20;              // u32 per row (80 B)
    constexpr int STG = 128 * ASTR;       // per stage, A or B

    uint32_t* sA = smu;
    uint32_t* sB = smu + 3 * STG;

    int zb = bz / ZH;
    int zh = bz - zb * ZH;
    const __half* Ab = A  + zb * sAb + zh * sAh;
    const __half* Bb = Bp + zb * sBb + zh * sBh;

    int row0 = by << 7;
    int col0 = bx << 7;
    int tid  = threadIdx.x;
    int wid  = tid >> 5;
    int lane = tid & 31;
    int wm0 = (wid >> 2) << 6;            // 0 or 64
    int wn0 = (wid & 3) << 5;             // 0,32,64,96
    int g = lane >> 2, t4 = lane & 3;
    int j = lane >> 3, r = lane & 7;

    uint32_t sA_u = (uint32_t)__cvta_generic_to_shared(sA);
    uint32_t sB_u = (uint32_t)__cvta_generic_to_shared(sB);
    uint32_t aoff0 = (uint32_t)(wm0 + (j & 1) * 8 + r) * 80 + (uint32_t)(j >> 1) * 16;
    uint32_t boff0 = (uint32_t)(wn0 + (j >> 1) * 8 + r) * 80 + (uint32_t)(j & 1) * 16;

    float acc[4][4][4] = {};

    auto load_stage = [&](int st, int k0) {
        uint32_t* a_s = sA + st * STG;
        uint32_t* b_s = sB + st * STG;
        #pragma unroll
        for (int i = 0; i < 2; i++) {
            int idx = tid + 256 * i;
            int rr = idx >> 2, q = idx & 3;
            cp_async16(a_s + rr * ASTR + q * 4,
                       Ab + (size_t)(row0 + rr) * lda + k0 + q * 8);
        }
        #pragma unroll
        for (int i = 0; i < 2; i++) {
            int idx = tid + 256 * i;
            int rr = idx >> 2, q = idx & 3;
            cp_async16(b_s + rr * ASTR + q * 4,
                       Bb + (size_t)(col0 + rr) * ldb + k0 + q * 8);
        }
    };

    int nk = K / 32;
    load_stage(0, 0);
    cp_commit();
    load_stage(1, 32);
    cp_commit();

    for (int i = 0; i < nk; i++) {
        cp_wait<1>();
        __syncthreads();
        if (i + 2 < nk) load_stage((i + 2) % 3, (i + 2) * 32);
        cp_commit();

        uint32_t abase = sA_u + (uint32_t)((i % 3) * STG) * 4 + aoff0;
        uint32_t bbase = sB_u + (uint32_t)((i % 3) * STG) * 4 + boff0;

        #pragma unroll
        for (int kk = 0; kk < 2; kk++) {
            uint32_t afr[4][4], bfr[2][4];
            #pragma unroll
            for (int mt = 0; mt < 4; mt++)
                ldsm4(afr[mt], abase + mt * 1280 + kk * 32);
            #pragma unroll
            for (int n2 = 0; n2 < 2; n2++)
                ldsm4(bfr[n2], bbase + n2 * 1280 + kk * 32);
            #pragma unroll
            for (int mt = 0; mt < 4; mt++)
                #pragma unroll
                for (int n2 = 0; n2 < 2; n2++) {
                    mma_f16(acc[mt][2 * n2],     afr[mt], &bfr[n2][0]);
                    mma_f16(acc[mt][2 * n2 + 1], afr[mt], &bfr[n2][2]);
                }
        }
    }

    size_t coff = (size_t)zb * sCb + (size_t)zh * sCh;
    #pragma unroll
    for (int mt = 0; mt < 4; mt++) {
        int r0 = row0 + wm0 + mt * 16 + g;
        #pragma unroll
        for (int nt = 0; nt < 4; nt++) {
            int c0c = col0 + wn0 + nt * 8 + 2 * t4;
            float b0 = bias ? bias[c0c] : 0.f;
            float b1 = bias ? bias[c0c + 1] : 0.f;
            float v00 = alpha * acc[mt][nt][0] + b0;
            float v01 = alpha * acc[mt][nt][1] + b1;
            float v10 = alpha * acc[mt][nt][2] + b0;
            float v11 = alpha * acc[mt][nt][3] + b1;
            if (ROPE) {
                int hc = c0c % QK_;
                if (hc >= NOPE_) {
                    int jj = (hc - NOPE_) >> 1;
                    int pos0 = r0 & (S_ - 1);
                    int pos1 = (r0 + 8) & (S_ - 1);
                    float c0 = cosp[pos0 * 32 + jj], s0 = sinp[pos0 * 32 + jj];
                    float c1 = cosp[pos1 * 32 + jj], s1 = sinp[pos1 * 32 + jj];
                    float xr = v00, xi = v01;
                    v00 = xr * c0 - xi * s0;
                    v01 = xr * s0 + xi * c0;
                    xr = v10; xi = v11;
                    v10 = xr * c1 - xi * s1;
                    v11 = xr * s1 + xi * c1;
                }
            }
            if (OUTHALF) {
                __half* Ch = (__half*)Cv + coff;
                *(__half2*)&Ch[(size_t)r0 * ldc + c0c]       = __floats2half2_rn(v00, v01);
                *(__half2*)&Ch[(size_t)(r0 + 8) * ldc + c0c] = __floats2half2_rn(v10, v11);
            } else {
                float* Cf = (float*)Cv + coff;
                *(float2*)&Cf[(size_t)r0 * ldc + c0c]       = make_float2(v00, v01);
                *(float2*)&Cf[(size_t)(r0 + 8) * ldc + c0c] = make_float2(v10, v11);
            }
        }
    }
}

template<bool OUTHALF, bool ROPE>
__global__ void __launch_bounds__(256, 2) gemm_h(
    int K,
    const __half* __restrict__ A, int lda, long long sAb, long long sAh,
    const __half* __restrict__ Bp, int ldb, long long sBb, long long sBh,
    void* __restrict__ Cv, int ldc, long long sCb, long long sCh,
    int ZH, float alpha, const float* __restrict__ bias,
    const float* __restrict__ cosp, const float* __restrict__ sinp)
{
    extern __shared__ uint32_t smu[];
    gemm_body<OUTHALF, ROPE>(blockIdx.x, blockIdx.y, blockIdx.z, K,
                             A, lda, sAb, sAh, Bp, ldb, sBb, sBh,
                             Cv, ldc, sCb, sCh, ZH, alpha, bias,
                             cosp, sinp, smu);
}

// Mega GEMM: [0,768)=q-proj(+rope); [768,1280)=vT; [1280,1792)=knope.
__global__ void __launch_bounds__(256, 2) gemm_mega(
    const __half* __restrict__ qa,   const __half* __restrict__ wqb,
    __half* __restrict__ q,          const float* __restrict__ biasq,
    const float* __restrict__ cosp,  const float* __restrict__ sinp,
    const __half* __restrict__ wkvb, const __half* __restrict__ kf,
    __half* __restrict__ vT,         __half* __restrict__ kfull)
{
    extern __shared__ uint32_t smu[];
    int bid = blockIdx.x;
    if (bid < 768) {
        gemm_body<true, true>(bid % 24, bid / 24, 0, QL,
                              qa, QL, 0, 0, wqb, QL, 0, 0,
                              q, HQK, 0, 0, 1, 1.f, biasq, cosp, sinp, smu);
    } else if (bid < 1280) {
        int t = bid - 768;
        gemm_body<true, false>(t & 15, 0, t >> 4, KVL,
                               wkvb + (size_t)NOPE_ * KVL, KVL, 0,
                               (long long)256 * KVL,
                               kf, KVL, (long long)S_ * KVL, 0,
                               vT, S_, (long long)H_ * VH_ * S_,
                               (long long)VH_ * S_, H_, 1.f, nullptr,
                               nullptr, nullptr, smu);
    } else {
        int t = bid - 1280;
        gemm_body<true, false>(0, t & 31, t >> 5, KVL,
                               kf, KVL, 0, 0,
                               wkvb, KVL, 0, (long long)256 * KVL,
                               kfull, HQK, 0, QK_, H_, 1.f, nullptr,
                               nullptr, nullptr, smu);
    }
}

// =============================================================================
// flash_h: 64-query CTAs, 128 threads, 2-stage K/V, 113.7 KB -> 2 CTAs/SM.
// =============================================================================
#define QROW 400
#define VROW 144
#define SQ_BYTES (64 * QROW)
#define SK_STG   (64 * QROW)
#define SV_STG   (128 * VROW)
#define FLASH_SMEM (SQ_BYTES + 2 * SK_STG + 2 * SV_STG)   // 113664

__global__ void __launch_bounds__(128) flash_h(
    const __half* __restrict__ q,
    const __half* __restrict__ kfull,
    const __half* __restrict__ vT,
    __half* __restrict__ oc)
{
    extern __shared__ char sm[];
    char* sQ = sm;
    char* sK = sm + SQ_BYTES;
    char* sV = sK + 2 * SK_STG;

    int qt = blockIdx.x;
    int bh = blockIdx.y;
    int b  = bh >> 4, h = bh & 15;
    int q0 = qt << 6;

    int tid = threadIdx.x, wid = tid >> 5, lane = tid & 31;
    int g = lane >> 2, t4 = lane & 3;
    int j = lane >> 3, r = lane & 7;

    const __half* qg = q     + (size_t)b * S_ * HQK + h * QK_;
    const __half* kg = kfull + (size_t)b * S_ * HQK + h * QK_;
    const __half* vg = vT    + (size_t)bh * VH_ * S_;

    #pragma unroll
    for (int i = 0; i < 12; i++) {
        int idx = tid + 128 * i;
        int row = idx / 24, c = idx % 24;
        cp_async16(sQ + row * QROW + c * 16,
                   (const char*)(qg + (size_t)(q0 + row) * HQK) + c * 16);
    }
    auto load_kv = [&](int st, int kc0) {
        char* k_s = sK + st * SK_STG;
        char* v_s = sV + st * SV_STG;
        #pragma unroll
        for (int i = 0; i < 12; i++) {
            int idx = tid + 128 * i;
            int row = idx / 24, c = idx % 24;
            cp_async16(k_s + row * QROW + c * 16,
                       (const char*)(kg + (size_t)(kc0 + row) * HQK) + c * 16);
        }
        #pragma unroll
        for (int i = 0; i < 8; i++) {
            int idx = tid + 128 * i;
            int row = idx >> 3, c = idx & 7;
            cp_async16(v_s + row * VROW + c * 16,
                       (const char*)(vg + (size_t)row * S_ + kc0) + c * 16);
        }
    };

    load_kv(0, 0);
    cp_commit();
    load_kv(1, 64);
    cp_commit();

    uint32_t sQ_u = (uint32_t)__cvta_generic_to_shared(sQ);
    uint32_t sK_u = (uint32_t)__cvta_generic_to_shared(sK);
    uint32_t sV_u = (uint32_t)__cvta_generic_to_shared(sV);
    uint32_t qoff = sQ_u + (uint32_t)(wid * 16 + (j & 1) * 8 + r) * QROW + (j >> 1) * 16;
    uint32_t koff = (uint32_t)((j >> 1) * 8 + r) * QROW + (j & 1) * 16;
    uint32_t voff = (uint32_t)((j >> 1) * 8 + r) * VROW + (j & 1) * 16;

    cp_wait<1>();
    __syncthreads();
    uint32_t qfr[12][4];
    #pragma unroll
    for (int kk = 0; kk < 12; kk++)
        ldsm4(qfr[kk], qoff + kk * 32);

    float oacc[16][4] = {};
    float m0 = -1e30f, m1 = -1e30f, l0 = 0.f, l1 = 0.f;
    const float K2 = SCALE * 1.4426950408889634f;

    for (int it = 0; it < 32; it++) {
        if (it > 0) {
            cp_wait<1>();
            __syncthreads();
        }
        int st = it & 1;
        uint32_t kb = sK_u + (uint32_t)(st * SK_STG) + koff;
        uint32_t vb = sV_u + (uint32_t)(st * SV_STG) + voff;

        float sacc[8][4] = {};
        #pragma unroll
        for (int kk = 0; kk < 12; kk++) {
            #pragma unroll
            for (int n2 = 0; n2 < 4; n2++) {
                uint32_t bk[4];
                ldsm4(bk, kb + n2 * (16 * QROW) + kk * 32);
                mma_f16(sacc[2 * n2],     qfr[kk], &bk[0]);
                mma_f16(sacc[2 * n2 + 1], qfr[kk], &bk[2]);
            }
        }

        float mx0 = -1e30f, mx1 = -1e30f;
        #pragma unroll
        for (int nt = 0; nt < 8; nt++) {
            mx0 = fmaxf(mx0, fmaxf(sacc[nt][0], sacc[nt][1]));
            mx1 = fmaxf(mx1, fmaxf(sacc[nt][2], sacc[nt][3]));
        }
        mx0 = fmaxf(mx0, __shfl_xor_sync(0xffffffffu, mx0, 1));
        mx0 = fmaxf(mx0, __shfl_xor_sync(0xffffffffu, mx0, 2));
        mx1 = fmaxf(mx1, __shfl_xor_sync(0xffffffffu, mx1, 1));
        mx1 = fmaxf(mx1, __shfl_xor_sync(0xffffffffu, mx1, 2));
        float mn0 = fmaxf(m0, mx0), mn1 = fmaxf(m1, mx1);
        float rs0 = exp2f((m0 - mn0) * K2), rs1 = exp2f((m1 - mn1) * K2);
        m0 = mn0; m1 = mn1;

        uint32_t p01[8], p23[8];
        float sum0 = 0.f, sum1 = 0.f;
        #pragma unroll
        for (int nt = 0; nt < 8; nt++) {
            __half2 a01 = __floats2half2_rn((sacc[nt][0] - mn0) * K2,
                                            (sacc[nt][1] - mn0) * K2);
            __half2 a23 = __floats2half2_rn((sacc[nt][2] - mn1) * K2,
                                            (sacc[nt][3] - mn1) * K2);
            __half2 e01 = h2exp2(a01);
            __half2 e23 = h2exp2(a23);
            float2 f01 = __half22float2(e01);
            float2 f23 = __half22float2(e23);
            sum0 += f01.x + f01.y;
            sum1 += f23.x + f23.y;
            p01[nt] = *(uint32_t*)&e01;
            p23[nt] = *(uint32_t*)&e23;
        }
        sum0 += __shfl_xor_sync(0xffffffffu, sum0, 1);
        sum0 += __shfl_xor_sync(0xffffffffu, sum0, 2);
        sum1 += __shfl_xor_sync(0xffffffffu, sum1, 1);
        sum1 += __shfl_xor_sync(0xffffffffu, sum1, 2);
        l0 = l0 * rs0 + sum0;
        l1 = l1 * rs1 + sum1;

        #pragma unroll
        for (int nt = 0; nt < 16; nt++) {
            oacc[nt][0] *= rs0; oacc[nt][1] *= rs0;
            oacc[nt][2] *= rs1; oacc[nt][3] *= rs1;
        }

        #pragma unroll
        for (int kk = 0; kk < 4; kk++) {
            uint32_t pa[4] = {p01[2 * kk], p23[2 * kk], p01[2 * kk + 1], p23[2 * kk + 1]};
            #pragma unroll
            for (int n2 = 0; n2 < 8; n2++) {
                uint32_t bv[4];
                ldsm4(bv, vb + n2 * (16 * VROW) + kk * 32);
                mma_f16(oacc[2 * n2],     pa, &bv[0]);
                mma_f16(oacc[2 * n2 + 1], pa, &bv[2]);
            }
        }

        __syncthreads();
        if (it + 2 < 32) load_kv(st, (it + 2) * 64);
        cp_commit();
    }

    float il0 = 1.f / l0, il1 = 1.f / l1;
    int row = q0 + wid * 16 + g;
    size_t tok0 = (size_t)b * S_ + row;
    __half* o0 = oc + tok0 * (H_ * VH_) + h * VH_;
    __half* o1 = o0 + (size_t)8 * (H_ * VH_);
    #pragma unroll
    for (int nt = 0; nt < 16; nt++) {
        int c = nt * 8 + 2 * t4;
        *(__half2*)&o0[c] = __floats2half2_rn(oacc[nt][0] * il0, oacc[nt][1] * il0);
        *(__half2*)&o1[c] = __floats2half2_rn(oacc[nt][2] * il1, oacc[nt][3] * il1);
    }
}

// =============================================================================
// convall_k: ALL input conversions in one launch.
// =============================================================================
#define RE0 ((size_t)NT * D_)
#define RE1 (RE0 + (size_t)QL * D_)
#define RE2 (RE1 + (size_t)KVP * D_)
#define RE3 (RE2 + (size_t)HQK * QL)
#define RE4 (RE3 + (size_t)H_ * 256 * KVL)
#define RE5 (RE4 + (size_t)D_ * H_ * VH_)
#define RE6 (RE5 + NCAT)
#define KFWD ((size_t)(KVL + ROPE_) * D_)

__device__ __forceinline__ void cvt4(const float* in, __half* out) {
    float4 v = *(const float4*)in;
    __half2* o = (__half2*)out;
    o[0] = __floats2half2_rn(v.x, v.y);
    o[1] = __floats2half2_rn(v.z, v.w);
}

__global__ void convall_k(
    const float* __restrict__ x,     __half* __restrict__ xh,
    const float* __restrict__ wqa,   __half* __restrict__ wcat,
    const float* __restrict__ wkva,
    const float* __restrict__ wqbf,  __half* __restrict__ wqb,
    const float* __restrict__ wkvbf, __half* __restrict__ wkvb,
    const float* __restrict__ wof,   __half* __restrict__ wo,
    const float* __restrict__ qbias, const float* __restrict__ kbias,
    float* __restrict__ bcat)
{
    size_t i = ((size_t)blockIdx.x * 256 + threadIdx.x) * 4;
    if (i >= RE6) return;
    if (i < RE0) {
        cvt4(x + i, xh + i);
    } else if (i < RE1) {
        size_t k = i - RE0;
        cvt4(wqa + k, wcat + k);
    } else if (i < RE2) {
        size_t k = i - RE1;
        __half* dst = wcat + (size_t)QL * D_ + k;
        if (k < KFWD) cvt4(wkva + k, dst);
        else {
            __half2 z = __half2{__half(0.f), __half(0.f)};
            ((__half2*)dst)[0] = z;
            ((__half2*)dst)[1] = z;
        }
    } else if (i < RE3) {
        size_t k = i - RE2;
        cvt4(wqbf + k, wqb + k);
    } else if (i < RE4) {
        size_t k = i - RE3;
        cvt4(wkvbf + k, wkvb + k);
    } else if (i < RE5) {
        size_t k = i - RE4;
        cvt4(wof + k, wo + k);
    } else {
        size_t k = i - RE5;
        #pragma unroll
        for (int m = 0; m < 4; m++) {
            size_t kk = k + m;
            bcat[kk] = (kk < QL) ? qbias[kk]
                     : (kk < QL + KVL + ROPE_) ? kbias[kk - QL] : 0.f;
        }
    }
}

// =============================================================================
// elem_k: rmsnorm_q + rmsnorm_kv + rope_k_bcast, one launch.
// =============================================================================
__device__ __forceinline__ void rms_body(const __half* ip_, __half* op_,
                                         const float* w, int width)
{
    const __half2* ip = (const __half2*)ip_;
    __half2* op = (__half2*)op_;
    int w2 = width >> 1;
    float ss = 0.f;
    for (int i = threadIdx.x; i < w2; i += 256) {
        float2 v = __half22float2(ip[i]);
        ss += v.x * v.x + v.y * v.y;
    }
    ss += __shfl_xor_sync(0xffffffffu, ss, 16);
    ss += __shfl_xor_sync(0xffffffffu, ss, 8);
    ss += __shfl_xor_sync(0xffffffffu, ss, 4);
    ss += __shfl_xor_sync(0xffffffffu, ss, 2);
    ss += __shfl_xor_sync(0xffffffffu, ss, 1);
    __shared__ float sm[8];
    if ((threadIdx.x & 31) == 0) sm[threadIdx.x >> 5] = ss;
    __syncthreads();
    float tot = sm[0] + sm[1] + sm[2] + sm[3] + sm[4] + sm[5] + sm[6] + sm[7];
    float rr = rsqrtf(tot / (float)width + 1e-3f);
    for (int i = threadIdx.x; i < w2; i += 256) {
        float2 v = __half22float2(ip[i]);
        op[i] = __floats2half2_rn(w[2 * i] * v.x * rr, w[2 * i + 1] * v.y * rr);
    }
}

__global__ void elem_k(const __half* __restrict__ qakv,
                       __half* __restrict__ qa, __half* __restrict__ kf,
                       __half* __restrict__ kfull,
                       const float* __restrict__ qw, const float* __restrict__ kvw,
                       const float* __restrict__ c, const float* __restrict__ s)
{
    int bid = blockIdx.x;
    if (bid < NT) {
        rms_body(qakv + (size_t)bid * NCAT, qa + (size_t)bid * QL, qw, QL);
    } else if (bid < 2 * NT) {
        int row = bid - NT;
        rms_body(qakv + (size_t)row * NCAT + QL, kf + (size_t)row * KVL, kvw, KVL);
    } else {
        int tok = (bid - 2 * NT) * 8 + (threadIdx.x >> 5);
        int j = threadIdx.x & 31;
        int pos = tok % S_;
        const __half* src = qakv + (size_t)tok * NCAT + QL + KVL;
        float xr = __half2float(src[2 * j]), xi = __half2float(src[2 * j + 1]);
        float cc = c[pos * 32 + j], sn = s[pos * 32 + j];
        __half2 v;
        v.x = __float2half(xr * cc - xi * sn);
        v.y = __float2half(xr * sn + xi * cc);
        __half* dst = kfull + (size_t)tok * HQK + NOPE_;
        #pragma unroll
        for (int h = 0; h < H_; h++)
            *(__half2*)&dst[h * QK_ + 2 * j] = v;
    }
}

// ---------------- host glue --------------------------------------------------
#define GEMM_SMEM (6 * 128 * 20 * 4)      // 61440 B

template<bool OUTHALF, bool ROPE>
static void launch_h(int M, int N, int K,
                     const __half* A, int lda, long long sAb, long long sAh,
                     const __half* Bp, int ldb, long long sBb, long long sBh,
                     void* C, int ldc, long long sCb, long long sCh,
                     int nb, int nh, float alpha, const float* bias,
                     const float* cosp, const float* sinp)
{
    cudaFuncSetAttribute(gemm_h<OUTHALF, ROPE>,
                         cudaFuncAttributeMaxDynamicSharedMemorySize, GEMM_SMEM);
    dim3 grid(N / 128, M / 128, nb * nh);
    gemm_h<OUTHALF, ROPE><<<grid, 256, GEMM_SMEM>>>(
        K, A, lda, sAb, sAh, Bp, ldb, sBb, sBh, C, ldc, sCb, sCh, nh, alpha, bias,
        cosp, sinp);
}

extern "C" void kernel_launch(void* const* d_in, const int* in_sizes, int n_in,
                              void* d_out, int out_size)
{
    const float* x        = (const float*)d_in[0];
    const float* cosp     = (const float*)d_in[2];
    const float* sinp     = (const float*)d_in[3];
    const float* wq_a_w   = (const float*)d_in[4];
    const float* wq_a_b   = (const float*)d_in[5];
    const float* q_norm_w = (const float*)d_in[6];
    const float* wq_b_w   = (const float*)d_in[7];
    const float* wq_b_b   = (const float*)d_in[8];
    const float* wkv_a_w  = (const float*)d_in[9];
    const float* wkv_a_b  = (const float*)d_in[10];
    const float* kv_norm_w= (const float*)d_in[11];
    const float* wkv_b_w  = (const float*)d_in[12];
    const float* wo_w     = (const float*)d_in[13];
    const float* wo_b     = (const float*)d_in[14];
    float* out = (float*)d_out;

    __half *xh, *qakv, *qa, *q, *kf, *kfull, *vT, *oc;
    __half *wcat, *wqb, *wkvb, *wo;
    float *bcat;
    cudaGetSymbolAddress((void**)&xh,   h_x);
    cudaGetSymbolAddress((void**)&qakv, h_qakv);
    cudaGetSymbolAddress((void**)&qa,   h_qa);
    cudaGetSymbolAddress((void**)&q,    h_q);
    cudaGetSymbolAddress((void**)&kf,   h_kf);
    cudaGetSymbolAddress((void**)&kfull,h_kfull);
    cudaGetSymbolAddress((void**)&vT,   h_vT);
    cudaGetSymbolAddress((void**)&oc,   h_oc);
    cudaGetSymbolAddress((void**)&wcat, h_wcat);
    cudaGetSymbolAddress((void**)&wqb,  h_wqb);
    cudaGetSymbolAddress((void**)&wkvb, h_wkvb);
    cudaGetSymbolAddress((void**)&wo,   h_wo);
    cudaGetSymbolAddress((void**)&bcat, g_biascat);

    // 0) ALL conversions
    {
        unsigned grid = (unsigned)((RE6 / 4 + 255) / 256);
        convall_k<<<grid, 256>>>(x, xh, wq_a_w, wcat, wkv_a_w,
                                 wq_b_w, wqb, wkv_b_w, wkvb, wo_w, wo,
                                 wq_a_b, wkv_a_b, bcat);
    }
    // 1) qakv = x @ wcat^T + bcat      [4096,1664] K=2048  (grid 13x32)
    launch_h<true, false>(NT, NCAT, D_, xh, D_, 0, 0, wcat, D_, 0, 0,
                          qakv, NCAT, 0, 0, 1, 1, 1.f, bcat, nullptr, nullptr);
    // 2) merged elementwise
    elem_k<<<2 * NT + NT / 8, 256>>>(qakv, qa, kf, kfull, q_norm_w, kv_norm_w,
                                     cosp, sinp);
    // 3) mega GEMM: q-proj(+rope) [768] + vT [512] + knope [512]
    {
        cudaFuncSetAttribute(gemm_mega,
                             cudaFuncAttributeMaxDynamicSharedMemorySize, GEMM_SMEM);
        gemm_mega<<<1792, 256, GEMM_SMEM>>>(qa, wqb, q, wq_b_b, cosp, sinp,
                                            wkvb, kf, vT, kfull);
    }
    // 4) fused attention (2 CTAs/SM)
    {
        cudaFuncSetAttribute(flash_h, cudaFuncAttributeMaxDynamicSharedMemorySize,
                             FLASH_SMEM);
        dim3 grid(S_ / 64, B_ * H_);
        flash_h<<<grid, 128, FLASH_SMEM>>>(q, kfull, vT, oc);
    }
    // 5) out = oc @ wo^T + b           [4096,2048] K=2048 (grid 16x32)
    launch_h<false, false>(NT, D_, H_ * VH_, oc, H_ * VH_, 0, 0, wo, D_, 0, 0,
                           out, D_, 0, 0, 1, 1, 1.f, wo_b, nullptr, nullptr);
}